// round 1
// baseline (speedup 1.0000x reference)
#include <cuda_runtime.h>
#include <cstddef>

// Problem constants (fixed shapes from reference)
#define BATCH   2
#define T_SEQ   2048
#define CDIM    1024
#define DIM     1024
#define NH      16
#define HD      64
#define QKV_N   3072          // 3*DIM
#define ROWS    (BATCH*T_SEQ) // 4096

// Scratch (allocation-free rule: __device__ globals)
__device__ float g_qkv[ROWS * QKV_N];   // (b,t, g,h,hd) row-major, 48 MB
__device__ float g_attn[ROWS * DIM];    // (b,t, h,hd) row-major, 16 MB

// ---------------------------------------------------------------------------
// Tiled SGEMM with bias: C[M,N] = A[M,K] @ B[K,N] + bias[N]
// BM=BN=128, BK=16, 8x8 per thread, 256 threads. M,N,K multiples of tiles.
// ---------------------------------------------------------------------------
__global__ __launch_bounds__(256) void sgemm_bias_kernel(
    const float* __restrict__ A, const float* __restrict__ B,
    const float* __restrict__ bias, float* __restrict__ C,
    int M, int N, int K)
{
    __shared__ float As[16][128];   // A tile transposed: As[k][row]
    __shared__ float Bs[16][128];   // B tile natural:    Bs[k][col]

    const int tid = threadIdx.x;
    const int ty  = tid >> 4;       // 0..15 (row group)
    const int tx  = tid & 15;       // 0..15 (col group)
    const int rowBase = blockIdx.y * 128;
    const int colBase = blockIdx.x * 128;

    float acc[8][8];
    #pragma unroll
    for (int m = 0; m < 8; m++)
        #pragma unroll
        for (int n = 0; n < 8; n++) acc[m][n] = 0.f;

    for (int kt = 0; kt < K; kt += 16) {
        // Load A tile: 128 rows x 16 cols = 512 float4; 2 per thread
        // Load B tile: 16 rows x 128 cols = 512 float4; 2 per thread
        #pragma unroll
        for (int l = 0; l < 2; l++) {
            int id  = tid + l * 256;
            int ar  = id >> 2;              // 0..127
            int ac4 = (id & 3) * 4;         // 0,4,8,12
            float4 a = *(const float4*)&A[(size_t)(rowBase + ar) * K + kt + ac4];
            As[ac4 + 0][ar] = a.x;
            As[ac4 + 1][ar] = a.y;
            As[ac4 + 2][ar] = a.z;
            As[ac4 + 3][ar] = a.w;
            int br  = id >> 5;              // 0..15
            int bc4 = (id & 31) * 4;        // 0..124
            float4 b = *(const float4*)&B[(size_t)(kt + br) * N + colBase + bc4];
            *(float4*)&Bs[br][bc4] = b;
        }
        __syncthreads();

        #pragma unroll
        for (int k = 0; k < 16; k++) {
            float ra[8], rb[8];
            float4 a0 = *(const float4*)&As[k][ty * 8];
            float4 a1 = *(const float4*)&As[k][ty * 8 + 4];
            ra[0]=a0.x; ra[1]=a0.y; ra[2]=a0.z; ra[3]=a0.w;
            ra[4]=a1.x; ra[5]=a1.y; ra[6]=a1.z; ra[7]=a1.w;
            float4 b0 = *(const float4*)&Bs[k][tx * 8];
            float4 b1 = *(const float4*)&Bs[k][tx * 8 + 4];
            rb[0]=b0.x; rb[1]=b0.y; rb[2]=b0.z; rb[3]=b0.w;
            rb[4]=b1.x; rb[5]=b1.y; rb[6]=b1.z; rb[7]=b1.w;
            #pragma unroll
            for (int m = 0; m < 8; m++)
                #pragma unroll
                for (int n = 0; n < 8; n++)
                    acc[m][n] += ra[m] * rb[n];
        }
        __syncthreads();
    }

    // Epilogue: add bias, write float4
    #pragma unroll
    for (int m = 0; m < 8; m++) {
        int row = rowBase + ty * 8 + m;
        #pragma unroll
        for (int n = 0; n < 8; n += 4) {
            int col = colBase + tx * 8 + n;
            float4 o;
            o.x = acc[m][n + 0] + bias[col + 0];
            o.y = acc[m][n + 1] + bias[col + 1];
            o.z = acc[m][n + 2] + bias[col + 2];
            o.w = acc[m][n + 3] + bias[col + 3];
            *(float4*)&C[(size_t)row * N + col] = o;
        }
    }
}

// ---------------------------------------------------------------------------
// Fused RBF attention per (b,h): out[i,:] = sum_j exp(-(||k_i||^2 + ||q_j||^2
//   - 2 k_i.q_j) * sigma) * v[j,:]
// Tiles: 64 i-rows per CTA, stream 64 j-rows. 256 threads, 4x4 per thread.
// smem: kT[64][64] + (qT | S^T)[64][64] + v[64][64] = 48 KB exactly.
// ---------------------------------------------------------------------------
__global__ __launch_bounds__(256) void attn_rbf_kernel(
    const float* __restrict__ qkv, const float* __restrict__ rsig,
    float* __restrict__ attn)
{
    __shared__ float sm[12288];
    float* ksT = sm;            // ksT[d*64 + i]   (k tile, d-major)
    float* qb  = sm + 4096;     // qsT[d*64 + j]  then reused as S^T[j*64 + i]
    float* vs  = sm + 8192;     // vs[j*64 + d]

    const int tid = threadIdx.x;
    const int ty  = tid >> 4;   // i group (0..15)
    const int tx  = tid & 15;   // j group / d group (0..15)
    const int bh  = blockIdx.y;
    const int b   = bh / NH;
    const int h   = bh % NH;
    const int i0  = blockIdx.x * 64;
    const float sigma = *rsig;

    const size_t rowbase = (size_t)b * T_SEQ * QKV_N;
    const float* qbase = qkv + rowbase + 0 * DIM + h * HD;
    const float* kbase = qkv + rowbase + 1 * DIM + h * HD;
    const float* vbase = qkv + rowbase + 2 * DIM + h * HD;

    // Load k tile transposed: 64 rows x 64 floats = 1024 float4, 4/thread
    #pragma unroll
    for (int l = 0; l < 4; l++) {
        int id = tid + l * 256;
        int r  = id >> 4;           // 0..63
        int c4 = (id & 15) * 4;     // 0..60
        float4 kv = *(const float4*)&kbase[(size_t)(i0 + r) * QKV_N + c4];
        ksT[(c4 + 0) * 64 + r] = kv.x;
        ksT[(c4 + 1) * 64 + r] = kv.y;
        ksT[(c4 + 2) * 64 + r] = kv.z;
        ksT[(c4 + 3) * 64 + r] = kv.w;
    }
    __syncthreads();

    // kn for this thread's 4 i-rows (constant across j tiles)
    float knr[4] = {0.f, 0.f, 0.f, 0.f};
    for (int d = 0; d < 64; d++) {
        float4 ka = *(const float4*)&ksT[d * 64 + ty * 4];
        knr[0] += ka.x * ka.x; knr[1] += ka.y * ka.y;
        knr[2] += ka.z * ka.z; knr[3] += ka.w * ka.w;
    }

    float acc[4][4];
    #pragma unroll
    for (int m = 0; m < 4; m++)
        #pragma unroll
        for (int n = 0; n < 4; n++) acc[m][n] = 0.f;

    for (int jt = 0; jt < T_SEQ / 64; jt++) {
        const int j0 = jt * 64;
        __syncthreads();   // previous iteration's reads of qb/vs done

        // Load q tile (transposed) and v tile (natural)
        #pragma unroll
        for (int l = 0; l < 4; l++) {
            int id = tid + l * 256;
            int r  = id >> 4;
            int c4 = (id & 15) * 4;
            float4 qv = *(const float4*)&qbase[(size_t)(j0 + r) * QKV_N + c4];
            qb[(c4 + 0) * 64 + r] = qv.x;
            qb[(c4 + 1) * 64 + r] = qv.y;
            qb[(c4 + 2) * 64 + r] = qv.z;
            qb[(c4 + 3) * 64 + r] = qv.w;
            float4 vv = *(const float4*)&vbase[(size_t)(j0 + r) * QKV_N + c4];
            *(float4*)&vs[r * 64 + c4] = vv;
        }
        __syncthreads();

        // dot[m][n] = k_i . q_j ; qnr[n] = ||q_j||^2 folded into same loop
        float dot[4][4];
        #pragma unroll
        for (int m = 0; m < 4; m++)
            #pragma unroll
            for (int n = 0; n < 4; n++) dot[m][n] = 0.f;
        float qnr[4] = {0.f, 0.f, 0.f, 0.f};

        #pragma unroll 8
        for (int d = 0; d < 64; d++) {
            float4 ka = *(const float4*)&ksT[d * 64 + ty * 4];
            float4 qa = *(const float4*)&qb [d * 64 + tx * 4];
            float ra[4] = {ka.x, ka.y, ka.z, ka.w};
            float rq[4] = {qa.x, qa.y, qa.z, qa.w};
            qnr[0] += rq[0] * rq[0]; qnr[1] += rq[1] * rq[1];
            qnr[2] += rq[2] * rq[2]; qnr[3] += rq[3] * rq[3];
            #pragma unroll
            for (int m = 0; m < 4; m++)
                #pragma unroll
                for (int n = 0; n < 4; n++)
                    dot[m][n] += ra[m] * rq[n];
        }
        __syncthreads();   // all qb (q tile) reads done before overwrite

        // S^T[j][i] = exp(-(kn_i + qn_j - 2 dot) * sigma), write into qb
        #pragma unroll
        for (int n = 0; n < 4; n++) {
            #pragma unroll
            for (int m = 0; m < 4; m++) {
                float d2 = knr[m] + qnr[n] - 2.f * dot[m][n];
                qb[(tx * 4 + n) * 64 + (ty * 4 + m)] = __expf(-d2 * sigma);
            }
        }
        __syncthreads();

        // acc[m][n] += S^T[j][i=ty*4+m] * v[j][d=tx*4+n]
        #pragma unroll 8
        for (int j = 0; j < 64; j++) {
            float4 s4 = *(const float4*)&qb[j * 64 + ty * 4];
            float4 v4 = *(const float4*)&vs[j * 64 + tx * 4];
            float rs[4] = {s4.x, s4.y, s4.z, s4.w};
            float rv[4] = {v4.x, v4.y, v4.z, v4.w};
            #pragma unroll
            for (int m = 0; m < 4; m++)
                #pragma unroll
                for (int n = 0; n < 4; n++)
                    acc[m][n] += rs[m] * rv[n];
        }
    }

    // Write out in (b,t,h,hd) layout -> makes projection GEMM row-major
    #pragma unroll
    for (int m = 0; m < 4; m++) {
        size_t row = (size_t)b * T_SEQ + i0 + ty * 4 + m;
        float4 o;
        o.x = acc[m][0]; o.y = acc[m][1]; o.z = acc[m][2]; o.w = acc[m][3];
        *(float4*)&attn[row * DIM + h * HD + tx * 4] = o;
    }
}

// ---------------------------------------------------------------------------
// Launch: x @ Wqkv + b -> g_qkv ; fused attention -> g_attn ; @ Wproj + b -> out
// Inputs (metadata order): x, Wqkv, bqkv, r_sigma, Wproj, bproj
// ---------------------------------------------------------------------------
extern "C" void kernel_launch(void* const* d_in, const int* in_sizes, int n_in,
                              void* d_out, int out_size)
{
    const float* x     = (const float*)d_in[0];
    const float* Wqkv  = (const float*)d_in[1];
    const float* bqkv  = (const float*)d_in[2];
    const float* rsig  = (const float*)d_in[3];
    const float* Wproj = (const float*)d_in[4];
    const float* bproj = (const float*)d_in[5];
    float* out = (float*)d_out;

    float *qkv_buf, *attn_buf;
    cudaGetSymbolAddress((void**)&qkv_buf, g_qkv);
    cudaGetSymbolAddress((void**)&attn_buf, g_attn);

    // Stage 1: qkv = x @ Wqkv + bqkv   (4096 x 3072, K=1024)
    {
        dim3 grid(QKV_N / 128, ROWS / 128);
        sgemm_bias_kernel<<<grid, 256>>>(x, Wqkv, bqkv, qkv_buf,
                                         ROWS, QKV_N, CDIM);
    }

    // Stage 2: fused RBF attention per (b,h), i-tiles of 64
    {
        dim3 grid(T_SEQ / 64, BATCH * NH);
        attn_rbf_kernel<<<grid, 256>>>(qkv_buf, rsig, attn_buf);
    }

    // Stage 3: out = attn @ Wproj + bproj   (4096 x 1024, K=1024)
    {
        dim3 grid(CDIM / 128, ROWS / 128);
        sgemm_bias_kernel<<<grid, 256>>>(attn_buf, Wproj, bproj, out,
                                         ROWS, CDIM, DIM);
    }
}

// round 2
// speedup vs baseline: 1.7231x; 1.7231x over previous
#include <cuda_runtime.h>
#include <cstdint>
#include <cstddef>

// Problem constants
#define BATCH   2
#define T_SEQ   2048
#define CDIM    1024
#define DIM     1024
#define NH      16
#define HD      64
#define QKV_N   3072
#define ROWS    (BATCH*T_SEQ)

// Scratch (__device__ globals: allocation-free rule)
__device__ float g_qkv[ROWS * QKV_N];   // 48 MB
__device__ float g_attn[ROWS * DIM];    // 16 MB

// ---------------------------------------------------------------------------
// tf32 helpers (3xTF32 precision scheme)
// ---------------------------------------------------------------------------
__device__ __forceinline__ uint32_t tf32_hi_bits(float x) {
    return __float_as_uint(x) & 0xFFFFE000u;
}
__device__ __forceinline__ void split_tf32(float x, uint32_t& hi, uint32_t& lo) {
    hi = tf32_hi_bits(x);
    lo = __float_as_uint(x - __uint_as_float(hi));
}

__device__ __forceinline__ void mma_tf32(float* d,
    uint32_t a0, uint32_t a1, uint32_t a2, uint32_t a3,
    uint32_t b0, uint32_t b1)
{
    asm volatile(
        "mma.sync.aligned.m16n8k8.row.col.f32.tf32.tf32.f32 "
        "{%0,%1,%2,%3}, {%4,%5,%6,%7}, {%8,%9}, {%0,%1,%2,%3};\n"
        : "+f"(d[0]), "+f"(d[1]), "+f"(d[2]), "+f"(d[3])
        : "r"(a0), "r"(a1), "r"(a2), "r"(a3), "r"(b0), "r"(b1));
}

// 3x scheme: hi*hi + hi*lo + lo*hi  (drop lo*lo, ~2^-22)
__device__ __forceinline__ void mma3(float* d,
    const uint32_t ah[4], const uint32_t al[4],
    const uint32_t bh[2], const uint32_t bl[2])
{
    mma_tf32(d, ah[0], ah[1], ah[2], ah[3], bh[0], bh[1]);
    mma_tf32(d, ah[0], ah[1], ah[2], ah[3], bl[0], bl[1]);
    mma_tf32(d, al[0], al[1], al[2], al[3], bh[0], bh[1]);
}

// ---------------------------------------------------------------------------
// GEMM: C[M,N] = A[M,K] @ B[K,N] + bias[N], tf32 mma, 128x128x16 tiles.
// 256 threads = 8 warps (2 x 4). Warp tile 64x32: 4 m16 x 4 n8 mma tiles.
// smem: As[m][k] stride 20 (conflict-free A frags), Bs[k][n] stride 136.
// ---------------------------------------------------------------------------
#define AS_S 20
#define BS_S 136
__global__ __launch_bounds__(256) void gemm_tf32_kernel(
    const float* __restrict__ A, const float* __restrict__ B,
    const float* __restrict__ bias, float* __restrict__ C,
    int M, int N, int K)
{
    __shared__ float As[128 * AS_S];
    __shared__ float Bs[16 * BS_S];

    const int tid   = threadIdx.x;
    const int lane  = tid & 31;
    const int wid   = tid >> 5;
    const int g     = lane >> 2;
    const int tg    = lane & 3;
    const int warpM = wid >> 2;      // 0..1
    const int warpN = wid & 3;       // 0..3
    const int rowBase = blockIdx.y * 128;
    const int colBase = blockIdx.x * 128;

    float acc[4][4][4];
    #pragma unroll
    for (int mt = 0; mt < 4; mt++)
        #pragma unroll
        for (int nt = 0; nt < 4; nt++)
            #pragma unroll
            for (int i = 0; i < 4; i++) acc[mt][nt][i] = 0.f;

    for (int kt = 0; kt < K; kt += 16) {
        #pragma unroll
        for (int l = 0; l < 2; l++) {
            int id  = tid + l * 256;
            int ar  = id >> 2;
            int ac4 = (id & 3) * 4;
            float4 av = *(const float4*)&A[(size_t)(rowBase + ar) * K + kt + ac4];
            As[ar * AS_S + ac4 + 0] = av.x;
            As[ar * AS_S + ac4 + 1] = av.y;
            As[ar * AS_S + ac4 + 2] = av.z;
            As[ar * AS_S + ac4 + 3] = av.w;
            int br  = id >> 5;
            int bc4 = (id & 31) * 4;
            *(float4*)&Bs[br * BS_S + bc4] =
                *(const float4*)&B[(size_t)(kt + br) * N + colBase + bc4];
        }
        __syncthreads();

        #pragma unroll
        for (int kk = 0; kk < 16; kk += 8) {
            uint32_t bh[4][2], bl[4][2];
            #pragma unroll
            for (int nt = 0; nt < 4; nt++) {
                int n0 = warpN * 32 + nt * 8 + g;
                float b0 = Bs[(kk + tg) * BS_S + n0];
                float b1 = Bs[(kk + tg + 4) * BS_S + n0];
                split_tf32(b0, bh[nt][0], bl[nt][0]);
                split_tf32(b1, bh[nt][1], bl[nt][1]);
            }
            #pragma unroll
            for (int mt = 0; mt < 4; mt++) {
                int m0 = warpM * 64 + mt * 16;
                float a0 = As[(m0 + g) * AS_S + kk + tg];
                float a1 = As[(m0 + g + 8) * AS_S + kk + tg];
                float a2 = As[(m0 + g) * AS_S + kk + tg + 4];
                float a3 = As[(m0 + g + 8) * AS_S + kk + tg + 4];
                uint32_t ah[4], al[4];
                split_tf32(a0, ah[0], al[0]);
                split_tf32(a1, ah[1], al[1]);
                split_tf32(a2, ah[2], al[2]);
                split_tf32(a3, ah[3], al[3]);
                #pragma unroll
                for (int nt = 0; nt < 4; nt++)
                    mma3(acc[mt][nt], ah, al, bh[nt], bl[nt]);
            }
        }
        __syncthreads();
    }

    #pragma unroll
    for (int mt = 0; mt < 4; mt++) {
        #pragma unroll
        for (int nt = 0; nt < 4; nt++) {
            int r0 = rowBase + warpM * 64 + mt * 16 + g;
            int c0 = colBase + warpN * 32 + nt * 8 + tg * 2;
            float bz0 = bias[c0], bz1 = bias[c0 + 1];
            float2 o01 = make_float2(acc[mt][nt][0] + bz0, acc[mt][nt][1] + bz1);
            float2 o23 = make_float2(acc[mt][nt][2] + bz0, acc[mt][nt][3] + bz1);
            *(float2*)&C[(size_t)r0 * N + c0] = o01;
            *(float2*)&C[(size_t)(r0 + 8) * N + c0] = o23;
        }
    }
}

// ---------------------------------------------------------------------------
// Fused RBF attention, tensor-core version.
// dist2 via augmented GEMM: A-row i = [-2*k_i (64), kn_i, 1, 0...](72),
//                           B-row j = [q_j (64),    1, qn_j, 0...](72)
// S = exp(-sigma*dist2); out = S @ V.   CTA: 64 i-rows, loop 64-j tiles.
// 8 warps 2x4: S warp-tile 32i x 16j; out warp-tile 32i x 16d.
// ---------------------------------------------------------------------------
#define KS_S 76
#define QS_S 76
#define VS_S 72
#define SS_S 68
#define ATT_SMEM_FLOATS (64*KS_S + 64*QS_S + 64*VS_S + 64*SS_S)
#define ATT_SMEM_BYTES  (ATT_SMEM_FLOATS * 4)

__global__ __launch_bounds__(256) void attn_rbf_tc_kernel(
    const float* __restrict__ qkv, const float* __restrict__ rsig,
    float* __restrict__ attn)
{
    extern __shared__ float sm[];
    float* ks = sm;                    // [64][KS_S]
    float* qs = ks + 64 * KS_S;        // [64][QS_S]
    float* vs = qs + 64 * QS_S;        // [64][VS_S]
    float* Ss = vs + 64 * VS_S;        // [64][SS_S]

    const int tid   = threadIdx.x;
    const int lane  = tid & 31;
    const int wid   = tid >> 5;
    const int g     = lane >> 2;
    const int tg    = lane & 3;
    const int warpM = wid >> 2;        // 0..1  (i: 32 rows each)
    const int warpN = wid & 3;         // 0..3  (j or d: 16 cols each)
    const int b     = blockIdx.y / NH;
    const int h     = blockIdx.y % NH;
    const int i0    = blockIdx.x * 64;
    const float sigma = *rsig;

    const size_t rowbase = (size_t)b * T_SEQ * QKV_N;
    const float* qbase = qkv + rowbase + 0 * DIM + h * HD;
    const float* kbase = qkv + rowbase + 1 * DIM + h * HD;
    const float* vbase = qkv + rowbase + 2 * DIM + h * HD;

    // ---- K tile: store -2*k, then kn/1/zeros in cols 64..71 ----
    #pragma unroll
    for (int l = 0; l < 4; l++) {
        int id = tid + l * 256;
        int r  = id >> 4;
        int c4 = (id & 15) * 4;
        float4 kv = *(const float4*)&kbase[(size_t)(i0 + r) * QKV_N + c4];
        kv.x *= -2.f; kv.y *= -2.f; kv.z *= -2.f; kv.w *= -2.f;
        *(float4*)&ks[r * KS_S + c4] = kv;
    }
    __syncthreads();
    {
        int r = tid >> 2, part = tid & 3;
        const float* row = &ks[r * KS_S + part * 16];
        float s = 0.f;
        #pragma unroll
        for (int i = 0; i < 4; i++) {
            float4 v = *(const float4*)&row[i * 4];
            s += v.x*v.x + v.y*v.y + v.z*v.z + v.w*v.w;
        }
        s += __shfl_xor_sync(0xffffffffu, s, 1);
        s += __shfl_xor_sync(0xffffffffu, s, 2);
        if (part == 0) {
            ks[r * KS_S + 64] = 0.25f * s;   // kn (stored values were -2k)
            ks[r * KS_S + 65] = 1.0f;
        } else {
            ks[r * KS_S + 64 + part * 2] = 0.f;
            ks[r * KS_S + 65 + part * 2] = 0.f;
        }
    }
    __syncthreads();

    float out[2][2][4];
    #pragma unroll
    for (int mt = 0; mt < 2; mt++)
        #pragma unroll
        for (int nt = 0; nt < 2; nt++)
            #pragma unroll
            for (int i = 0; i < 4; i++) out[mt][nt][i] = 0.f;

    for (int jt = 0; jt < T_SEQ / 64; jt++) {
        const int j0 = jt * 64;

        // ---- load q, v tiles ----
        #pragma unroll
        for (int l = 0; l < 4; l++) {
            int id = tid + l * 256;
            int r  = id >> 4;
            int c4 = (id & 15) * 4;
            float4 qv = *(const float4*)&qbase[(size_t)(j0 + r) * QKV_N + c4];
            *(float4*)&qs[r * QS_S + c4] = qv;
            float4 vv = *(const float4*)&vbase[(size_t)(j0 + r) * QKV_N + c4];
            *(float4*)&vs[r * VS_S + c4] = vv;
        }
        __syncthreads();
        {
            int r = tid >> 2, part = tid & 3;
            const float* row = &qs[r * QS_S + part * 16];
            float s = 0.f;
            #pragma unroll
            for (int i = 0; i < 4; i++) {
                float4 v = *(const float4*)&row[i * 4];
                s += v.x*v.x + v.y*v.y + v.z*v.z + v.w*v.w;
            }
            s += __shfl_xor_sync(0xffffffffu, s, 1);
            s += __shfl_xor_sync(0xffffffffu, s, 2);
            if (part == 0) {
                qs[r * QS_S + 64] = 1.0f;
                qs[r * QS_S + 65] = s;       // qn
            } else {
                qs[r * QS_S + 64 + part * 2] = 0.f;
                qs[r * QS_S + 65 + part * 2] = 0.f;
            }
        }
        __syncthreads();

        // ---- S = dist2 via mma over 72 dims ----
        float sacc[2][2][4];
        #pragma unroll
        for (int mt = 0; mt < 2; mt++)
            #pragma unroll
            for (int nt = 0; nt < 2; nt++)
                #pragma unroll
                for (int i = 0; i < 4; i++) sacc[mt][nt][i] = 0.f;

        #pragma unroll
        for (int kk = 0; kk < 72; kk += 8) {
            uint32_t bh[2][2], bl[2][2];
            #pragma unroll
            for (int nt = 0; nt < 2; nt++) {
                int n0 = warpN * 16 + nt * 8 + g;      // j index
                float b0 = qs[n0 * QS_S + kk + tg];
                float b1 = qs[n0 * QS_S + kk + tg + 4];
                split_tf32(b0, bh[nt][0], bl[nt][0]);
                split_tf32(b1, bh[nt][1], bl[nt][1]);
            }
            #pragma unroll
            for (int mt = 0; mt < 2; mt++) {
                int m0 = warpM * 32 + mt * 16;
                float a0 = ks[(m0 + g) * KS_S + kk + tg];
                float a1 = ks[(m0 + g + 8) * KS_S + kk + tg];
                float a2 = ks[(m0 + g) * KS_S + kk + tg + 4];
                float a3 = ks[(m0 + g + 8) * KS_S + kk + tg + 4];
                uint32_t ah[4], al[4];
                split_tf32(a0, ah[0], al[0]);
                split_tf32(a1, ah[1], al[1]);
                split_tf32(a2, ah[2], al[2]);
                split_tf32(a3, ah[3], al[3]);
                #pragma unroll
                for (int nt = 0; nt < 2; nt++)
                    mma3(sacc[mt][nt], ah, al, bh[nt], bl[nt]);
            }
        }

        // ---- exp, write S to smem ----
        #pragma unroll
        for (int mt = 0; mt < 2; mt++) {
            #pragma unroll
            for (int nt = 0; nt < 2; nt++) {
                int si = warpM * 32 + mt * 16 + g;
                int sj = warpN * 16 + nt * 8 + tg * 2;
                Ss[si * SS_S + sj]           = __expf(-sigma * sacc[mt][nt][0]);
                Ss[si * SS_S + sj + 1]       = __expf(-sigma * sacc[mt][nt][1]);
                Ss[(si + 8) * SS_S + sj]     = __expf(-sigma * sacc[mt][nt][2]);
                Ss[(si + 8) * SS_S + sj + 1] = __expf(-sigma * sacc[mt][nt][3]);
            }
        }
        __syncthreads();

        // ---- out += S @ V ----
        #pragma unroll
        for (int kk = 0; kk < 64; kk += 8) {
            uint32_t bh[2][2], bl[2][2];
            #pragma unroll
            for (int nt = 0; nt < 2; nt++) {
                int n0 = warpN * 16 + nt * 8 + g;      // d index
                float b0 = vs[(kk + tg) * VS_S + n0];
                float b1 = vs[(kk + tg + 4) * VS_S + n0];
                split_tf32(b0, bh[nt][0], bl[nt][0]);
                split_tf32(b1, bh[nt][1], bl[nt][1]);
            }
            #pragma unroll
            for (int mt = 0; mt < 2; mt++) {
                int m0 = warpM * 32 + mt * 16;
                float a0 = Ss[(m0 + g) * SS_S + kk + tg];
                float a1 = Ss[(m0 + g + 8) * SS_S + kk + tg];
                float a2 = Ss[(m0 + g) * SS_S + kk + tg + 4];
                float a3 = Ss[(m0 + g + 8) * SS_S + kk + tg + 4];
                uint32_t ah[4], al[4];
                split_tf32(a0, ah[0], al[0]);
                split_tf32(a1, ah[1], al[1]);
                split_tf32(a2, ah[2], al[2]);
                split_tf32(a3, ah[3], al[3]);
                #pragma unroll
                for (int nt = 0; nt < 2; nt++)
                    mma3(out[mt][nt], ah, al, bh[nt], bl[nt]);
            }
        }
        __syncthreads();
    }

    // ---- epilogue: write (b,t,h,d) layout ----
    #pragma unroll
    for (int mt = 0; mt < 2; mt++) {
        #pragma unroll
        for (int nt = 0; nt < 2; nt++) {
            int irow = i0 + warpM * 32 + mt * 16 + g;
            int dcol = warpN * 16 + nt * 8 + tg * 2;
            size_t base = ((size_t)b * T_SEQ + irow) * DIM + h * HD + dcol;
            *(float2*)&attn[base] = make_float2(out[mt][nt][0], out[mt][nt][1]);
            *(float2*)&attn[base + (size_t)8 * DIM] =
                make_float2(out[mt][nt][2], out[mt][nt][3]);
        }
    }
}

// ---------------------------------------------------------------------------
extern "C" void kernel_launch(void* const* d_in, const int* in_sizes, int n_in,
                              void* d_out, int out_size)
{
    const float* x     = (const float*)d_in[0];
    const float* Wqkv  = (const float*)d_in[1];
    const float* bqkv  = (const float*)d_in[2];
    const float* rsig  = (const float*)d_in[3];
    const float* Wproj = (const float*)d_in[4];
    const float* bproj = (const float*)d_in[5];
    float* out = (float*)d_out;

    float *qkv_buf, *attn_buf;
    cudaGetSymbolAddress((void**)&qkv_buf, g_qkv);
    cudaGetSymbolAddress((void**)&attn_buf, g_attn);

    static bool attr_set = false;
    if (!attr_set) {
        cudaFuncSetAttribute(attn_rbf_tc_kernel,
                             cudaFuncAttributeMaxDynamicSharedMemorySize,
                             ATT_SMEM_BYTES);
        attr_set = true;
    }

    // Stage 1: qkv = x @ Wqkv + bqkv
    {
        dim3 grid(QKV_N / 128, ROWS / 128);
        gemm_tf32_kernel<<<grid, 256>>>(x, Wqkv, bqkv, qkv_buf,
                                        ROWS, QKV_N, CDIM);
    }
    // Stage 2: fused RBF attention
    {
        dim3 grid(T_SEQ / 64, BATCH * NH);
        attn_rbf_tc_kernel<<<grid, 256, ATT_SMEM_BYTES>>>(qkv_buf, rsig, attn_buf);
    }
    // Stage 3: out = attn @ Wproj + bproj
    {
        dim3 grid(CDIM / 128, ROWS / 128);
        gemm_tf32_kernel<<<grid, 256>>>(attn_buf, Wproj, bproj, out,
                                        ROWS, CDIM, DIM);
    }
}

// round 3
// speedup vs baseline: 2.4116x; 1.3996x over previous
#include <cuda_runtime.h>
#include <cuda_fp16.h>
#include <cstdint>
#include <cstddef>

// Problem constants
#define BATCH   2
#define T_SEQ   2048
#define CDIM    1024
#define DIM     1024
#define NH      16
#define HD      64
#define QKV_N   3072
#define ROWS    (BATCH*T_SEQ)

// ---------------------------------------------------------------------------
// Device scratch (allocation-free rule). All 16B aligned for int4/cp.async.
// ---------------------------------------------------------------------------
__device__ __align__(16) __half g_x_hi[ROWS * CDIM];
__device__ __align__(16) __half g_x_lo[ROWS * CDIM];
__device__ __align__(16) __half2 g_wqkv_hi[(CDIM/2) * QKV_N];  // [K/2][N] k-pair packed
__device__ __align__(16) __half2 g_wqkv_lo[(CDIM/2) * QKV_N];
__device__ __align__(16) __half2 g_wproj_hi[(DIM/2) * CDIM];
__device__ __align__(16) __half2 g_wproj_lo[(DIM/2) * CDIM];
__device__ __align__(16) __half g_qkv_hi[ROWS * QKV_N];        // [row][3072]
__device__ __align__(16) __half g_qkv_lo[ROWS * QKV_N];
__device__ __align__(16) __half2 g_vT_hi[BATCH*NH * HD * (T_SEQ/2)]; // [bh][d][T/2]
__device__ __align__(16) __half2 g_vT_lo[BATCH*NH * HD * (T_SEQ/2)];
__device__ __align__(16) __half g_attn_hi[ROWS * DIM];
__device__ __align__(16) __half g_attn_lo[ROWS * DIM];

// ---------------------------------------------------------------------------
// helpers
// ---------------------------------------------------------------------------
__device__ __forceinline__ void split_h(float x, __half& hi, __half& lo) {
    hi = __float2half_rn(x);
    lo = __float2half_rn(x - __half2float(hi));
}
__device__ __forceinline__ void split2(float a, float b, __half2& h, __half2& l) {
    __half ha, la, hb, lb;
    split_h(a, ha, la);
    split_h(b, hb, lb);
    h = __halves2half2(ha, hb);
    l = __halves2half2(la, lb);
}

__device__ __forceinline__ void mma_h(float* d,
    uint32_t a0, uint32_t a1, uint32_t a2, uint32_t a3,
    uint32_t b0, uint32_t b1)
{
    asm volatile(
        "mma.sync.aligned.m16n8k16.row.col.f32.f16.f16.f32 "
        "{%0,%1,%2,%3}, {%4,%5,%6,%7}, {%8,%9}, {%0,%1,%2,%3};\n"
        : "+f"(d[0]), "+f"(d[1]), "+f"(d[2]), "+f"(d[3])
        : "r"(a0), "r"(a1), "r"(a2), "r"(a3), "r"(b0), "r"(b1));
}
// hi*hi + hi*lo + lo*hi
__device__ __forceinline__ void mma3(float* d,
    const uint32_t ah[4], const uint32_t al[4],
    const uint32_t bh[2], const uint32_t bl[2])
{
    mma_h(d, ah[0], ah[1], ah[2], ah[3], bh[0], bh[1]);
    mma_h(d, ah[0], ah[1], ah[2], ah[3], bl[0], bl[1]);
    mma_h(d, al[0], al[1], al[2], al[3], bh[0], bh[1]);
}

__device__ __forceinline__ void cp16(void* dst, const void* src) {
    uint32_t d = (uint32_t)__cvta_generic_to_shared(dst);
    asm volatile("cp.async.cg.shared.global [%0], [%1], 16;\n" :: "r"(d), "l"(src));
}
__device__ __forceinline__ void cp_commit() { asm volatile("cp.async.commit_group;\n"); }
template<int N> __device__ __forceinline__ void cp_wait() {
    asm volatile("cp.async.wait_group %0;\n" :: "n"(N));
}

// ---------------------------------------------------------------------------
// Prep: split fp32 -> hi/lo halves (elementwise, float4 per thread)
// ---------------------------------------------------------------------------
__global__ void split_kernel(const float* __restrict__ src,
                             __half2* __restrict__ hi, __half2* __restrict__ lo,
                             int n4)
{
    int i = blockIdx.x * blockDim.x + threadIdx.x;
    if (i >= n4) return;
    float4 v = *(const float4*)(src + (size_t)i * 4);
    __half2 h0, l0, h1, l1;
    split2(v.x, v.y, h0, l0);
    split2(v.z, v.w, h1, l1);
    hi[(size_t)i * 2]     = h0;
    hi[(size_t)i * 2 + 1] = h1;
    lo[(size_t)i * 2]     = l0;
    lo[(size_t)i * 2 + 1] = l1;
}

// Pack weights: W[K][N] fp32 -> [K/2][N] half2 (k-pair in one half2)
__global__ void pack_w_kernel(const float* __restrict__ W,
                              __half2* __restrict__ hi, __half2* __restrict__ lo,
                              int K, int N)
{
    int idx = blockIdx.x * blockDim.x + threadIdx.x;
    int total = (K / 2) * (N / 4);
    if (idx >= total) return;
    int kp = idx / (N / 4);
    int n4 = (idx % (N / 4)) * 4;
    float4 r0 = *(const float4*)(W + (size_t)(2 * kp) * N + n4);
    float4 r1 = *(const float4*)(W + (size_t)(2 * kp + 1) * N + n4);
    const float a[4] = {r0.x, r0.y, r0.z, r0.w};
    const float b[4] = {r1.x, r1.y, r1.z, r1.w};
    #pragma unroll
    for (int t = 0; t < 4; t++) {
        __half h0, l0, h1, l1;
        split_h(a[t], h0, l0);
        split_h(b[t], h1, l1);
        hi[(size_t)kp * N + n4 + t] = __halves2half2(h0, h1);
        lo[(size_t)kp * N + n4 + t] = __halves2half2(l0, l1);
    }
}

// ---------------------------------------------------------------------------
// GEMM: C[M,N] = (Ahi+Alo)[M,K] @ W[K,N] + bias, fp16 split mma, cp.async 2-stage.
// BM=128 BN=128 BK=16. 256 thr = 8 warps (2x4), warp tile 64x32, 4x4 mma tiles.
// ---------------------------------------------------------------------------
#define AS_S 12     // half2 stride per m-row (8 used + 4 pad) -> conflict-free
#define BS_S 132    // half2 stride per kp-row (128 used + 4 pad)

template<bool SPLIT_OUT>
__global__ __launch_bounds__(256) void gemm_h2_kernel(
    const __half* __restrict__ Ahi, const __half* __restrict__ Alo,
    const __half2* __restrict__ Bhi, const __half2* __restrict__ Blo,
    const float* __restrict__ bias,
    float* __restrict__ Cf, __half2* __restrict__ Chi, __half2* __restrict__ Clo,
    int M, int N, int K)
{
    __shared__ __half2 As[2][2][128 * AS_S];
    __shared__ __half2 Bs[2][2][8 * BS_S];

    const int tid   = threadIdx.x;
    const int lane  = tid & 31;
    const int wid   = tid >> 5;
    const int g     = lane >> 2;
    const int tg    = lane & 3;
    const int warpM = wid >> 2;
    const int warpN = wid & 3;
    const int rowBase = blockIdx.y * 128;
    const int colBase = blockIdx.x * 128;

    // load assignments
    const int am = tid >> 1;          // 0..127
    const int ac = tid & 1;           // int4 chunk (8 halves)
    const int bkp = tid >> 5;         // 0..7
    const int bn  = (lane) * 4;       // half2 col

    float acc[4][4][4];
    #pragma unroll
    for (int mt = 0; mt < 4; mt++)
        #pragma unroll
        for (int nt = 0; nt < 4; nt++)
            #pragma unroll
            for (int i = 0; i < 4; i++) acc[mt][nt][i] = 0.f;

    const int NT = K / 16;

    auto issue = [&](int s, int kt) {
        cp16(&As[s][0][am * AS_S + ac * 4], Ahi + (size_t)(rowBase + am) * K + kt + ac * 8);
        cp16(&As[s][1][am * AS_S + ac * 4], Alo + (size_t)(rowBase + am) * K + kt + ac * 8);
        cp16(&Bs[s][0][bkp * BS_S + bn], Bhi + (size_t)((kt >> 1) + bkp) * N + colBase + bn);
        cp16(&Bs[s][1][bkp * BS_S + bn], Blo + (size_t)((kt >> 1) + bkp) * N + colBase + bn);
    };

    issue(0, 0);
    cp_commit();

    for (int t = 0; t < NT; t++) {
        if (t + 1 < NT) {
            issue((t + 1) & 1, (t + 1) * 16);
            cp_commit();
            cp_wait<1>();
        } else {
            cp_wait<0>();
        }
        __syncthreads();

        const int s = t & 1;
        // B frags
        uint32_t bh[4][2], bl[4][2];
        #pragma unroll
        for (int nt = 0; nt < 4; nt++) {
            int n0 = warpN * 32 + nt * 8 + g;
            bh[nt][0] = *(const uint32_t*)&Bs[s][0][tg * BS_S + n0];
            bh[nt][1] = *(const uint32_t*)&Bs[s][0][(tg + 4) * BS_S + n0];
            bl[nt][0] = *(const uint32_t*)&Bs[s][1][tg * BS_S + n0];
            bl[nt][1] = *(const uint32_t*)&Bs[s][1][(tg + 4) * BS_S + n0];
        }
        #pragma unroll
        for (int mt = 0; mt < 4; mt++) {
            int m0 = warpM * 64 + mt * 16;
            uint32_t ah[4], al[4];
            ah[0] = *(const uint32_t*)&As[s][0][(m0 + g) * AS_S + tg];
            ah[1] = *(const uint32_t*)&As[s][0][(m0 + g + 8) * AS_S + tg];
            ah[2] = *(const uint32_t*)&As[s][0][(m0 + g) * AS_S + tg + 4];
            ah[3] = *(const uint32_t*)&As[s][0][(m0 + g + 8) * AS_S + tg + 4];
            al[0] = *(const uint32_t*)&As[s][1][(m0 + g) * AS_S + tg];
            al[1] = *(const uint32_t*)&As[s][1][(m0 + g + 8) * AS_S + tg];
            al[2] = *(const uint32_t*)&As[s][1][(m0 + g) * AS_S + tg + 4];
            al[3] = *(const uint32_t*)&As[s][1][(m0 + g + 8) * AS_S + tg + 4];
            #pragma unroll
            for (int nt = 0; nt < 4; nt++)
                mma3(acc[mt][nt], ah, al, bh[nt], bl[nt]);
        }
        __syncthreads();
    }

    // epilogue
    #pragma unroll
    for (int mt = 0; mt < 4; mt++) {
        #pragma unroll
        for (int nt = 0; nt < 4; nt++) {
            int r0 = rowBase + warpM * 64 + mt * 16 + g;
            int c0 = colBase + warpN * 32 + nt * 8 + tg * 2;
            float bz0 = bias[c0], bz1 = bias[c0 + 1];
            float v0 = acc[mt][nt][0] + bz0, v1 = acc[mt][nt][1] + bz1;
            float v2 = acc[mt][nt][2] + bz0, v3 = acc[mt][nt][3] + bz1;
            if (SPLIT_OUT) {
                __half2 h, l;
                split2(v0, v1, h, l);
                Chi[(size_t)r0 * (N / 2) + c0 / 2] = h;
                Clo[(size_t)r0 * (N / 2) + c0 / 2] = l;
                split2(v2, v3, h, l);
                Chi[(size_t)(r0 + 8) * (N / 2) + c0 / 2] = h;
                Clo[(size_t)(r0 + 8) * (N / 2) + c0 / 2] = l;
            } else {
                *(float2*)&Cf[(size_t)r0 * N + c0] = make_float2(v0, v1);
                *(float2*)&Cf[(size_t)(r0 + 8) * N + c0] = make_float2(v2, v3);
            }
        }
    }
}

// ---------------------------------------------------------------------------
// Repack V: qkv v-region [row][d] halves -> vT [bh][d][T/2] half2 (j-pairs)
// grid: (T/64, B*NH), 256 threads, via smem transpose tile
// ---------------------------------------------------------------------------
#define VT_S 36
__global__ __launch_bounds__(256) void repack_v_kernel(
    const __half* __restrict__ qkv_hi, const __half* __restrict__ qkv_lo,
    __half2* __restrict__ vT_hi, __half2* __restrict__ vT_lo)
{
    __shared__ __half2 sm_hi[64 * VT_S];
    __shared__ __half2 sm_lo[64 * VT_S];
    const int tid = threadIdx.x;
    const int bh  = blockIdx.y;
    const int b   = bh / NH;
    const int h   = bh % NH;
    const int j0  = blockIdx.x * 64;

    const size_t base = ((size_t)(b * T_SEQ + j0)) * QKV_N + 2 * DIM + h * HD;
    #pragma unroll
    for (int l = 0; l < 2; l++) {
        int id = tid + l * 256;
        int r  = id >> 3;
        int c  = id & 7;
        *(int4*)&sm_hi[r * VT_S + c * 4] = *(const int4*)(qkv_hi + base + (size_t)r * QKV_N + c * 8);
        *(int4*)&sm_lo[r * VT_S + c * 4] = *(const int4*)(qkv_lo + base + (size_t)r * QKV_N + c * 8);
    }
    __syncthreads();
    #pragma unroll
    for (int l = 0; l < 8; l++) {
        int id = tid + l * 256;
        int d  = id >> 5;         // 0..63
        int jp = id & 31;         // 0..31
        __half2 a = sm_hi[(2 * jp) * VT_S + (d >> 1)];
        __half2 c = sm_hi[(2 * jp + 1) * VT_S + (d >> 1)];
        __half va = (d & 1) ? __high2half(a) : __low2half(a);
        __half vc = (d & 1) ? __high2half(c) : __low2half(c);
        vT_hi[((size_t)bh * HD + d) * (T_SEQ / 2) + j0 / 2 + jp] = __halves2half2(va, vc);
        a = sm_lo[(2 * jp) * VT_S + (d >> 1)];
        c = sm_lo[(2 * jp + 1) * VT_S + (d >> 1)];
        va = (d & 1) ? __high2half(a) : __low2half(a);
        vc = (d & 1) ? __high2half(c) : __low2half(c);
        vT_lo[((size_t)bh * HD + d) * (T_SEQ / 2) + j0 / 2 + jp] = __halves2half2(va, vc);
    }
}

// ---------------------------------------------------------------------------
// Fused RBF attention, fp16-split mma.
// S = exp(-sigma*(kn_i + qn_j - 2 k.q)); out = S @ V
// CTA: 64 i-rows x full j loop (64-j tiles). 8 warps 2x4.
// smem arrays [64][36] half2: ks(hi,lo), qs(hi,lo | aliased Ss), vT(hi,lo)
// ---------------------------------------------------------------------------
#define AT_S 36
#define ATT_SMEM_BYTES (6 * 64 * AT_S * 4 + 2 * 64 * 4)

__global__ __launch_bounds__(256) void attn_h2_kernel(
    const __half* __restrict__ qkv_hi, const __half* __restrict__ qkv_lo,
    const __half2* __restrict__ vT_hi, const __half2* __restrict__ vT_lo,
    const float* __restrict__ rsig,
    __half2* __restrict__ attn_hi, __half2* __restrict__ attn_lo)
{
    extern __shared__ char smraw[];
    __half2* ks_hi = (__half2*)smraw;
    __half2* ks_lo = ks_hi + 64 * AT_S;
    __half2* qs_hi = ks_lo + 64 * AT_S;   // aliased as Ss_hi after S-mma
    __half2* qs_lo = qs_hi + 64 * AT_S;   // aliased as Ss_lo
    __half2* vs_hi = qs_lo + 64 * AT_S;
    __half2* vs_lo = vs_hi + 64 * AT_S;
    float*   knv   = (float*)(vs_lo + 64 * AT_S);
    float*   qnv   = knv + 64;

    const int tid   = threadIdx.x;
    const int lane  = tid & 31;
    const int wid   = tid >> 5;
    const int g     = lane >> 2;
    const int tg    = lane & 3;
    const int warpM = wid >> 2;
    const int warpN = wid & 3;
    const int bh    = blockIdx.y;
    const int b     = bh / NH;
    const int h     = bh % NH;
    const int i0    = blockIdx.x * 64;
    const float nsig = -rsig[0];

    const size_t qoff = (size_t)b * T_SEQ * QKV_N + 0 * DIM + h * HD;
    const size_t koff = (size_t)b * T_SEQ * QKV_N + 1 * DIM + h * HD;

    // ---- load K tile ----
    #pragma unroll
    for (int l = 0; l < 2; l++) {
        int id = tid + l * 256;
        int r  = id >> 3;
        int c  = id & 7;
        *(int4*)&ks_hi[r * AT_S + c * 4] =
            *(const int4*)(qkv_hi + koff + (size_t)(i0 + r) * QKV_N + c * 8);
        *(int4*)&ks_lo[r * AT_S + c * 4] =
            *(const int4*)(qkv_lo + koff + (size_t)(i0 + r) * QKV_N + c * 8);
    }
    __syncthreads();
    // ---- kn ----
    {
        int r = tid >> 2, part = tid & 3;
        float s = 0.f;
        #pragma unroll
        for (int i = 0; i < 8; i++) {
            __half2 hh = ks_hi[r * AT_S + part * 8 + i];
            __half2 ll = ks_lo[r * AT_S + part * 8 + i];
            float2 hf = __half22float2(hh), lf = __half22float2(ll);
            float a = hf.x + lf.x, c = hf.y + lf.y;
            s += a * a + c * c;
        }
        s += __shfl_xor_sync(0xffffffffu, s, 1);
        s += __shfl_xor_sync(0xffffffffu, s, 2);
        if (part == 0) knv[r] = s;
    }

    float out[2][2][4];
    #pragma unroll
    for (int mt = 0; mt < 2; mt++)
        #pragma unroll
        for (int nt = 0; nt < 2; nt++)
            #pragma unroll
            for (int i = 0; i < 4; i++) out[mt][nt][i] = 0.f;

    for (int jt = 0; jt < T_SEQ / 64; jt++) {
        const int j0 = jt * 64;
        __syncthreads();  // prior S@V reads done (and kn visible on jt==0)

        // ---- load q tile + vT tile ----
        #pragma unroll
        for (int l = 0; l < 2; l++) {
            int id = tid + l * 256;
            int r  = id >> 3;
            int c  = id & 7;
            *(int4*)&qs_hi[r * AT_S + c * 4] =
                *(const int4*)(qkv_hi + qoff + (size_t)(j0 + r) * QKV_N + c * 8);
            *(int4*)&qs_lo[r * AT_S + c * 4] =
                *(const int4*)(qkv_lo + qoff + (size_t)(j0 + r) * QKV_N + c * 8);
            const size_t vbase = ((size_t)bh * HD + r) * (T_SEQ / 2) + j0 / 2;
            *(int4*)&vs_hi[r * AT_S + c * 4] = *(const int4*)(vT_hi + vbase + c * 4);
            *(int4*)&vs_lo[r * AT_S + c * 4] = *(const int4*)(vT_lo + vbase + c * 4);
        }
        __syncthreads();
        // ---- qn ----
        {
            int r = tid >> 2, part = tid & 3;
            float s = 0.f;
            #pragma unroll
            for (int i = 0; i < 8; i++) {
                __half2 hh = qs_hi[r * AT_S + part * 8 + i];
                __half2 ll = qs_lo[r * AT_S + part * 8 + i];
                float2 hf = __half22float2(hh), lf = __half22float2(ll);
                float a = hf.x + lf.x, c = hf.y + lf.y;
                s += a * a + c * c;
            }
            s += __shfl_xor_sync(0xffffffffu, s, 1);
            s += __shfl_xor_sync(0xffffffffu, s, 2);
            if (part == 0) qnv[r] = s;
        }
        __syncthreads();

        // ---- S-mma: dot[i][j] over 64 dims ----
        float sacc[2][2][4];
        #pragma unroll
        for (int mt = 0; mt < 2; mt++)
            #pragma unroll
            for (int nt = 0; nt < 2; nt++)
                #pragma unroll
                for (int i = 0; i < 4; i++) sacc[mt][nt][i] = 0.f;

        #pragma unroll
        for (int kc = 0; kc < 4; kc++) {
            int kp = kc * 8;
            uint32_t bh2[2][2], bl2[2][2];
            #pragma unroll
            for (int nt = 0; nt < 2; nt++) {
                int n0 = warpN * 16 + nt * 8 + g;
                bh2[nt][0] = *(const uint32_t*)&qs_hi[n0 * AT_S + kp + tg];
                bh2[nt][1] = *(const uint32_t*)&qs_hi[n0 * AT_S + kp + tg + 4];
                bl2[nt][0] = *(const uint32_t*)&qs_lo[n0 * AT_S + kp + tg];
                bl2[nt][1] = *(const uint32_t*)&qs_lo[n0 * AT_S + kp + tg + 4];
            }
            #pragma unroll
            for (int mt = 0; mt < 2; mt++) {
                int m0 = warpM * 32 + mt * 16;
                uint32_t ah[4], al[4];
                ah[0] = *(const uint32_t*)&ks_hi[(m0 + g) * AT_S + kp + tg];
                ah[1] = *(const uint32_t*)&ks_hi[(m0 + g + 8) * AT_S + kp + tg];
                ah[2] = *(const uint32_t*)&ks_hi[(m0 + g) * AT_S + kp + tg + 4];
                ah[3] = *(const uint32_t*)&ks_hi[(m0 + g + 8) * AT_S + kp + tg + 4];
                al[0] = *(const uint32_t*)&ks_lo[(m0 + g) * AT_S + kp + tg];
                al[1] = *(const uint32_t*)&ks_lo[(m0 + g + 8) * AT_S + kp + tg];
                al[2] = *(const uint32_t*)&ks_lo[(m0 + g) * AT_S + kp + tg + 4];
                al[3] = *(const uint32_t*)&ks_lo[(m0 + g + 8) * AT_S + kp + tg + 4];
                #pragma unroll
                for (int nt = 0; nt < 2; nt++)
                    mma3(sacc[mt][nt], ah, al, bh2[nt], bl2[nt]);
            }
        }

        // ---- exp in regs ----
        float ev[2][2][4];
        #pragma unroll
        for (int mt = 0; mt < 2; mt++) {
            int si = warpM * 32 + mt * 16 + g;
            float kA = knv[si], kB = knv[si + 8];
            #pragma unroll
            for (int nt = 0; nt < 2; nt++) {
                int jj = warpN * 16 + nt * 8 + tg * 2;
                float qA = qnv[jj], qB = qnv[jj + 1];
                ev[mt][nt][0] = __expf(nsig * (kA + qA - 2.f * sacc[mt][nt][0]));
                ev[mt][nt][1] = __expf(nsig * (kA + qB - 2.f * sacc[mt][nt][1]));
                ev[mt][nt][2] = __expf(nsig * (kB + qA - 2.f * sacc[mt][nt][2]));
                ev[mt][nt][3] = __expf(nsig * (kB + qB - 2.f * sacc[mt][nt][3]));
            }
        }
        __syncthreads();   // all S-mma reads of qs done

        // ---- store S split into qs region (Ss[i][jpair]) ----
        #pragma unroll
        for (int mt = 0; mt < 2; mt++) {
            int si = warpM * 32 + mt * 16 + g;
            #pragma unroll
            for (int nt = 0; nt < 2; nt++) {
                int jp = warpN * 8 + nt * 4 + tg;
                __half2 hh, ll;
                split2(ev[mt][nt][0], ev[mt][nt][1], hh, ll);
                qs_hi[si * AT_S + jp] = hh;
                qs_lo[si * AT_S + jp] = ll;
                split2(ev[mt][nt][2], ev[mt][nt][3], hh, ll);
                qs_hi[(si + 8) * AT_S + jp] = hh;
                qs_lo[(si + 8) * AT_S + jp] = ll;
            }
        }
        __syncthreads();

        // ---- out += S @ V ----
        #pragma unroll
        for (int kc = 0; kc < 4; kc++) {
            int kp = kc * 8;
            uint32_t bh2[2][2], bl2[2][2];
            #pragma unroll
            for (int nt = 0; nt < 2; nt++) {
                int n0 = warpN * 16 + nt * 8 + g;   // d
                bh2[nt][0] = *(const uint32_t*)&vs_hi[n0 * AT_S + kp + tg];
                bh2[nt][1] = *(const uint32_t*)&vs_hi[n0 * AT_S + kp + tg + 4];
                bl2[nt][0] = *(const uint32_t*)&vs_lo[n0 * AT_S + kp + tg];
                bl2[nt][1] = *(const uint32_t*)&vs_lo[n0 * AT_S + kp + tg + 4];
            }
            #pragma unroll
            for (int mt = 0; mt < 2; mt++) {
                int m0 = warpM * 32 + mt * 16;
                uint32_t ah[4], al[4];
                ah[0] = *(const uint32_t*)&qs_hi[(m0 + g) * AT_S + kp + tg];
                ah[1] = *(const uint32_t*)&qs_hi[(m0 + g + 8) * AT_S + kp + tg];
                ah[2] = *(const uint32_t*)&qs_hi[(m0 + g) * AT_S + kp + tg + 4];
                ah[3] = *(const uint32_t*)&qs_hi[(m0 + g + 8) * AT_S + kp + tg + 4];
                al[0] = *(const uint32_t*)&qs_lo[(m0 + g) * AT_S + kp + tg];
                al[1] = *(const uint32_t*)&qs_lo[(m0 + g + 8) * AT_S + kp + tg];
                al[2] = *(const uint32_t*)&qs_lo[(m0 + g) * AT_S + kp + tg + 4];
                al[3] = *(const uint32_t*)&qs_lo[(m0 + g + 8) * AT_S + kp + tg + 4];
                #pragma unroll
                for (int nt = 0; nt < 2; nt++)
                    mma3(out[mt][nt], ah, al, bh2[nt], bl2[nt]);
            }
        }
    }

    // ---- epilogue: split halves in (b,t,h,d) layout ----
    #pragma unroll
    for (int mt = 0; mt < 2; mt++) {
        #pragma unroll
        for (int nt = 0; nt < 2; nt++) {
            int irow = i0 + warpM * 32 + mt * 16 + g;
            int dcol = warpN * 16 + nt * 8 + tg * 2;
            size_t base = ((size_t)(b * T_SEQ + irow)) * (DIM / 2) + (h * HD + dcol) / 2;
            __half2 hh, ll;
            split2(out[mt][nt][0], out[mt][nt][1], hh, ll);
            attn_hi[base] = hh;
            attn_lo[base] = ll;
            split2(out[mt][nt][2], out[mt][nt][3], hh, ll);
            attn_hi[base + (size_t)8 * (DIM / 2)] = hh;
            attn_lo[base + (size_t)8 * (DIM / 2)] = ll;
        }
    }
}

// ---------------------------------------------------------------------------
extern "C" void kernel_launch(void* const* d_in, const int* in_sizes, int n_in,
                              void* d_out, int out_size)
{
    const float* x     = (const float*)d_in[0];
    const float* Wqkv  = (const float*)d_in[1];
    const float* bqkv  = (const float*)d_in[2];
    const float* rsig  = (const float*)d_in[3];
    const float* Wproj = (const float*)d_in[4];
    const float* bproj = (const float*)d_in[5];
    float* out = (float*)d_out;

    __half *x_hi, *x_lo, *qkv_hi, *qkv_lo, *attn_hi, *attn_lo;
    __half2 *wqkv_hi, *wqkv_lo, *wproj_hi, *wproj_lo, *vT_hi, *vT_lo;
    cudaGetSymbolAddress((void**)&x_hi, g_x_hi);
    cudaGetSymbolAddress((void**)&x_lo, g_x_lo);
    cudaGetSymbolAddress((void**)&wqkv_hi, g_wqkv_hi);
    cudaGetSymbolAddress((void**)&wqkv_lo, g_wqkv_lo);
    cudaGetSymbolAddress((void**)&wproj_hi, g_wproj_hi);
    cudaGetSymbolAddress((void**)&wproj_lo, g_wproj_lo);
    cudaGetSymbolAddress((void**)&qkv_hi, g_qkv_hi);
    cudaGetSymbolAddress((void**)&qkv_lo, g_qkv_lo);
    cudaGetSymbolAddress((void**)&vT_hi, g_vT_hi);
    cudaGetSymbolAddress((void**)&vT_lo, g_vT_lo);
    cudaGetSymbolAddress((void**)&attn_hi, g_attn_hi);
    cudaGetSymbolAddress((void**)&attn_lo, g_attn_lo);

    cudaFuncSetAttribute(attn_h2_kernel,
                         cudaFuncAttributeMaxDynamicSharedMemorySize,
                         ATT_SMEM_BYTES);

    // prep: split x, pack weights
    {
        int n4 = ROWS * CDIM / 4;
        split_kernel<<<(n4 + 255) / 256, 256>>>(x, (__half2*)x_hi, (__half2*)x_lo, n4);
        int tq = (CDIM / 2) * (QKV_N / 4);
        pack_w_kernel<<<(tq + 255) / 256, 256>>>(Wqkv, wqkv_hi, wqkv_lo, CDIM, QKV_N);
        int tp = (DIM / 2) * (CDIM / 4);
        pack_w_kernel<<<(tp + 255) / 256, 256>>>(Wproj, wproj_hi, wproj_lo, DIM, CDIM);
    }
    // stage 1: qkv (split output)
    {
        dim3 grid(QKV_N / 128, ROWS / 128);
        gemm_h2_kernel<true><<<grid, 256>>>(x_hi, x_lo, wqkv_hi, wqkv_lo, bqkv,
                                            nullptr, (__half2*)qkv_hi, (__half2*)qkv_lo,
                                            ROWS, QKV_N, CDIM);
    }
    // repack V
    {
        dim3 grid(T_SEQ / 64, BATCH * NH);
        repack_v_kernel<<<grid, 256>>>(qkv_hi, qkv_lo, vT_hi, vT_lo);
    }
    // stage 2: attention
    {
        dim3 grid(T_SEQ / 64, BATCH * NH);
        attn_h2_kernel<<<grid, 256, ATT_SMEM_BYTES>>>(qkv_hi, qkv_lo, vT_hi, vT_lo,
                                                      rsig,
                                                      (__half2*)attn_hi, (__half2*)attn_lo);
    }
    // stage 3: out
    {
        dim3 grid(CDIM / 128, ROWS / 128);
        gemm_h2_kernel<false><<<grid, 256>>>(attn_hi, attn_lo, wproj_hi, wproj_lo, bproj,
                                             out, nullptr, nullptr,
                                             ROWS, CDIM, DIM);
    }
}

// round 5
// speedup vs baseline: 2.8592x; 1.1856x over previous
#include <cuda_runtime.h>
#include <cuda_fp16.h>
#include <cstdint>
#include <cstddef>

// Problem constants
#define BATCH   2
#define T_SEQ   2048
#define CDIM    1024
#define DIM     1024
#define NH      16
#define HD      64
#define QKV_N   3072
#define ROWS    (BATCH*T_SEQ)

// ---------------------------------------------------------------------------
// Device scratch (allocation-free rule). All 16B aligned.
// ---------------------------------------------------------------------------
__device__ __align__(16) __half g_x_hi[ROWS * CDIM];
__device__ __align__(16) __half g_x_lo[ROWS * CDIM];
__device__ __align__(16) __half2 g_wqkv_hi[(CDIM/2) * QKV_N];  // [K/2][N] k-pair packed
__device__ __align__(16) __half2 g_wqkv_lo[(CDIM/2) * QKV_N];
__device__ __align__(16) __half2 g_wproj_hi[(DIM/2) * CDIM];
__device__ __align__(16) __half2 g_wproj_lo[(DIM/2) * CDIM];
__device__ __align__(16) __half g_qkv_hi[ROWS * QKV_N];
__device__ __align__(16) __half g_qkv_lo[ROWS * QKV_N];
__device__ __align__(16) __half2 g_vT_hi[BATCH*NH * HD * (T_SEQ/2)]; // [bh][d][T/2]
__device__ __align__(16) __half2 g_vT_lo[BATCH*NH * HD * (T_SEQ/2)];
__device__ __align__(16) __half g_attn_hi[ROWS * DIM];
__device__ __align__(16) __half g_attn_lo[ROWS * DIM];

// ---------------------------------------------------------------------------
// helpers
// ---------------------------------------------------------------------------
__device__ __forceinline__ void split_h(float x, __half& hi, __half& lo) {
    hi = __float2half_rn(x);
    lo = __float2half_rn(x - __half2float(hi));
}
__device__ __forceinline__ void split2(float a, float b, __half2& h, __half2& l) {
    __half ha, la, hb, lb;
    split_h(a, ha, la);
    split_h(b, hb, lb);
    h = __halves2half2(ha, hb);
    l = __halves2half2(la, lb);
}

__device__ __forceinline__ void mma_h(float* d,
    uint32_t a0, uint32_t a1, uint32_t a2, uint32_t a3,
    uint32_t b0, uint32_t b1)
{
    asm volatile(
        "mma.sync.aligned.m16n8k16.row.col.f32.f16.f16.f32 "
        "{%0,%1,%2,%3}, {%4,%5,%6,%7}, {%8,%9}, {%0,%1,%2,%3};\n"
        : "+f"(d[0]), "+f"(d[1]), "+f"(d[2]), "+f"(d[3])
        : "r"(a0), "r"(a1), "r"(a2), "r"(a3), "r"(b0), "r"(b1));
}
// hi*hi + hi*lo + lo*hi
__device__ __forceinline__ void mma3(float* d,
    const uint32_t ah[4], const uint32_t al[4],
    const uint32_t bh[2], const uint32_t bl[2])
{
    mma_h(d, ah[0], ah[1], ah[2], ah[3], bh[0], bh[1]);
    mma_h(d, ah[0], ah[1], ah[2], ah[3], bl[0], bl[1]);
    mma_h(d, al[0], al[1], al[2], al[3], bh[0], bh[1]);
}

__device__ __forceinline__ void cp16(void* dst, const void* src) {
    uint32_t d = (uint32_t)__cvta_generic_to_shared(dst);
    asm volatile("cp.async.cg.shared.global [%0], [%1], 16;\n" :: "r"(d), "l"(src));
}
__device__ __forceinline__ void cp_commit() { asm volatile("cp.async.commit_group;\n"); }
template<int N> __device__ __forceinline__ void cp_wait() {
    asm volatile("cp.async.wait_group %0;\n" :: "n"(N));
}

// sum of squares of 8 split halves
__device__ __forceinline__ float sumsq8(int4 hbits, int4 lbits) {
    const __half2* h = (const __half2*)&hbits;
    const __half2* l = (const __half2*)&lbits;
    float s = 0.f;
    #pragma unroll
    for (int i = 0; i < 4; i++) {
        float2 a = __half22float2(h[i]);
        float2 b = __half22float2(l[i]);
        float x = a.x + b.x, y = a.y + b.y;
        s += x * x + y * y;
    }
    return s;
}

// ---------------------------------------------------------------------------
// Prep kernels
// ---------------------------------------------------------------------------
__global__ void split_kernel(const float* __restrict__ src,
                             __half2* __restrict__ hi, __half2* __restrict__ lo,
                             int n4)
{
    int i = blockIdx.x * blockDim.x + threadIdx.x;
    if (i >= n4) return;
    float4 v = *(const float4*)(src + (size_t)i * 4);
    __half2 h0, l0, h1, l1;
    split2(v.x, v.y, h0, l0);
    split2(v.z, v.w, h1, l1);
    hi[(size_t)i * 2]     = h0;
    hi[(size_t)i * 2 + 1] = h1;
    lo[(size_t)i * 2]     = l0;
    lo[(size_t)i * 2 + 1] = l1;
}

// Pack weights: W[K][N] fp32 -> [K/2][N] half2 (k-pair in one half2)
__global__ void pack_w_kernel(const float* __restrict__ W,
                              __half2* __restrict__ hi, __half2* __restrict__ lo,
                              int K, int N)
{
    int idx = blockIdx.x * blockDim.x + threadIdx.x;
    int total = (K / 2) * (N / 4);
    if (idx >= total) return;
    int kp = idx / (N / 4);
    int n4 = (idx % (N / 4)) * 4;
    float4 r0 = *(const float4*)(W + (size_t)(2 * kp) * N + n4);
    float4 r1 = *(const float4*)(W + (size_t)(2 * kp + 1) * N + n4);
    const float a[4] = {r0.x, r0.y, r0.z, r0.w};
    const float b[4] = {r1.x, r1.y, r1.z, r1.w};
    #pragma unroll
    for (int t = 0; t < 4; t++) {
        __half h0, l0, h1, l1;
        split_h(a[t], h0, l0);
        split_h(b[t], h1, l1);
        hi[(size_t)kp * N + n4 + t] = __halves2half2(h0, h1);
        lo[(size_t)kp * N + n4 + t] = __halves2half2(l0, l1);
    }
}

// ---------------------------------------------------------------------------
// GEMM: C[M,N] = (Ahi+Alo)[M,K] @ W[K,N] + bias, fp16 split mma.
// BM=128 BN=128 BK=16. 256 thr (8 warps, 2x4), warp tile 64x32, 4x4 mma tiles.
// 3-stage cp.async ring, single __syncthreads per k-step, 2 CTAs/SM.
// ---------------------------------------------------------------------------
#define AS_S 12     // half2 stride per m-row (8 used + 4 pad)
#define BS_S 132    // half2 stride per kp-row (128 used + 4 pad)
#define A_H2 (128 * AS_S)
#define B_H2 (8 * BS_S)
#define STG_H2 (2 * A_H2 + 2 * B_H2)
#define G_SMEM_BYTES (3 * STG_H2 * 4)

template<bool SPLIT_OUT>
__global__ __launch_bounds__(256, 2) void gemm_h2_kernel(
    const __half* __restrict__ Ahi, const __half* __restrict__ Alo,
    const __half2* __restrict__ Bhi, const __half2* __restrict__ Blo,
    const float* __restrict__ bias,
    float* __restrict__ Cf, __half2* __restrict__ Chi, __half2* __restrict__ Clo,
    int M, int N, int K)
{
    extern __shared__ __half2 smg[];

    const int tid   = threadIdx.x;
    const int lane  = tid & 31;
    const int wid   = tid >> 5;
    const int g     = lane >> 2;
    const int tg    = lane & 3;
    const int warpM = wid >> 2;
    const int warpN = wid & 3;
    const int rowBase = blockIdx.y * 128;
    const int colBase = blockIdx.x * 128;

    const int am  = tid >> 1;         // 0..127
    const int ac  = tid & 1;          // 16B chunk
    const int bkp = tid >> 5;         // 0..7
    const int bn  = lane * 4;         // half2 col

    float acc[4][4][4];
    #pragma unroll
    for (int mt = 0; mt < 4; mt++)
        #pragma unroll
        for (int nt = 0; nt < 4; nt++)
            #pragma unroll
            for (int i = 0; i < 4; i++) acc[mt][nt][i] = 0.f;

    const int NT = K / 16;

    auto issue = [&](int st, int kt) {
        __half2* S = smg + st * STG_H2;
        cp16(&S[am * AS_S + ac * 4], Ahi + (size_t)(rowBase + am) * K + kt + ac * 8);
        cp16(&S[A_H2 + am * AS_S + ac * 4], Alo + (size_t)(rowBase + am) * K + kt + ac * 8);
        cp16(&S[2 * A_H2 + bkp * BS_S + bn],
             Bhi + (size_t)((kt >> 1) + bkp) * N + colBase + bn);
        cp16(&S[2 * A_H2 + B_H2 + bkp * BS_S + bn],
             Blo + (size_t)((kt >> 1) + bkp) * N + colBase + bn);
        cp_commit();
    };

    issue(0, 0);
    issue(1, 16);

    for (int t = 0; t < NT; t++) {
        if (t + 1 < NT) cp_wait<1>(); else cp_wait<0>();
        __syncthreads();
        if (t + 2 < NT) issue((t + 2) % 3, (t + 2) * 16);

        const __half2* S = smg + (t % 3) * STG_H2;
        const __half2* Ah = S;
        const __half2* Al = S + A_H2;
        const __half2* Bh = S + 2 * A_H2;
        const __half2* Bl = S + 2 * A_H2 + B_H2;

        uint32_t bh[4][2], bl[4][2];
        #pragma unroll
        for (int nt = 0; nt < 4; nt++) {
            int n0 = warpN * 32 + nt * 8 + g;
            bh[nt][0] = *(const uint32_t*)&Bh[tg * BS_S + n0];
            bh[nt][1] = *(const uint32_t*)&Bh[(tg + 4) * BS_S + n0];
            bl[nt][0] = *(const uint32_t*)&Bl[tg * BS_S + n0];
            bl[nt][1] = *(const uint32_t*)&Bl[(tg + 4) * BS_S + n0];
        }
        #pragma unroll
        for (int mt = 0; mt < 4; mt++) {
            int m0 = warpM * 64 + mt * 16;
            uint32_t ah[4], al[4];
            ah[0] = *(const uint32_t*)&Ah[(m0 + g) * AS_S + tg];
            ah[1] = *(const uint32_t*)&Ah[(m0 + g + 8) * AS_S + tg];
            ah[2] = *(const uint32_t*)&Ah[(m0 + g) * AS_S + tg + 4];
            ah[3] = *(const uint32_t*)&Ah[(m0 + g + 8) * AS_S + tg + 4];
            al[0] = *(const uint32_t*)&Al[(m0 + g) * AS_S + tg];
            al[1] = *(const uint32_t*)&Al[(m0 + g + 8) * AS_S + tg];
            al[2] = *(const uint32_t*)&Al[(m0 + g) * AS_S + tg + 4];
            al[3] = *(const uint32_t*)&Al[(m0 + g + 8) * AS_S + tg + 4];
            #pragma unroll
            for (int nt = 0; nt < 4; nt++)
                mma3(acc[mt][nt], ah, al, bh[nt], bl[nt]);
        }
    }

    // epilogue
    #pragma unroll
    for (int mt = 0; mt < 4; mt++) {
        #pragma unroll
        for (int nt = 0; nt < 4; nt++) {
            int r0 = rowBase + warpM * 64 + mt * 16 + g;
            int c0 = colBase + warpN * 32 + nt * 8 + tg * 2;
            float bz0 = bias[c0], bz1 = bias[c0 + 1];
            float v0 = acc[mt][nt][0] + bz0, v1 = acc[mt][nt][1] + bz1;
            float v2 = acc[mt][nt][2] + bz0, v3 = acc[mt][nt][3] + bz1;
            if (SPLIT_OUT) {
                __half2 h, l;
                split2(v0, v1, h, l);
                Chi[(size_t)r0 * (N / 2) + c0 / 2] = h;
                Clo[(size_t)r0 * (N / 2) + c0 / 2] = l;
                split2(v2, v3, h, l);
                Chi[(size_t)(r0 + 8) * (N / 2) + c0 / 2] = h;
                Clo[(size_t)(r0 + 8) * (N / 2) + c0 / 2] = l;
            } else {
                *(float2*)&Cf[(size_t)r0 * N + c0] = make_float2(v0, v1);
                *(float2*)&Cf[(size_t)(r0 + 8) * N + c0] = make_float2(v2, v3);
            }
        }
    }
}

// ---------------------------------------------------------------------------
// Repack V: qkv v-region [row][d] halves -> vT [bh][d][T/2] half2 (j-pairs)
// ---------------------------------------------------------------------------
#define VT_S 36
__global__ __launch_bounds__(256) void repack_v_kernel(
    const __half* __restrict__ qkv_hi, const __half* __restrict__ qkv_lo,
    __half2* __restrict__ vT_hi, __half2* __restrict__ vT_lo)
{
    __shared__ __half2 sm_hi[64 * VT_S];
    __shared__ __half2 sm_lo[64 * VT_S];
    const int tid = threadIdx.x;
    const int bh  = blockIdx.y;
    const int b   = bh / NH;
    const int h   = bh % NH;
    const int j0  = blockIdx.x * 64;

    const size_t base = ((size_t)(b * T_SEQ + j0)) * QKV_N + 2 * DIM + h * HD;
    #pragma unroll
    for (int l = 0; l < 2; l++) {
        int id = tid + l * 256;
        int r  = id >> 3;
        int c  = id & 7;
        *(int4*)&sm_hi[r * VT_S + c * 4] = *(const int4*)(qkv_hi + base + (size_t)r * QKV_N + c * 8);
        *(int4*)&sm_lo[r * VT_S + c * 4] = *(const int4*)(qkv_lo + base + (size_t)r * QKV_N + c * 8);
    }
    __syncthreads();
    #pragma unroll
    for (int l = 0; l < 8; l++) {
        int id = tid + l * 256;
        int d  = id >> 5;
        int jp = id & 31;
        __half2 a = sm_hi[(2 * jp) * VT_S + (d >> 1)];
        __half2 c = sm_hi[(2 * jp + 1) * VT_S + (d >> 1)];
        __half va = (d & 1) ? __high2half(a) : __low2half(a);
        __half vc = (d & 1) ? __high2half(c) : __low2half(c);
        vT_hi[((size_t)bh * HD + d) * (T_SEQ / 2) + j0 / 2 + jp] = __halves2half2(va, vc);
        a = sm_lo[(2 * jp) * VT_S + (d >> 1)];
        c = sm_lo[(2 * jp + 1) * VT_S + (d >> 1)];
        va = (d & 1) ? __high2half(a) : __low2half(a);
        vc = (d & 1) ? __high2half(c) : __low2half(c);
        vT_lo[((size_t)bh * HD + d) * (T_SEQ / 2) + j0 / 2 + jp] = __halves2half2(va, vc);
    }
}

// ---------------------------------------------------------------------------
// Fused RBF attention, fp16-split mma.
// S_scaled = 4096*exp(-sigma*dist2) stored as single fp16 (normal range);
// out = (S_scaled @ V) / 4096.  Norms folded into the tile-load (shuffle reduce).
// ---------------------------------------------------------------------------
#define AT_S 36
#define ATT_SMEM_BYTES (6 * 64 * AT_S * 4 + 2 * 64 * 4)
#define LOG4096 8.317766166719343f
#define INV4096 2.44140625e-4f

__global__ __launch_bounds__(256, 2) void attn_h2_kernel(
    const __half* __restrict__ qkv_hi, const __half* __restrict__ qkv_lo,
    const __half2* __restrict__ vT_hi, const __half2* __restrict__ vT_lo,
    const float* __restrict__ rsig,
    __half2* __restrict__ attn_hi, __half2* __restrict__ attn_lo)
{
    extern __shared__ char smraw[];
    __half2* ks_hi = (__half2*)smraw;
    __half2* ks_lo = ks_hi + 64 * AT_S;
    __half2* qs_hi = ks_lo + 64 * AT_S;   // reused as S_scaled (fp16 single)
    __half2* qs_lo = qs_hi + 64 * AT_S;
    __half2* vs_hi = qs_lo + 64 * AT_S;
    __half2* vs_lo = vs_hi + 64 * AT_S;
    float*   knv   = (float*)(vs_lo + 64 * AT_S);
    float*   qnv   = knv + 64;

    const int tid   = threadIdx.x;
    const int lane  = tid & 31;
    const int wid   = tid >> 5;
    const int g     = lane >> 2;
    const int tg    = lane & 3;
    const int warpM = wid >> 2;
    const int warpN = wid & 3;
    const int bh    = blockIdx.y;
    const int b     = bh / NH;
    const int h     = bh % NH;
    const int i0    = blockIdx.x * 64;
    const float nsig = -rsig[0];

    const size_t qoff = (size_t)b * T_SEQ * QKV_N + 0 * DIM + h * HD;
    const size_t koff = (size_t)b * T_SEQ * QKV_N + 1 * DIM + h * HD;

    const int lr = tid >> 3;   // load row (0..31), +32 on second pass
    const int lc = tid & 7;    // 16B chunk

    // ---- load K tile + fused kn ----
    {
        float kp0, kp1;
        {
            int4 vh = *(const int4*)(qkv_hi + koff + (size_t)(i0 + lr) * QKV_N + lc * 8);
            int4 vl = *(const int4*)(qkv_lo + koff + (size_t)(i0 + lr) * QKV_N + lc * 8);
            *(int4*)&ks_hi[lr * AT_S + lc * 4] = vh;
            *(int4*)&ks_lo[lr * AT_S + lc * 4] = vl;
            kp0 = sumsq8(vh, vl);
        }
        {
            int r = 32 + lr;
            int4 vh = *(const int4*)(qkv_hi + koff + (size_t)(i0 + r) * QKV_N + lc * 8);
            int4 vl = *(const int4*)(qkv_lo + koff + (size_t)(i0 + r) * QKV_N + lc * 8);
            *(int4*)&ks_hi[r * AT_S + lc * 4] = vh;
            *(int4*)&ks_lo[r * AT_S + lc * 4] = vl;
            kp1 = sumsq8(vh, vl);
        }
        #pragma unroll
        for (int d = 1; d < 8; d <<= 1) {
            kp0 += __shfl_xor_sync(0xffffffffu, kp0, d);
            kp1 += __shfl_xor_sync(0xffffffffu, kp1, d);
        }
        if (lc == 0) { knv[lr] = kp0; knv[32 + lr] = kp1; }
    }

    float out[2][2][4];
    #pragma unroll
    for (int mt = 0; mt < 2; mt++)
        #pragma unroll
        for (int nt = 0; nt < 2; nt++)
            #pragma unroll
            for (int i = 0; i < 4; i++) out[mt][nt][i] = 0.f;

    for (int jt = 0; jt < T_SEQ / 64; jt++) {
        const int j0 = jt * 64;
        __syncthreads();   // prior S@V reads of qs/vs done

        // ---- load q + v tiles, fused qn ----
        float qp0, qp1;
        {
            int4 vh = *(const int4*)(qkv_hi + qoff + (size_t)(j0 + lr) * QKV_N + lc * 8);
            int4 vl = *(const int4*)(qkv_lo + qoff + (size_t)(j0 + lr) * QKV_N + lc * 8);
            *(int4*)&qs_hi[lr * AT_S + lc * 4] = vh;
            *(int4*)&qs_lo[lr * AT_S + lc * 4] = vl;
            qp0 = sumsq8(vh, vl);
            const size_t vbase = ((size_t)bh * HD + lr) * (T_SEQ / 2) + j0 / 2;
            *(int4*)&vs_hi[lr * AT_S + lc * 4] = *(const int4*)(vT_hi + vbase + lc * 4);
            *(int4*)&vs_lo[lr * AT_S + lc * 4] = *(const int4*)(vT_lo + vbase + lc * 4);
        }
        {
            int r = 32 + lr;
            int4 vh = *(const int4*)(qkv_hi + qoff + (size_t)(j0 + r) * QKV_N + lc * 8);
            int4 vl = *(const int4*)(qkv_lo + qoff + (size_t)(j0 + r) * QKV_N + lc * 8);
            *(int4*)&qs_hi[r * AT_S + lc * 4] = vh;
            *(int4*)&qs_lo[r * AT_S + lc * 4] = vl;
            qp1 = sumsq8(vh, vl);
            const size_t vbase = ((size_t)bh * HD + r) * (T_SEQ / 2) + j0 / 2;
            *(int4*)&vs_hi[r * AT_S + lc * 4] = *(const int4*)(vT_hi + vbase + lc * 4);
            *(int4*)&vs_lo[r * AT_S + lc * 4] = *(const int4*)(vT_lo + vbase + lc * 4);
        }
        #pragma unroll
        for (int d = 1; d < 8; d <<= 1) {
            qp0 += __shfl_xor_sync(0xffffffffu, qp0, d);
            qp1 += __shfl_xor_sync(0xffffffffu, qp1, d);
        }
        if (lc == 0) { qnv[lr] = qp0; qnv[32 + lr] = qp1; }
        __syncthreads();

        // ---- S-mma: dot[i][j] over 64 dims (3-term split) ----
        float sacc[2][2][4];
        #pragma unroll
        for (int mt = 0; mt < 2; mt++)
            #pragma unroll
            for (int nt = 0; nt < 2; nt++)
                #pragma unroll
                for (int i = 0; i < 4; i++) sacc[mt][nt][i] = 0.f;

        #pragma unroll
        for (int kc = 0; kc < 4; kc++) {
            int kp = kc * 8;
            uint32_t bh2[2][2], bl2[2][2];
            #pragma unroll
            for (int nt = 0; nt < 2; nt++) {
                int n0 = warpN * 16 + nt * 8 + g;
                bh2[nt][0] = *(const uint32_t*)&qs_hi[n0 * AT_S + kp + tg];
                bh2[nt][1] = *(const uint32_t*)&qs_hi[n0 * AT_S + kp + tg + 4];
                bl2[nt][0] = *(const uint32_t*)&qs_lo[n0 * AT_S + kp + tg];
                bl2[nt][1] = *(const uint32_t*)&qs_lo[n0 * AT_S + kp + tg + 4];
            }
            #pragma unroll
            for (int mt = 0; mt < 2; mt++) {
                int m0 = warpM * 32 + mt * 16;
                uint32_t ah[4], al[4];
                ah[0] = *(const uint32_t*)&ks_hi[(m0 + g) * AT_S + kp + tg];
                ah[1] = *(const uint32_t*)&ks_hi[(m0 + g + 8) * AT_S + kp + tg];
                ah[2] = *(const uint32_t*)&ks_hi[(m0 + g) * AT_S + kp + tg + 4];
                ah[3] = *(const uint32_t*)&ks_hi[(m0 + g + 8) * AT_S + kp + tg + 4];
                al[0] = *(const uint32_t*)&ks_lo[(m0 + g) * AT_S + kp + tg];
                al[1] = *(const uint32_t*)&ks_lo[(m0 + g + 8) * AT_S + kp + tg];
                al[2] = *(const uint32_t*)&ks_lo[(m0 + g) * AT_S + kp + tg + 4];
                al[3] = *(const uint32_t*)&ks_lo[(m0 + g + 8) * AT_S + kp + tg + 4];
                #pragma unroll
                for (int nt = 0; nt < 2; nt++)
                    mma3(sacc[mt][nt], ah, al, bh2[nt], bl2[nt]);
            }
        }

        // ---- exp (scaled by 4096 via +ln4096 in the argument) ----
        float ev[2][2][4];
        #pragma unroll
        for (int mt = 0; mt < 2; mt++) {
            int si = warpM * 32 + mt * 16 + g;
            float kA = knv[si], kB = knv[si + 8];
            #pragma unroll
            for (int nt = 0; nt < 2; nt++) {
                int jj = warpN * 16 + nt * 8 + tg * 2;
                float qA = qnv[jj], qB = qnv[jj + 1];
                ev[mt][nt][0] = __expf(nsig * (kA + qA - 2.f * sacc[mt][nt][0]) + LOG4096);
                ev[mt][nt][1] = __expf(nsig * (kA + qB - 2.f * sacc[mt][nt][1]) + LOG4096);
                ev[mt][nt][2] = __expf(nsig * (kB + qA - 2.f * sacc[mt][nt][2]) + LOG4096);
                ev[mt][nt][3] = __expf(nsig * (kB + qB - 2.f * sacc[mt][nt][3]) + LOG4096);
            }
        }
        __syncthreads();   // all S-mma reads of qs done

        // ---- store scaled S (single fp16) into qs_hi ----
        #pragma unroll
        for (int mt = 0; mt < 2; mt++) {
            int si = warpM * 32 + mt * 16 + g;
            #pragma unroll
            for (int nt = 0; nt < 2; nt++) {
                int jp = warpN * 8 + nt * 4 + tg;
                qs_hi[si * AT_S + jp]       = __floats2half2_rn(ev[mt][nt][0], ev[mt][nt][1]);
                qs_hi[(si + 8) * AT_S + jp] = __floats2half2_rn(ev[mt][nt][2], ev[mt][nt][3]);
            }
        }
        __syncthreads();

        // ---- out += S @ V  (2-term: Sh*Vh + Sh*Vl) ----
        #pragma unroll
        for (int kc = 0; kc < 4; kc++) {
            int kp = kc * 8;
            uint32_t bh2[2][2], bl2[2][2];
            #pragma unroll
            for (int nt = 0; nt < 2; nt++) {
                int n0 = warpN * 16 + nt * 8 + g;
                bh2[nt][0] = *(const uint32_t*)&vs_hi[n0 * AT_S + kp + tg];
                bh2[nt][1] = *(const uint32_t*)&vs_hi[n0 * AT_S + kp + tg + 4];
                bl2[nt][0] = *(const uint32_t*)&vs_lo[n0 * AT_S + kp + tg];
                bl2[nt][1] = *(const uint32_t*)&vs_lo[n0 * AT_S + kp + tg + 4];
            }
            #pragma unroll
            for (int mt = 0; mt < 2; mt++) {
                int m0 = warpM * 32 + mt * 16;
                uint32_t ah[4];
                ah[0] = *(const uint32_t*)&qs_hi[(m0 + g) * AT_S + kp + tg];
                ah[1] = *(const uint32_t*)&qs_hi[(m0 + g + 8) * AT_S + kp + tg];
                ah[2] = *(const uint32_t*)&qs_hi[(m0 + g) * AT_S + kp + tg + 4];
                ah[3] = *(const uint32_t*)&qs_hi[(m0 + g + 8) * AT_S + kp + tg + 4];
                #pragma unroll
                for (int nt = 0; nt < 2; nt++) {
                    mma_h(out[mt][nt], ah[0], ah[1], ah[2], ah[3],
                          bh2[nt][0], bh2[nt][1]);
                    mma_h(out[mt][nt], ah[0], ah[1], ah[2], ah[3],
                          bl2[nt][0], bl2[nt][1]);
                }
            }
        }
    }

    // ---- epilogue: unscale, split halves in (b,t,h,d) layout ----
    #pragma unroll
    for (int mt = 0; mt < 2; mt++) {
        #pragma unroll
        for (int nt = 0; nt < 2; nt++) {
            int irow = i0 + warpM * 32 + mt * 16 + g;
            int dcol = warpN * 16 + nt * 8 + tg * 2;
            size_t base = ((size_t)(b * T_SEQ + irow)) * (DIM / 2) + (h * HD + dcol) / 2;
            __half2 hh, ll;
            split2(out[mt][nt][0] * INV4096, out[mt][nt][1] * INV4096, hh, ll);
            attn_hi[base] = hh;
            attn_lo[base] = ll;
            split2(out[mt][nt][2] * INV4096, out[mt][nt][3] * INV4096, hh, ll);
            attn_hi[base + (size_t)8 * (DIM / 2)] = hh;
            attn_lo[base + (size_t)8 * (DIM / 2)] = ll;
        }
    }
}

// ---------------------------------------------------------------------------
extern "C" void kernel_launch(void* const* d_in, const int* in_sizes, int n_in,
                              void* d_out, int out_size)
{
    const float* x     = (const float*)d_in[0];
    const float* Wqkv  = (const float*)d_in[1];
    const float* bqkv  = (const float*)d_in[2];
    const float* rsig  = (const float*)d_in[3];
    const float* Wproj = (const float*)d_in[4];
    const float* bproj = (const float*)d_in[5];
    float* out = (float*)d_out;

    __half *x_hi, *x_lo, *qkv_hi, *qkv_lo, *attn_hi, *attn_lo;
    __half2 *wqkv_hi, *wqkv_lo, *wproj_hi, *wproj_lo, *vT_hi, *vT_lo;
    cudaGetSymbolAddress((void**)&x_hi, g_x_hi);
    cudaGetSymbolAddress((void**)&x_lo, g_x_lo);
    cudaGetSymbolAddress((void**)&wqkv_hi, g_wqkv_hi);
    cudaGetSymbolAddress((void**)&wqkv_lo, g_wqkv_lo);
    cudaGetSymbolAddress((void**)&wproj_hi, g_wproj_hi);
    cudaGetSymbolAddress((void**)&wproj_lo, g_wproj_lo);
    cudaGetSymbolAddress((void**)&qkv_hi, g_qkv_hi);
    cudaGetSymbolAddress((void**)&qkv_lo, g_qkv_lo);
    cudaGetSymbolAddress((void**)&vT_hi, g_vT_hi);
    cudaGetSymbolAddress((void**)&vT_lo, g_vT_lo);
    cudaGetSymbolAddress((void**)&attn_hi, g_attn_hi);
    cudaGetSymbolAddress((void**)&attn_lo, g_attn_lo);

    cudaFuncSetAttribute(attn_h2_kernel,
                         cudaFuncAttributeMaxDynamicSharedMemorySize, ATT_SMEM_BYTES);
    cudaFuncSetAttribute(gemm_h2_kernel<true>,
                         cudaFuncAttributeMaxDynamicSharedMemorySize, G_SMEM_BYTES);
    cudaFuncSetAttribute(gemm_h2_kernel<false>,
                         cudaFuncAttributeMaxDynamicSharedMemorySize, G_SMEM_BYTES);

    // prep: split x, pack weights
    {
        int n4 = ROWS * CDIM / 4;
        split_kernel<<<(n4 + 255) / 256, 256>>>(x, (__half2*)x_hi, (__half2*)x_lo, n4);
        int tq = (CDIM / 2) * (QKV_N / 4);
        pack_w_kernel<<<(tq + 255) / 256, 256>>>(Wqkv, wqkv_hi, wqkv_lo, CDIM, QKV_N);
        int tp = (DIM / 2) * (CDIM / 4);
        pack_w_kernel<<<(tp + 255) / 256, 256>>>(Wproj, wproj_hi, wproj_lo, DIM, CDIM);
    }
    // stage 1: qkv (split output)
    {
        dim3 grid(QKV_N / 128, ROWS / 128);
        gemm_h2_kernel<true><<<grid, 256, G_SMEM_BYTES>>>(
            x_hi, x_lo, wqkv_hi, wqkv_lo, bqkv,
            nullptr, (__half2*)qkv_hi, (__half2*)qkv_lo, ROWS, QKV_N, CDIM);
    }
    // repack V
    {
        dim3 grid(T_SEQ / 64, BATCH * NH);
        repack_v_kernel<<<grid, 256>>>(qkv_hi, qkv_lo, vT_hi, vT_lo);
    }
    // stage 2: attention
    {
        dim3 grid(T_SEQ / 64, BATCH * NH);
        attn_h2_kernel<<<grid, 256, ATT_SMEM_BYTES>>>(qkv_hi, qkv_lo, vT_hi, vT_lo,
                                                      rsig,
                                                      (__half2*)attn_hi, (__half2*)attn_lo);
    }
    // stage 3: out
    {
        dim3 grid(CDIM / 128, ROWS / 128);
        gemm_h2_kernel<false><<<grid, 256, G_SMEM_BYTES>>>(
            attn_hi, attn_lo, wproj_hi, wproj_lo, bproj,
            out, nullptr, nullptr, ROWS, CDIM, DIM);
    }
}

// round 7
// speedup vs baseline: 3.1302x; 1.0948x over previous
#include <cuda_runtime.h>
#include <cuda_fp16.h>
#include <cstdint>
#include <cstddef>

// Problem constants
#define BATCH   2
#define T_SEQ   2048
#define CDIM    1024
#define DIM     1024
#define NH      16
#define HD      64
#define QKV_N   3072
#define ROWS    (BATCH*T_SEQ)

// ---------------------------------------------------------------------------
// Device scratch (allocation-free rule). All 16B aligned.
// ---------------------------------------------------------------------------
__device__ __align__(16) __half g_x_hi[ROWS * CDIM];
__device__ __align__(16) __half g_x_lo[ROWS * CDIM];
__device__ __align__(16) __half2 g_wqkv_hi[(CDIM/2) * QKV_N];  // [K/2][N] k-pair packed
__device__ __align__(16) __half2 g_wqkv_lo[(CDIM/2) * QKV_N];
__device__ __align__(16) __half2 g_wproj_hi[(DIM/2) * CDIM];
__device__ __align__(16) __half2 g_wproj_lo[(DIM/2) * CDIM];
__device__ __align__(16) __half g_qkv_hi[ROWS * QKV_N];
__device__ __align__(16) __half g_qkv_lo[ROWS * QKV_N];
__device__ __align__(16) __half2 g_vT_hi[BATCH*NH * HD * (T_SEQ/2)]; // [bh][d][T/2]
__device__ __align__(16) __half2 g_vT_lo[BATCH*NH * HD * (T_SEQ/2)];
__device__ __align__(16) __half g_attn_hi[ROWS * DIM];
__device__ __align__(16) __half g_attn_lo[ROWS * DIM];

// ---------------------------------------------------------------------------
// helpers
// ---------------------------------------------------------------------------
__device__ __forceinline__ void split_h(float x, __half& hi, __half& lo) {
    hi = __float2half_rn(x);
    lo = __float2half_rn(x - __half2float(hi));
}
__device__ __forceinline__ void split2(float a, float b, __half2& h, __half2& l) {
    __half ha, la, hb, lb;
    split_h(a, ha, la);
    split_h(b, hb, lb);
    h = __halves2half2(ha, hb);
    l = __halves2half2(la, lb);
}

__device__ __forceinline__ void mma_h(float* d,
    uint32_t a0, uint32_t a1, uint32_t a2, uint32_t a3,
    uint32_t b0, uint32_t b1)
{
    asm volatile(
        "mma.sync.aligned.m16n8k16.row.col.f32.f16.f16.f32 "
        "{%0,%1,%2,%3}, {%4,%5,%6,%7}, {%8,%9}, {%0,%1,%2,%3};\n"
        : "+f"(d[0]), "+f"(d[1]), "+f"(d[2]), "+f"(d[3])
        : "r"(a0), "r"(a1), "r"(a2), "r"(a3), "r"(b0), "r"(b1));
}
// hi*hi + hi*lo + lo*hi
__device__ __forceinline__ void mma3(float* d,
    const uint32_t ah[4], const uint32_t al[4],
    const uint32_t bh[2], const uint32_t bl[2])
{
    mma_h(d, ah[0], ah[1], ah[2], ah[3], bh[0], bh[1]);
    mma_h(d, ah[0], ah[1], ah[2], ah[3], bl[0], bl[1]);
    mma_h(d, al[0], al[1], al[2], al[3], bh[0], bh[1]);
}

__device__ __forceinline__ void ldsm_x4(uint32_t* r, uint32_t addr) {
    asm volatile("ldmatrix.sync.aligned.m8n8.x4.shared.b16 {%0,%1,%2,%3}, [%4];"
        : "=r"(r[0]), "=r"(r[1]), "=r"(r[2]), "=r"(r[3]) : "r"(addr));
}

__device__ __forceinline__ void cp16(void* dst, const void* src) {
    uint32_t d = (uint32_t)__cvta_generic_to_shared(dst);
    asm volatile("cp.async.cg.shared.global [%0], [%1], 16;\n" :: "r"(d), "l"(src));
}
__device__ __forceinline__ void cp_commit() { asm volatile("cp.async.commit_group;\n"); }
template<int N> __device__ __forceinline__ void cp_wait() {
    asm volatile("cp.async.wait_group %0;\n" :: "n"(N));
}

// sum of squares of 8 split halves
__device__ __forceinline__ float sumsq8(int4 hbits, int4 lbits) {
    const __half2* h = (const __half2*)&hbits;
    const __half2* l = (const __half2*)&lbits;
    float s = 0.f;
    #pragma unroll
    for (int i = 0; i < 4; i++) {
        float2 a = __half22float2(h[i]);
        float2 b = __half22float2(l[i]);
        float x = a.x + b.x, y = a.y + b.y;
        s += x * x + y * y;
    }
    return s;
}

// ---------------------------------------------------------------------------
// Prep kernels
// ---------------------------------------------------------------------------
__global__ void split_kernel(const float* __restrict__ src,
                             __half2* __restrict__ hi, __half2* __restrict__ lo,
                             int n4)
{
    int i = blockIdx.x * blockDim.x + threadIdx.x;
    if (i >= n4) return;
    float4 v = *(const float4*)(src + (size_t)i * 4);
    __half2 h0, l0, h1, l1;
    split2(v.x, v.y, h0, l0);
    split2(v.z, v.w, h1, l1);
    hi[(size_t)i * 2]     = h0;
    hi[(size_t)i * 2 + 1] = h1;
    lo[(size_t)i * 2]     = l0;
    lo[(size_t)i * 2 + 1] = l1;
}

// Pack weights: W[K][N] fp32 -> [K/2][N] half2 (k-pair in one half2)
__global__ void pack_w_kernel(const float* __restrict__ W,
                              __half2* __restrict__ hi, __half2* __restrict__ lo,
                              int K, int N)
{
    int idx = blockIdx.x * blockDim.x + threadIdx.x;
    int total = (K / 2) * (N / 4);
    if (idx >= total) return;
    int kp = idx / (N / 4);
    int n4 = (idx % (N / 4)) * 4;
    float4 r0 = *(const float4*)(W + (size_t)(2 * kp) * N + n4);
    float4 r1 = *(const float4*)(W + (size_t)(2 * kp + 1) * N + n4);
    const float a[4] = {r0.x, r0.y, r0.z, r0.w};
    const float b[4] = {r1.x, r1.y, r1.z, r1.w};
    #pragma unroll
    for (int t = 0; t < 4; t++) {
        __half h0, l0, h1, l1;
        split_h(a[t], h0, l0);
        split_h(b[t], h1, l1);
        hi[(size_t)kp * N + n4 + t] = __halves2half2(h0, h1);
        lo[(size_t)kp * N + n4 + t] = __halves2half2(l0, l1);
    }
}

// ---------------------------------------------------------------------------
// GEMM: C[M,N] = (Ahi+Alo)[M,K] @ W[K,N] + bias, fp16 split mma.
// BM=128 BN=128 BK=16, 8 warps (2x4), warp tile 64x32.
// 3-stage cp.async ring; A fragments via ldmatrix.x4.
// ---------------------------------------------------------------------------
#define AS_S 12     // half2 stride per m-row (8 used + 4 pad)
#define BS_S 132    // half2 stride per kp-row (128 used + 4 pad)
#define A_H2 (128 * AS_S)
#define B_H2 (8 * BS_S)
#define STG_H2 (2 * A_H2 + 2 * B_H2)
#define G_SMEM_BYTES (3 * STG_H2 * 4)

template<bool SPLIT_OUT>
__global__ __launch_bounds__(256, 2) void gemm_h2_kernel(
    const __half* __restrict__ Ahi, const __half* __restrict__ Alo,
    const __half2* __restrict__ Bhi, const __half2* __restrict__ Blo,
    const float* __restrict__ bias,
    float* __restrict__ Cf, __half2* __restrict__ Chi, __half2* __restrict__ Clo,
    int M, int N, int K)
{
    extern __shared__ __half2 smg[];

    const int tid   = threadIdx.x;
    const int lane  = tid & 31;
    const int wid   = tid >> 5;
    const int g     = lane >> 2;
    const int tg    = lane & 3;
    const int warpM = wid >> 2;
    const int warpN = wid & 3;
    const int rowBase = blockIdx.y * 128;
    const int colBase = blockIdx.x * 128;
    const uint32_t sbase = (uint32_t)__cvta_generic_to_shared(smg);

    const int am  = tid >> 1;
    const int ac  = tid & 1;
    const int bkp = tid >> 5;
    const int bn  = lane * 4;

    // ldmatrix lane offset within an m16k16 A tile (rows: AS_S*4=48B stride)
    const uint32_t lds_row = (lane & 7) + (lane & 8);
    const uint32_t lds_off = lds_row * (AS_S * 4) + (lane & 16);

    float acc[4][4][4];
    #pragma unroll
    for (int mt = 0; mt < 4; mt++)
        #pragma unroll
        for (int nt = 0; nt < 4; nt++)
            #pragma unroll
            for (int i = 0; i < 4; i++) acc[mt][nt][i] = 0.f;

    const int NT = K / 16;

    auto issue = [&](int st, int kt) {
        __half2* S = smg + st * STG_H2;
        cp16(&S[am * AS_S + ac * 4], Ahi + (size_t)(rowBase + am) * K + kt + ac * 8);
        cp16(&S[A_H2 + am * AS_S + ac * 4], Alo + (size_t)(rowBase + am) * K + kt + ac * 8);
        cp16(&S[2 * A_H2 + bkp * BS_S + bn],
             Bhi + (size_t)((kt >> 1) + bkp) * N + colBase + bn);
        cp16(&S[2 * A_H2 + B_H2 + bkp * BS_S + bn],
             Blo + (size_t)((kt >> 1) + bkp) * N + colBase + bn);
        cp_commit();
    };

    issue(0, 0);
    issue(1, 16);

    for (int t = 0; t < NT; t++) {
        if (t + 1 < NT) cp_wait<1>(); else cp_wait<0>();
        __syncthreads();
        if (t + 2 < NT) issue((t + 2) % 3, (t + 2) * 16);

        const uint32_t stg = sbase + (uint32_t)((t % 3) * STG_H2) * 4u;
        const uint32_t aHb = stg + lds_off + (uint32_t)(warpM * 64) * (AS_S * 4);
        const uint32_t aLb = aHb + (uint32_t)A_H2 * 4u;
        const __half2* S = smg + (t % 3) * STG_H2;
        const __half2* Bh = S + 2 * A_H2;
        const __half2* Bl = S + 2 * A_H2 + B_H2;

        uint32_t bh[4][2], bl[4][2];
        #pragma unroll
        for (int nt = 0; nt < 4; nt++) {
            int n0 = warpN * 32 + nt * 8 + g;
            bh[nt][0] = *(const uint32_t*)&Bh[tg * BS_S + n0];
            bh[nt][1] = *(const uint32_t*)&Bh[(tg + 4) * BS_S + n0];
            bl[nt][0] = *(const uint32_t*)&Bl[tg * BS_S + n0];
            bl[nt][1] = *(const uint32_t*)&Bl[(tg + 4) * BS_S + n0];
        }
        #pragma unroll
        for (int mt = 0; mt < 4; mt++) {
            uint32_t ah[4], al[4];
            ldsm_x4(ah, aHb + (uint32_t)(mt * 16) * (AS_S * 4));
            ldsm_x4(al, aLb + (uint32_t)(mt * 16) * (AS_S * 4));
            #pragma unroll
            for (int nt = 0; nt < 4; nt++)
                mma3(acc[mt][nt], ah, al, bh[nt], bl[nt]);
        }
    }

    // epilogue
    #pragma unroll
    for (int mt = 0; mt < 4; mt++) {
        #pragma unroll
        for (int nt = 0; nt < 4; nt++) {
            int r0 = rowBase + warpM * 64 + mt * 16 + g;
            int c0 = colBase + warpN * 32 + nt * 8 + tg * 2;
            float bz0 = bias[c0], bz1 = bias[c0 + 1];
            float v0 = acc[mt][nt][0] + bz0, v1 = acc[mt][nt][1] + bz1;
            float v2 = acc[mt][nt][2] + bz0, v3 = acc[mt][nt][3] + bz1;
            if (SPLIT_OUT) {
                __half2 h, l;
                split2(v0, v1, h, l);
                Chi[(size_t)r0 * (N / 2) + c0 / 2] = h;
                Clo[(size_t)r0 * (N / 2) + c0 / 2] = l;
                split2(v2, v3, h, l);
                Chi[(size_t)(r0 + 8) * (N / 2) + c0 / 2] = h;
                Clo[(size_t)(r0 + 8) * (N / 2) + c0 / 2] = l;
            } else {
                *(float2*)&Cf[(size_t)r0 * N + c0] = make_float2(v0, v1);
                *(float2*)&Cf[(size_t)(r0 + 8) * N + c0] = make_float2(v2, v3);
            }
        }
    }
}

// ---------------------------------------------------------------------------
// Repack V: qkv v-region [row][d] halves -> vT [bh][d][T/2] half2 (j-pairs)
// ---------------------------------------------------------------------------
#define VT_S 36
__global__ __launch_bounds__(256) void repack_v_kernel(
    const __half* __restrict__ qkv_hi, const __half* __restrict__ qkv_lo,
    __half2* __restrict__ vT_hi, __half2* __restrict__ vT_lo)
{
    __shared__ __half2 sm_hi[64 * VT_S];
    __shared__ __half2 sm_lo[64 * VT_S];
    const int tid = threadIdx.x;
    const int bh  = blockIdx.y;
    const int b   = bh / NH;
    const int h   = bh % NH;
    const int j0  = blockIdx.x * 64;

    const size_t base = ((size_t)(b * T_SEQ + j0)) * QKV_N + 2 * DIM + h * HD;
    #pragma unroll
    for (int l = 0; l < 2; l++) {
        int id = tid + l * 256;
        int r  = id >> 3;
        int c  = id & 7;
        *(int4*)&sm_hi[r * VT_S + c * 4] = *(const int4*)(qkv_hi + base + (size_t)r * QKV_N + c * 8);
        *(int4*)&sm_lo[r * VT_S + c * 4] = *(const int4*)(qkv_lo + base + (size_t)r * QKV_N + c * 8);
    }
    __syncthreads();
    #pragma unroll
    for (int l = 0; l < 8; l++) {
        int id = tid + l * 256;
        int d  = id >> 5;
        int jp = id & 31;
        __half2 a = sm_hi[(2 * jp) * VT_S + (d >> 1)];
        __half2 c = sm_hi[(2 * jp + 1) * VT_S + (d >> 1)];
        __half va = (d & 1) ? __high2half(a) : __low2half(a);
        __half vc = (d & 1) ? __high2half(c) : __low2half(c);
        vT_hi[((size_t)bh * HD + d) * (T_SEQ / 2) + j0 / 2 + jp] = __halves2half2(va, vc);
        a = sm_lo[(2 * jp) * VT_S + (d >> 1)];
        c = sm_lo[(2 * jp + 1) * VT_S + (d >> 1)];
        va = (d & 1) ? __high2half(a) : __low2half(a);
        vc = (d & 1) ? __high2half(c) : __low2half(c);
        vT_lo[((size_t)bh * HD + d) * (T_SEQ / 2) + j0 / 2 + jp] = __halves2half2(va, vc);
    }
}

// ---------------------------------------------------------------------------
// Fused RBF attention, fp16-split mma, i-tile = 128 rows.
// 8 warps as 4(i) x 2(j/d). S_scaled = 4096*exp(...) single fp16.
// smem: ks(hi,lo)[128], qs(hi,lo)[64], vs(hi,lo)[64], Ss[128], knv[128], qnv[64]
// ---------------------------------------------------------------------------
#define AT_S 36
#define AT_RB (AT_S * 4)       // row stride bytes (144)
#define ATT_SMEM_BYTES ((2*128 + 2*64 + 2*64 + 128) * AT_S * 4 + 128*4 + 64*4)
#define LOG4096 8.317766166719343f
#define INV4096 2.44140625e-4f

__global__ __launch_bounds__(256, 2) void attn_h2_kernel(
    const __half* __restrict__ qkv_hi, const __half* __restrict__ qkv_lo,
    const __half2* __restrict__ vT_hi, const __half2* __restrict__ vT_lo,
    const float* __restrict__ rsig,
    __half2* __restrict__ attn_hi, __half2* __restrict__ attn_lo)
{
    extern __shared__ char smraw[];
    __half2* ks_hi = (__half2*)smraw;                 // [128][AT_S]
    __half2* ks_lo = ks_hi + 128 * AT_S;
    __half2* qs_hi = ks_lo + 128 * AT_S;              // [64][AT_S]
    __half2* qs_lo = qs_hi + 64 * AT_S;
    __half2* vs_hi = qs_lo + 64 * AT_S;
    __half2* vs_lo = vs_hi + 64 * AT_S;
    __half2* Ss    = vs_lo + 64 * AT_S;               // [128][AT_S]
    float*   knv   = (float*)(Ss + 128 * AT_S);
    float*   qnv   = knv + 128;

    const int tid   = threadIdx.x;
    const int lane  = tid & 31;
    const int wid   = tid >> 5;
    const int g     = lane >> 2;
    const int tg    = lane & 3;
    const int warpM = wid & 3;        // i: 32 rows each (0..3)
    const int warpN = wid >> 2;       // j/d: 32 cols each (0..1)
    const int bh    = blockIdx.y;
    const int b     = bh / NH;
    const int h     = bh % NH;
    const int i0    = blockIdx.x * 128;
    const float nsig = -rsig[0];

    const uint32_t ksHib = (uint32_t)__cvta_generic_to_shared(ks_hi);
    const uint32_t ksLob = (uint32_t)__cvta_generic_to_shared(ks_lo);
    const uint32_t Ssb   = (uint32_t)__cvta_generic_to_shared(Ss);
    const uint32_t lds_off = ((lane & 7) + (lane & 8)) * AT_RB + (lane & 16);

    const size_t qoff = (size_t)b * T_SEQ * QKV_N + 0 * DIM + h * HD;
    const size_t koff = (size_t)b * T_SEQ * QKV_N + 1 * DIM + h * HD;

    const int lr = tid >> 3;   // 0..31
    const int lc = tid & 7;    // 16B chunk

    // ---- load K tile (128 rows) + fused kn ----
    {
        float kp[4];
        #pragma unroll
        for (int p = 0; p < 4; p++) {
            int r = lr + p * 32;
            int4 vh = *(const int4*)(qkv_hi + koff + (size_t)(i0 + r) * QKV_N + lc * 8);
            int4 vl = *(const int4*)(qkv_lo + koff + (size_t)(i0 + r) * QKV_N + lc * 8);
            *(int4*)&ks_hi[r * AT_S + lc * 4] = vh;
            *(int4*)&ks_lo[r * AT_S + lc * 4] = vl;
            kp[p] = sumsq8(vh, vl);
        }
        #pragma unroll
        for (int d = 1; d < 8; d <<= 1) {
            #pragma unroll
            for (int p = 0; p < 4; p++)
                kp[p] += __shfl_xor_sync(0xffffffffu, kp[p], d);
        }
        if (lc == 0) {
            #pragma unroll
            for (int p = 0; p < 4; p++) knv[lr + p * 32] = kp[p];
        }
    }

    float out[2][4][4];
    #pragma unroll
    for (int mt = 0; mt < 2; mt++)
        #pragma unroll
        for (int nt = 0; nt < 4; nt++)
            #pragma unroll
            for (int i = 0; i < 4; i++) out[mt][nt][i] = 0.f;

    for (int jt = 0; jt < T_SEQ / 64; jt++) {
        const int j0 = jt * 64;
        __syncthreads();   // prior iteration's reads of qs/vs/Ss done

        // ---- load q + v tiles (64 rows each), fused qn ----
        float qp[2];
        #pragma unroll
        for (int p = 0; p < 2; p++) {
            int r = lr + p * 32;
            int4 vh = *(const int4*)(qkv_hi + qoff + (size_t)(j0 + r) * QKV_N + lc * 8);
            int4 vl = *(const int4*)(qkv_lo + qoff + (size_t)(j0 + r) * QKV_N + lc * 8);
            *(int4*)&qs_hi[r * AT_S + lc * 4] = vh;
            *(int4*)&qs_lo[r * AT_S + lc * 4] = vl;
            qp[p] = sumsq8(vh, vl);
            const size_t vbase = ((size_t)bh * HD + r) * (T_SEQ / 2) + j0 / 2;
            *(int4*)&vs_hi[r * AT_S + lc * 4] = *(const int4*)(vT_hi + vbase + lc * 4);
            *(int4*)&vs_lo[r * AT_S + lc * 4] = *(const int4*)(vT_lo + vbase + lc * 4);
        }
        #pragma unroll
        for (int d = 1; d < 8; d <<= 1) {
            qp[0] += __shfl_xor_sync(0xffffffffu, qp[0], d);
            qp[1] += __shfl_xor_sync(0xffffffffu, qp[1], d);
        }
        if (lc == 0) { qnv[lr] = qp[0]; qnv[32 + lr] = qp[1]; }
        __syncthreads();

        // ---- S-mma: dot[i][j] over 64 dims (3-term split, K frags via ldmatrix) ----
        float sacc[2][4][4];
        #pragma unroll
        for (int mt = 0; mt < 2; mt++)
            #pragma unroll
            for (int nt = 0; nt < 4; nt++)
                #pragma unroll
                for (int i = 0; i < 4; i++) sacc[mt][nt][i] = 0.f;

        #pragma unroll
        for (int kc = 0; kc < 4; kc++) {
            int kp = kc * 8;
            uint32_t bh2[4][2], bl2[4][2];
            #pragma unroll
            for (int nt = 0; nt < 4; nt++) {
                int n0 = warpN * 32 + nt * 8 + g;
                bh2[nt][0] = *(const uint32_t*)&qs_hi[n0 * AT_S + kp + tg];
                bh2[nt][1] = *(const uint32_t*)&qs_hi[n0 * AT_S + kp + tg + 4];
                bl2[nt][0] = *(const uint32_t*)&qs_lo[n0 * AT_S + kp + tg];
                bl2[nt][1] = *(const uint32_t*)&qs_lo[n0 * AT_S + kp + tg + 4];
            }
            #pragma unroll
            for (int mt = 0; mt < 2; mt++) {
                uint32_t rowb = (uint32_t)(warpM * 32 + mt * 16) * AT_RB + kc * 32 + lds_off;
                uint32_t ah[4], al[4];
                ldsm_x4(ah, ksHib + rowb);
                ldsm_x4(al, ksLob + rowb);
                #pragma unroll
                for (int nt = 0; nt < 4; nt++)
                    mma3(sacc[mt][nt], ah, al, bh2[nt], bl2[nt]);
            }
        }

        // ---- exp (scaled by 4096) ----
        float ev[2][4][4];
        #pragma unroll
        for (int mt = 0; mt < 2; mt++) {
            int si = warpM * 32 + mt * 16 + g;
            float kA = knv[si], kB = knv[si + 8];
            #pragma unroll
            for (int nt = 0; nt < 4; nt++) {
                int jj = warpN * 32 + nt * 8 + tg * 2;
                float qA = qnv[jj], qB = qnv[jj + 1];
                ev[mt][nt][0] = __expf(nsig * (kA + qA - 2.f * sacc[mt][nt][0]) + LOG4096);
                ev[mt][nt][1] = __expf(nsig * (kA + qB - 2.f * sacc[mt][nt][1]) + LOG4096);
                ev[mt][nt][2] = __expf(nsig * (kB + qA - 2.f * sacc[mt][nt][2]) + LOG4096);
                ev[mt][nt][3] = __expf(nsig * (kB + qB - 2.f * sacc[mt][nt][3]) + LOG4096);
            }
        }

        // ---- store scaled S (single fp16) into Ss ----
        #pragma unroll
        for (int mt = 0; mt < 2; mt++) {
            int si = warpM * 32 + mt * 16 + g;
            #pragma unroll
            for (int nt = 0; nt < 4; nt++) {
                int jp = warpN * 16 + nt * 4 + tg;
                Ss[si * AT_S + jp]       = __floats2half2_rn(ev[mt][nt][0], ev[mt][nt][1]);
                Ss[(si + 8) * AT_S + jp] = __floats2half2_rn(ev[mt][nt][2], ev[mt][nt][3]);
            }
        }
        __syncthreads();

        // ---- out += S @ V  (2-term: S*Vh + S*Vl; S frags via ldmatrix) ----
        #pragma unroll
        for (int kc = 0; kc < 4; kc++) {
            int kp = kc * 8;
            uint32_t bh2[4][2], bl2[4][2];
            #pragma unroll
            for (int nt = 0; nt < 4; nt++) {
                int n0 = warpN * 32 + nt * 8 + g;
                bh2[nt][0] = *(const uint32_t*)&vs_hi[n0 * AT_S + kp + tg];
                bh2[nt][1] = *(const uint32_t*)&vs_hi[n0 * AT_S + kp + tg + 4];
                bl2[nt][0] = *(const uint32_t*)&vs_lo[n0 * AT_S + kp + tg];
                bl2[nt][1] = *(const uint32_t*)&vs_lo[n0 * AT_S + kp + tg + 4];
            }
            #pragma unroll
            for (int mt = 0; mt < 2; mt++) {
                uint32_t rowb = (uint32_t)(warpM * 32 + mt * 16) * AT_RB + kc * 32 + lds_off;
                uint32_t ah[4];
                ldsm_x4(ah, Ssb + rowb);
                #pragma unroll
                for (int nt = 0; nt < 4; nt++) {
                    mma_h(out[mt][nt], ah[0], ah[1], ah[2], ah[3],
                          bh2[nt][0], bh2[nt][1]);
                    mma_h(out[mt][nt], ah[0], ah[1], ah[2], ah[3],
                          bl2[nt][0], bl2[nt][1]);
                }
            }
        }
    }

    // ---- epilogue: unscale, split halves in (b,t,h,d) layout ----
    #pragma unroll
    for (int mt = 0; mt < 2; mt++) {
        #pragma unroll
        for (int nt = 0; nt < 4; nt++) {
            int irow = i0 + warpM * 32 + mt * 16 + g;
            int dcol = warpN * 32 + nt * 8 + tg * 2;
            size_t base = ((size_t)(b * T_SEQ + irow)) * (DIM / 2) + (h * HD + dcol) / 2;
            __half2 hh, ll;
            split2(out[mt][nt][0] * INV4096, out[mt][nt][1] * INV4096, hh, ll);
            attn_hi[base] = hh;
            attn_lo[base] = ll;
            split2(out[mt][nt][2] * INV4096, out[mt][nt][3] * INV4096, hh, ll);
            attn_hi[base + (size_t)8 * (DIM / 2)] = hh;
            attn_lo[base + (size_t)8 * (DIM / 2)] = ll;
        }
    }
}

// ---------------------------------------------------------------------------
extern "C" void kernel_launch(void* const* d_in, const int* in_sizes, int n_in,
                              void* d_out, int out_size)
{
    const float* x     = (const float*)d_in[0];
    const float* Wqkv  = (const float*)d_in[1];
    const float* bqkv  = (const float*)d_in[2];
    const float* rsig  = (const float*)d_in[3];
    const float* Wproj = (const float*)d_in[4];
    const float* bproj = (const float*)d_in[5];
    float* out = (float*)d_out;

    __half *x_hi, *x_lo, *qkv_hi, *qkv_lo, *attn_hi, *attn_lo;
    __half2 *wqkv_hi, *wqkv_lo, *wproj_hi, *wproj_lo, *vT_hi, *vT_lo;
    cudaGetSymbolAddress((void**)&x_hi, g_x_hi);
    cudaGetSymbolAddress((void**)&x_lo, g_x_lo);
    cudaGetSymbolAddress((void**)&wqkv_hi, g_wqkv_hi);
    cudaGetSymbolAddress((void**)&wqkv_lo, g_wqkv_lo);
    cudaGetSymbolAddress((void**)&wproj_hi, g_wproj_hi);
    cudaGetSymbolAddress((void**)&wproj_lo, g_wproj_lo);
    cudaGetSymbolAddress((void**)&qkv_hi, g_qkv_hi);
    cudaGetSymbolAddress((void**)&qkv_lo, g_qkv_lo);
    cudaGetSymbolAddress((void**)&vT_hi, g_vT_hi);
    cudaGetSymbolAddress((void**)&vT_lo, g_vT_lo);
    cudaGetSymbolAddress((void**)&attn_hi, g_attn_hi);
    cudaGetSymbolAddress((void**)&attn_lo, g_attn_lo);

    cudaFuncSetAttribute(attn_h2_kernel,
                         cudaFuncAttributeMaxDynamicSharedMemorySize, ATT_SMEM_BYTES);
    cudaFuncSetAttribute(gemm_h2_kernel<true>,
                         cudaFuncAttributeMaxDynamicSharedMemorySize, G_SMEM_BYTES);
    cudaFuncSetAttribute(gemm_h2_kernel<false>,
                         cudaFuncAttributeMaxDynamicSharedMemorySize, G_SMEM_BYTES);

    // prep: split x, pack weights
    {
        int n4 = ROWS * CDIM / 4;
        split_kernel<<<(n4 + 255) / 256, 256>>>(x, (__half2*)x_hi, (__half2*)x_lo, n4);
        int tq = (CDIM / 2) * (QKV_N / 4);
        pack_w_kernel<<<(tq + 255) / 256, 256>>>(Wqkv, wqkv_hi, wqkv_lo, CDIM, QKV_N);
        int tp = (DIM / 2) * (CDIM / 4);
        pack_w_kernel<<<(tp + 255) / 256, 256>>>(Wproj, wproj_hi, wproj_lo, DIM, CDIM);
    }
    // stage 1: qkv (split output)
    {
        dim3 grid(QKV_N / 128, ROWS / 128);
        gemm_h2_kernel<true><<<grid, 256, G_SMEM_BYTES>>>(
            x_hi, x_lo, wqkv_hi, wqkv_lo, bqkv,
            nullptr, (__half2*)qkv_hi, (__half2*)qkv_lo, ROWS, QKV_N, CDIM);
    }
    // repack V
    {
        dim3 grid(T_SEQ / 64, BATCH * NH);
        repack_v_kernel<<<grid, 256>>>(qkv_hi, qkv_lo, vT_hi, vT_lo);
    }
    // stage 2: attention (i-tile 128)
    {
        dim3 grid(T_SEQ / 128, BATCH * NH);
        attn_h2_kernel<<<grid, 256, ATT_SMEM_BYTES>>>(qkv_hi, qkv_lo, vT_hi, vT_lo,
                                                      rsig,
                                                      (__half2*)attn_hi, (__half2*)attn_lo);
    }
    // stage 3: out
    {
        dim3 grid(CDIM / 128, ROWS / 128);
        gemm_h2_kernel<false><<<grid, 256, G_SMEM_BYTES>>>(
            attn_hi, attn_lo, wproj_hi, wproj_lo, bproj,
            out, nullptr, nullptr, ROWS, CDIM, DIM);
    }
}

// round 9
// speedup vs baseline: 3.2507x; 1.0385x over previous
#include <cuda_runtime.h>
#include <cuda_fp16.h>
#include <cstdint>
#include <cstddef>

// Problem constants
#define BATCH   2
#define T_SEQ   2048
#define CDIM    1024
#define DIM     1024
#define NH      16
#define HD      64
#define QKV_N   3072
#define ROWS    (BATCH*T_SEQ)

// ---------------------------------------------------------------------------
// Device scratch (allocation-free rule). All 16B aligned.
// ---------------------------------------------------------------------------
__device__ __align__(16) __half g_x_hi[ROWS * CDIM];
__device__ __align__(16) __half g_x_lo[ROWS * CDIM];
__device__ __align__(16) __half2 g_wqkv_hi[(CDIM/2) * QKV_N];  // [K/2][N] k-pair packed
__device__ __align__(16) __half2 g_wqkv_lo[(CDIM/2) * QKV_N];
__device__ __align__(16) __half2 g_wproj_hi[(DIM/2) * CDIM];
__device__ __align__(16) __half2 g_wproj_lo[(DIM/2) * CDIM];
__device__ __align__(16) __half g_qkv_hi[ROWS * QKV_N];
__device__ __align__(16) __half g_qkv_lo[ROWS * QKV_N];
__device__ __align__(16) __half2 g_vT_hi[BATCH*NH * HD * (T_SEQ/2)]; // [bh][d][T/2]
__device__ __align__(16) __half2 g_vT_lo[BATCH*NH * HD * (T_SEQ/2)];
__device__ __align__(16) __half g_attn_hi[ROWS * DIM];
__device__ __align__(16) __half g_attn_lo[ROWS * DIM];

// ---------------------------------------------------------------------------
// helpers
// ---------------------------------------------------------------------------
__device__ __forceinline__ void split_h(float x, __half& hi, __half& lo) {
    hi = __float2half_rn(x);
    lo = __float2half_rn(x - __half2float(hi));
}
__device__ __forceinline__ void split2(float a, float b, __half2& h, __half2& l) {
    __half ha, la, hb, lb;
    split_h(a, ha, la);
    split_h(b, hb, lb);
    h = __halves2half2(ha, hb);
    l = __halves2half2(la, lb);
}

__device__ __forceinline__ void mma_h(float* d,
    uint32_t a0, uint32_t a1, uint32_t a2, uint32_t a3,
    uint32_t b0, uint32_t b1)
{
    asm volatile(
        "mma.sync.aligned.m16n8k16.row.col.f32.f16.f16.f32 "
        "{%0,%1,%2,%3}, {%4,%5,%6,%7}, {%8,%9}, {%0,%1,%2,%3};\n"
        : "+f"(d[0]), "+f"(d[1]), "+f"(d[2]), "+f"(d[3])
        : "r"(a0), "r"(a1), "r"(a2), "r"(a3), "r"(b0), "r"(b1));
}
// hi*hi + hi*lo + lo*hi
__device__ __forceinline__ void mma3(float* d,
    const uint32_t ah[4], const uint32_t al[4],
    const uint32_t bh[2], const uint32_t bl[2])
{
    mma_h(d, ah[0], ah[1], ah[2], ah[3], bh[0], bh[1]);
    mma_h(d, ah[0], ah[1], ah[2], ah[3], bl[0], bl[1]);
    mma_h(d, al[0], al[1], al[2], al[3], bh[0], bh[1]);
}

__device__ __forceinline__ void ldsm_x4(uint32_t* r, uint32_t addr) {
    asm volatile("ldmatrix.sync.aligned.m8n8.x4.shared.b16 {%0,%1,%2,%3}, [%4];"
        : "=r"(r[0]), "=r"(r[1]), "=r"(r[2]), "=r"(r[3]) : "r"(addr));
}

__device__ __forceinline__ void cp16(void* dst, const void* src) {
    uint32_t d = (uint32_t)__cvta_generic_to_shared(dst);
    asm volatile("cp.async.cg.shared.global [%0], [%1], 16;\n" :: "r"(d), "l"(src));
}
__device__ __forceinline__ void cp_commit() { asm volatile("cp.async.commit_group;\n"); }
template<int N> __device__ __forceinline__ void cp_wait() {
    asm volatile("cp.async.wait_group %0;\n" :: "n"(N));
}

// sum of squares of 8 split halves
__device__ __forceinline__ float sumsq8(int4 hbits, int4 lbits) {
    const __half2* h = (const __half2*)&hbits;
    const __half2* l = (const __half2*)&lbits;
    float s = 0.f;
    #pragma unroll
    for (int i = 0; i < 4; i++) {
        float2 a = __half22float2(h[i]);
        float2 b = __half22float2(l[i]);
        float x = a.x + b.x, y = a.y + b.y;
        s += x * x + y * y;
    }
    return s;
}

// ---------------------------------------------------------------------------
// Prep kernels
// ---------------------------------------------------------------------------
__global__ void split_kernel(const float* __restrict__ src,
                             __half2* __restrict__ hi, __half2* __restrict__ lo,
                             int n4)
{
    int i = blockIdx.x * blockDim.x + threadIdx.x;
    if (i >= n4) return;
    float4 v = *(const float4*)(src + (size_t)i * 4);
    __half2 h0, l0, h1, l1;
    split2(v.x, v.y, h0, l0);
    split2(v.z, v.w, h1, l1);
    hi[(size_t)i * 2]     = h0;
    hi[(size_t)i * 2 + 1] = h1;
    lo[(size_t)i * 2]     = l0;
    lo[(size_t)i * 2 + 1] = l1;
}

// Pack weights: W[K][N] fp32 -> [K/2][N] half2 (k-pair in one half2)
__global__ void pack_w_kernel(const float* __restrict__ W,
                              __half2* __restrict__ hi, __half2* __restrict__ lo,
                              int K, int N)
{
    int idx = blockIdx.x * blockDim.x + threadIdx.x;
    int total = (K / 2) * (N / 4);
    if (idx >= total) return;
    int kp = idx / (N / 4);
    int n4 = (idx % (N / 4)) * 4;
    float4 r0 = *(const float4*)(W + (size_t)(2 * kp) * N + n4);
    float4 r1 = *(const float4*)(W + (size_t)(2 * kp + 1) * N + n4);
    const float a[4] = {r0.x, r0.y, r0.z, r0.w};
    const float b[4] = {r1.x, r1.y, r1.z, r1.w};
    #pragma unroll
    for (int t = 0; t < 4; t++) {
        __half h0, l0, h1, l1;
        split_h(a[t], h0, l0);
        split_h(b[t], h1, l1);
        hi[(size_t)kp * N + n4 + t] = __halves2half2(h0, h1);
        lo[(size_t)kp * N + n4 + t] = __halves2half2(l0, l1);
    }
}

// ---------------------------------------------------------------------------
// GEMM: C[M,N] = (Ahi+Alo)[M,K] @ W[K,N] + bias, fp16 split mma.
// BM=128 BN=128 BK=32, 8 warps (2x4), warp tile 64x32.
// 3-stage cp.async ring (1 sync per 32-k chunk); A frags via ldmatrix.x4.
// A row stride 20 half2 = 80B: multiple of 16B (cp.async legal), and
// 8-row ldmatrix offsets mod 128 all distinct (conflict-free).
// ---------------------------------------------------------------------------
#define AS_S 20     // half2 stride per m-row (16 used + 4 pad) = 80B
#define BS_S 132    // half2 stride per kp-row (128 used + 4 pad) = 528B
#define A_H2 (128 * AS_S)
#define B_H2 (16 * BS_S)
#define STG_H2 (2 * A_H2 + 2 * B_H2)
#define G_SMEM_BYTES (3 * STG_H2 * 4)

template<bool SPLIT_OUT>
__global__ __launch_bounds__(256, 2) void gemm_h2_kernel(
    const __half* __restrict__ Ahi, const __half* __restrict__ Alo,
    const __half2* __restrict__ Bhi, const __half2* __restrict__ Blo,
    const float* __restrict__ bias,
    float* __restrict__ Cf, __half2* __restrict__ Chi, __half2* __restrict__ Clo,
    int M, int N, int K)
{
    extern __shared__ __half2 smg[];

    const int tid   = threadIdx.x;
    const int lane  = tid & 31;
    const int wid   = tid >> 5;
    const int g     = lane >> 2;
    const int tg    = lane & 3;
    const int warpM = wid >> 2;
    const int warpN = wid & 3;
    const int rowBase = blockIdx.y * 128;
    const int colBase = blockIdx.x * 128;
    const uint32_t sbase = (uint32_t)__cvta_generic_to_shared(smg);

    // ldmatrix lane offset within an A tile (row stride AS_S*4 = 80B)
    const uint32_t lds_off = ((lane & 7) + (lane & 8)) * (AS_S * 4) + (lane & 16);

    float acc[4][4][4];
    #pragma unroll
    for (int mt = 0; mt < 4; mt++)
        #pragma unroll
        for (int nt = 0; nt < 4; nt++)
            #pragma unroll
            for (int i = 0; i < 4; i++) acc[mt][nt][i] = 0.f;

    const int NT = K / 32;

    auto issue = [&](int st, int kt) {
        __half2* S = smg + st * STG_H2;
        // A: 128 rows x 32 halves (64B) = 512 chunks of 16B; 2 per thread
        #pragma unroll
        for (int l = 0; l < 2; l++) {
            int id = tid + l * 256;
            int ar = id >> 2, ac = id & 3;
            const size_t src = (size_t)(rowBase + ar) * K + kt + ac * 8;
            cp16(&S[ar * AS_S + ac * 4], Ahi + src);
            cp16(&S[A_H2 + ar * AS_S + ac * 4], Alo + src);
        }
        // B: 16 kp-rows x 128 half2 = 512 chunks of 16B; 2 per thread
        #pragma unroll
        for (int l = 0; l < 2; l++) {
            int id = tid + l * 256;
            int br = id >> 5, bc = id & 31;
            const size_t src = (size_t)((kt >> 1) + br) * N + colBase + bc * 4;
            cp16(&S[2 * A_H2 + br * BS_S + bc * 4], Bhi + src);
            cp16(&S[2 * A_H2 + B_H2 + br * BS_S + bc * 4], Blo + src);
        }
        cp_commit();
    };

    issue(0, 0);
    issue(1, 32);

    for (int t = 0; t < NT; t++) {
        if (t + 1 < NT) cp_wait<1>(); else cp_wait<0>();
        __syncthreads();
        if (t + 2 < NT) issue((t + 2) % 3, (t + 2) * 32);

        const uint32_t stg = sbase + (uint32_t)((t % 3) * STG_H2) * 4u;
        const uint32_t aHb = stg + lds_off + (uint32_t)(warpM * 64) * (AS_S * 4);
        const uint32_t aLb = aHb + (uint32_t)A_H2 * 4u;
        const __half2* S = smg + (t % 3) * STG_H2;
        const __half2* Bh = S + 2 * A_H2;
        const __half2* Bl = S + 2 * A_H2 + B_H2;

        #pragma unroll
        for (int kk = 0; kk < 32; kk += 16) {
            const int kpr = kk >> 1;   // kp row base for this sub-chunk
            uint32_t bh[4][2], bl[4][2];
            #pragma unroll
            for (int nt = 0; nt < 4; nt++) {
                int n0 = warpN * 32 + nt * 8 + g;
                bh[nt][0] = *(const uint32_t*)&Bh[(kpr + tg) * BS_S + n0];
                bh[nt][1] = *(const uint32_t*)&Bh[(kpr + tg + 4) * BS_S + n0];
                bl[nt][0] = *(const uint32_t*)&Bl[(kpr + tg) * BS_S + n0];
                bl[nt][1] = *(const uint32_t*)&Bl[(kpr + tg + 4) * BS_S + n0];
            }
            #pragma unroll
            for (int mt = 0; mt < 4; mt++) {
                uint32_t off = (uint32_t)(mt * 16) * (AS_S * 4) + kk * 2;
                uint32_t ah[4], al[4];
                ldsm_x4(ah, aHb + off);
                ldsm_x4(al, aLb + off);
                #pragma unroll
                for (int nt = 0; nt < 4; nt++)
                    mma3(acc[mt][nt], ah, al, bh[nt], bl[nt]);
            }
        }
    }

    // epilogue
    #pragma unroll
    for (int mt = 0; mt < 4; mt++) {
        #pragma unroll
        for (int nt = 0; nt < 4; nt++) {
            int r0 = rowBase + warpM * 64 + mt * 16 + g;
            int c0 = colBase + warpN * 32 + nt * 8 + tg * 2;
            float bz0 = bias[c0], bz1 = bias[c0 + 1];
            float v0 = acc[mt][nt][0] + bz0, v1 = acc[mt][nt][1] + bz1;
            float v2 = acc[mt][nt][2] + bz0, v3 = acc[mt][nt][3] + bz1;
            if (SPLIT_OUT) {
                __half2 h, l;
                split2(v0, v1, h, l);
                Chi[(size_t)r0 * (N / 2) + c0 / 2] = h;
                Clo[(size_t)r0 * (N / 2) + c0 / 2] = l;
                split2(v2, v3, h, l);
                Chi[(size_t)(r0 + 8) * (N / 2) + c0 / 2] = h;
                Clo[(size_t)(r0 + 8) * (N / 2) + c0 / 2] = l;
            } else {
                *(float2*)&Cf[(size_t)r0 * N + c0] = make_float2(v0, v1);
                *(float2*)&Cf[(size_t)(r0 + 8) * N + c0] = make_float2(v2, v3);
            }
        }
    }
}

// ---------------------------------------------------------------------------
// Repack V: qkv v-region [row][d] halves -> vT [bh][d][T/2] half2 (j-pairs)
// ---------------------------------------------------------------------------
#define VT_S 36
__global__ __launch_bounds__(256) void repack_v_kernel(
    const __half* __restrict__ qkv_hi, const __half* __restrict__ qkv_lo,
    __half2* __restrict__ vT_hi, __half2* __restrict__ vT_lo)
{
    __shared__ __half2 sm_hi[64 * VT_S];
    __shared__ __half2 sm_lo[64 * VT_S];
    const int tid = threadIdx.x;
    const int bh  = blockIdx.y;
    const int b   = bh / NH;
    const int h   = bh % NH;
    const int j0  = blockIdx.x * 64;

    const size_t base = ((size_t)(b * T_SEQ + j0)) * QKV_N + 2 * DIM + h * HD;
    #pragma unroll
    for (int l = 0; l < 2; l++) {
        int id = tid + l * 256;
        int r  = id >> 3;
        int c  = id & 7;
        *(int4*)&sm_hi[r * VT_S + c * 4] = *(const int4*)(qkv_hi + base + (size_t)r * QKV_N + c * 8);
        *(int4*)&sm_lo[r * VT_S + c * 4] = *(const int4*)(qkv_lo + base + (size_t)r * QKV_N + c * 8);
    }
    __syncthreads();
    #pragma unroll
    for (int l = 0; l < 8; l++) {
        int id = tid + l * 256;
        int d  = id >> 5;
        int jp = id & 31;
        __half2 a = sm_hi[(2 * jp) * VT_S + (d >> 1)];
        __half2 c = sm_hi[(2 * jp + 1) * VT_S + (d >> 1)];
        __half va = (d & 1) ? __high2half(a) : __low2half(a);
        __half vc = (d & 1) ? __high2half(c) : __low2half(c);
        vT_hi[((size_t)bh * HD + d) * (T_SEQ / 2) + j0 / 2 + jp] = __halves2half2(va, vc);
        a = sm_lo[(2 * jp) * VT_S + (d >> 1)];
        c = sm_lo[(2 * jp + 1) * VT_S + (d >> 1)];
        va = (d & 1) ? __high2half(a) : __low2half(a);
        vc = (d & 1) ? __high2half(c) : __low2half(c);
        vT_lo[((size_t)bh * HD + d) * (T_SEQ / 2) + j0 / 2 + jp] = __halves2half2(va, vc);
    }
}

// ---------------------------------------------------------------------------
// Fused RBF attention, fp16-split mma, i-tile = 128 rows.
// 8 warps as 4(i) x 2(j/d). S_scaled = 4096*exp(...) single fp16.
// ---------------------------------------------------------------------------
#define AT_S 36
#define AT_RB (AT_S * 4)       // row stride bytes (144)
#define ATT_SMEM_BYTES ((2*128 + 2*64 + 2*64 + 128) * AT_S * 4 + 128*4 + 64*4)
#define LOG4096 8.317766166719343f
#define INV4096 2.44140625e-4f

__global__ __launch_bounds__(256, 2) void attn_h2_kernel(
    const __half* __restrict__ qkv_hi, const __half* __restrict__ qkv_lo,
    const __half2* __restrict__ vT_hi, const __half2* __restrict__ vT_lo,
    const float* __restrict__ rsig,
    __half2* __restrict__ attn_hi, __half2* __restrict__ attn_lo)
{
    extern __shared__ char smraw[];
    __half2* ks_hi = (__half2*)smraw;                 // [128][AT_S]
    __half2* ks_lo = ks_hi + 128 * AT_S;
    __half2* qs_hi = ks_lo + 128 * AT_S;              // [64][AT_S]
    __half2* qs_lo = qs_hi + 64 * AT_S;
    __half2* vs_hi = qs_lo + 64 * AT_S;
    __half2* vs_lo = vs_hi + 64 * AT_S;
    __half2* Ss    = vs_lo + 64 * AT_S;               // [128][AT_S]
    float*   knv   = (float*)(Ss + 128 * AT_S);
    float*   qnv   = knv + 128;

    const int tid   = threadIdx.x;
    const int lane  = tid & 31;
    const int wid   = tid >> 5;
    const int g     = lane >> 2;
    const int tg    = lane & 3;
    const int warpM = wid & 3;        // i: 32 rows each (0..3)
    const int warpN = wid >> 2;       // j/d: 32 cols each (0..1)
    const int bh    = blockIdx.y;
    const int b     = bh / NH;
    const int h     = bh % NH;
    const int i0    = blockIdx.x * 128;
    const float nsig = -rsig[0];

    const uint32_t ksHib = (uint32_t)__cvta_generic_to_shared(ks_hi);
    const uint32_t ksLob = (uint32_t)__cvta_generic_to_shared(ks_lo);
    const uint32_t Ssb   = (uint32_t)__cvta_generic_to_shared(Ss);
    const uint32_t lds_off = ((lane & 7) + (lane & 8)) * AT_RB + (lane & 16);

    const size_t qoff = (size_t)b * T_SEQ * QKV_N + 0 * DIM + h * HD;
    const size_t koff = (size_t)b * T_SEQ * QKV_N + 1 * DIM + h * HD;

    const int lr = tid >> 3;   // 0..31
    const int lc = tid & 7;    // 16B chunk

    // ---- load K tile (128 rows) + fused kn ----
    {
        float kp[4];
        #pragma unroll
        for (int p = 0; p < 4; p++) {
            int r = lr + p * 32;
            int4 vh = *(const int4*)(qkv_hi + koff + (size_t)(i0 + r) * QKV_N + lc * 8);
            int4 vl = *(const int4*)(qkv_lo + koff + (size_t)(i0 + r) * QKV_N + lc * 8);
            *(int4*)&ks_hi[r * AT_S + lc * 4] = vh;
            *(int4*)&ks_lo[r * AT_S + lc * 4] = vl;
            kp[p] = sumsq8(vh, vl);
        }
        #pragma unroll
        for (int d = 1; d < 8; d <<= 1) {
            #pragma unroll
            for (int p = 0; p < 4; p++)
                kp[p] += __shfl_xor_sync(0xffffffffu, kp[p], d);
        }
        if (lc == 0) {
            #pragma unroll
            for (int p = 0; p < 4; p++) knv[lr + p * 32] = kp[p];
        }
    }

    float out[2][4][4];
    #pragma unroll
    for (int mt = 0; mt < 2; mt++)
        #pragma unroll
        for (int nt = 0; nt < 4; nt++)
            #pragma unroll
            for (int i = 0; i < 4; i++) out[mt][nt][i] = 0.f;

    for (int jt = 0; jt < T_SEQ / 64; jt++) {
        const int j0 = jt * 64;
        __syncthreads();   // prior iteration's reads of qs/vs/Ss done

        // ---- load q + v tiles (64 rows each), fused qn ----
        float qp[2];
        #pragma unroll
        for (int p = 0; p < 2; p++) {
            int r = lr + p * 32;
            int4 vh = *(const int4*)(qkv_hi + qoff + (size_t)(j0 + r) * QKV_N + lc * 8);
            int4 vl = *(const int4*)(qkv_lo + qoff + (size_t)(j0 + r) * QKV_N + lc * 8);
            *(int4*)&qs_hi[r * AT_S + lc * 4] = vh;
            *(int4*)&qs_lo[r * AT_S + lc * 4] = vl;
            qp[p] = sumsq8(vh, vl);
            const size_t vbase = ((size_t)bh * HD + r) * (T_SEQ / 2) + j0 / 2;
            *(int4*)&vs_hi[r * AT_S + lc * 4] = *(const int4*)(vT_hi + vbase + lc * 4);
            *(int4*)&vs_lo[r * AT_S + lc * 4] = *(const int4*)(vT_lo + vbase + lc * 4);
        }
        #pragma unroll
        for (int d = 1; d < 8; d <<= 1) {
            qp[0] += __shfl_xor_sync(0xffffffffu, qp[0], d);
            qp[1] += __shfl_xor_sync(0xffffffffu, qp[1], d);
        }
        if (lc == 0) { qnv[lr] = qp[0]; qnv[32 + lr] = qp[1]; }
        __syncthreads();

        // ---- S-mma: dot[i][j] over 64 dims (3-term split, K frags via ldmatrix) ----
        float sacc[2][4][4];
        #pragma unroll
        for (int mt = 0; mt < 2; mt++)
            #pragma unroll
            for (int nt = 0; nt < 4; nt++)
                #pragma unroll
                for (int i = 0; i < 4; i++) sacc[mt][nt][i] = 0.f;

        #pragma unroll
        for (int kc = 0; kc < 4; kc++) {
            int kp = kc * 8;
            uint32_t bh2[4][2], bl2[4][2];
            #pragma unroll
            for (int nt = 0; nt < 4; nt++) {
                int n0 = warpN * 32 + nt * 8 + g;
                bh2[nt][0] = *(const uint32_t*)&qs_hi[n0 * AT_S + kp + tg];
                bh2[nt][1] = *(const uint32_t*)&qs_hi[n0 * AT_S + kp + tg + 4];
                bl2[nt][0] = *(const uint32_t*)&qs_lo[n0 * AT_S + kp + tg];
                bl2[nt][1] = *(const uint32_t*)&qs_lo[n0 * AT_S + kp + tg + 4];
            }
            #pragma unroll
            for (int mt = 0; mt < 2; mt++) {
                uint32_t rowb = (uint32_t)(warpM * 32 + mt * 16) * AT_RB + kc * 32 + lds_off;
                uint32_t ah[4], al[4];
                ldsm_x4(ah, ksHib + rowb);
                ldsm_x4(al, ksLob + rowb);
                #pragma unroll
                for (int nt = 0; nt < 4; nt++)
                    mma3(sacc[mt][nt], ah, al, bh2[nt], bl2[nt]);
            }
        }

        // ---- exp (scaled by 4096) ----
        float ev[2][4][4];
        #pragma unroll
        for (int mt = 0; mt < 2; mt++) {
            int si = warpM * 32 + mt * 16 + g;
            float kA = knv[si], kB = knv[si + 8];
            #pragma unroll
            for (int nt = 0; nt < 4; nt++) {
                int jj = warpN * 32 + nt * 8 + tg * 2;
                float qA = qnv[jj], qB = qnv[jj + 1];
                ev[mt][nt][0] = __expf(nsig * (kA + qA - 2.f * sacc[mt][nt][0]) + LOG4096);
                ev[mt][nt][1] = __expf(nsig * (kA + qB - 2.f * sacc[mt][nt][1]) + LOG4096);
                ev[mt][nt][2] = __expf(nsig * (kB + qA - 2.f * sacc[mt][nt][2]) + LOG4096);
                ev[mt][nt][3] = __expf(nsig * (kB + qB - 2.f * sacc[mt][nt][3]) + LOG4096);
            }
        }

        // ---- store scaled S (single fp16) into Ss ----
        #pragma unroll
        for (int mt = 0; mt < 2; mt++) {
            int si = warpM * 32 + mt * 16 + g;
            #pragma unroll
            for (int nt = 0; nt < 4; nt++) {
                int jp = warpN * 16 + nt * 4 + tg;
                Ss[si * AT_S + jp]       = __floats2half2_rn(ev[mt][nt][0], ev[mt][nt][1]);
                Ss[(si + 8) * AT_S + jp] = __floats2half2_rn(ev[mt][nt][2], ev[mt][nt][3]);
            }
        }
        __syncthreads();

        // ---- out += S @ V  (2-term: S*Vh + S*Vl; S frags via ldmatrix) ----
        #pragma unroll
        for (int kc = 0; kc < 4; kc++) {
            int kp = kc * 8;
            uint32_t bh2[4][2], bl2[4][2];
            #pragma unroll
            for (int nt = 0; nt < 4; nt++) {
                int n0 = warpN * 32 + nt * 8 + g;
                bh2[nt][0] = *(const uint32_t*)&vs_hi[n0 * AT_S + kp + tg];
                bh2[nt][1] = *(const uint32_t*)&vs_hi[n0 * AT_S + kp + tg + 4];
                bl2[nt][0] = *(const uint32_t*)&vs_lo[n0 * AT_S + kp + tg];
                bl2[nt][1] = *(const uint32_t*)&vs_lo[n0 * AT_S + kp + tg + 4];
            }
            #pragma unroll
            for (int mt = 0; mt < 2; mt++) {
                uint32_t rowb = (uint32_t)(warpM * 32 + mt * 16) * AT_RB + kc * 32 + lds_off;
                uint32_t ah[4];
                ldsm_x4(ah, Ssb + rowb);
                #pragma unroll
                for (int nt = 0; nt < 4; nt++) {
                    mma_h(out[mt][nt], ah[0], ah[1], ah[2], ah[3],
                          bh2[nt][0], bh2[nt][1]);
                    mma_h(out[mt][nt], ah[0], ah[1], ah[2], ah[3],
                          bl2[nt][0], bl2[nt][1]);
                }
            }
        }
    }

    // ---- epilogue: unscale, split halves in (b,t,h,d) layout ----
    #pragma unroll
    for (int mt = 0; mt < 2; mt++) {
        #pragma unroll
        for (int nt = 0; nt < 4; nt++) {
            int irow = i0 + warpM * 32 + mt * 16 + g;
            int dcol = warpN * 32 + nt * 8 + tg * 2;
            size_t base = ((size_t)(b * T_SEQ + irow)) * (DIM / 2) + (h * HD + dcol) / 2;
            __half2 hh, ll;
            split2(out[mt][nt][0] * INV4096, out[mt][nt][1] * INV4096, hh, ll);
            attn_hi[base] = hh;
            attn_lo[base] = ll;
            split2(out[mt][nt][2] * INV4096, out[mt][nt][3] * INV4096, hh, ll);
            attn_hi[base + (size_t)8 * (DIM / 2)] = hh;
            attn_lo[base + (size_t)8 * (DIM / 2)] = ll;
        }
    }
}

// ---------------------------------------------------------------------------
extern "C" void kernel_launch(void* const* d_in, const int* in_sizes, int n_in,
                              void* d_out, int out_size)
{
    const float* x     = (const float*)d_in[0];
    const float* Wqkv  = (const float*)d_in[1];
    const float* bqkv  = (const float*)d_in[2];
    const float* rsig  = (const float*)d_in[3];
    const float* Wproj = (const float*)d_in[4];
    const float* bproj = (const float*)d_in[5];
    float* out = (float*)d_out;

    __half *x_hi, *x_lo, *qkv_hi, *qkv_lo, *attn_hi, *attn_lo;
    __half2 *wqkv_hi, *wqkv_lo, *wproj_hi, *wproj_lo, *vT_hi, *vT_lo;
    cudaGetSymbolAddress((void**)&x_hi, g_x_hi);
    cudaGetSymbolAddress((void**)&x_lo, g_x_lo);
    cudaGetSymbolAddress((void**)&wqkv_hi, g_wqkv_hi);
    cudaGetSymbolAddress((void**)&wqkv_lo, g_wqkv_lo);
    cudaGetSymbolAddress((void**)&wproj_hi, g_wproj_hi);
    cudaGetSymbolAddress((void**)&wproj_lo, g_wproj_lo);
    cudaGetSymbolAddress((void**)&qkv_hi, g_qkv_hi);
    cudaGetSymbolAddress((void**)&qkv_lo, g_qkv_lo);
    cudaGetSymbolAddress((void**)&vT_hi, g_vT_hi);
    cudaGetSymbolAddress((void**)&vT_lo, g_vT_lo);
    cudaGetSymbolAddress((void**)&attn_hi, g_attn_hi);
    cudaGetSymbolAddress((void**)&attn_lo, g_attn_lo);

    cudaFuncSetAttribute(attn_h2_kernel,
                         cudaFuncAttributeMaxDynamicSharedMemorySize, ATT_SMEM_BYTES);
    cudaFuncSetAttribute(gemm_h2_kernel<true>,
                         cudaFuncAttributeMaxDynamicSharedMemorySize, G_SMEM_BYTES);
    cudaFuncSetAttribute(gemm_h2_kernel<false>,
                         cudaFuncAttributeMaxDynamicSharedMemorySize, G_SMEM_BYTES);

    // prep: split x, pack weights
    {
        int n4 = ROWS * CDIM / 4;
        split_kernel<<<(n4 + 255) / 256, 256>>>(x, (__half2*)x_hi, (__half2*)x_lo, n4);
        int tq = (CDIM / 2) * (QKV_N / 4);
        pack_w_kernel<<<(tq + 255) / 256, 256>>>(Wqkv, wqkv_hi, wqkv_lo, CDIM, QKV_N);
        int tp = (DIM / 2) * (CDIM / 4);
        pack_w_kernel<<<(tp + 255) / 256, 256>>>(Wproj, wproj_hi, wproj_lo, DIM, CDIM);
    }
    // stage 1: qkv (split output)
    {
        dim3 grid(QKV_N / 128, ROWS / 128);
        gemm_h2_kernel<true><<<grid, 256, G_SMEM_BYTES>>>(
            x_hi, x_lo, wqkv_hi, wqkv_lo, bqkv,
            nullptr, (__half2*)qkv_hi, (__half2*)qkv_lo, ROWS, QKV_N, CDIM);
    }
    // repack V
    {
        dim3 grid(T_SEQ / 64, BATCH * NH);
        repack_v_kernel<<<grid, 256>>>(qkv_hi, qkv_lo, vT_hi, vT_lo);
    }
    // stage 2: attention (i-tile 128)
    {
        dim3 grid(T_SEQ / 128, BATCH * NH);
        attn_h2_kernel<<<grid, 256, ATT_SMEM_BYTES>>>(qkv_hi, qkv_lo, vT_hi, vT_lo,
                                                      rsig,
                                                      (__half2*)attn_hi, (__half2*)attn_lo);
    }
    // stage 3: out
    {
        dim3 grid(CDIM / 128, ROWS / 128);
        gemm_h2_kernel<false><<<grid, 256, G_SMEM_BYTES>>>(
            attn_hi, attn_lo, wproj_hi, wproj_lo, bproj,
            out, nullptr, nullptr, ROWS, CDIM, DIM);
    }
}

// round 10
// speedup vs baseline: 3.2513x; 1.0002x over previous
#include <cuda_runtime.h>
#include <cuda_fp16.h>
#include <cstdint>
#include <cstddef>

// Problem constants
#define BATCH   2
#define T_SEQ   2048
#define CDIM    1024
#define DIM     1024
#define NH      16
#define HD      64
#define QKV_N   3072
#define ROWS    (BATCH*T_SEQ)

// ---------------------------------------------------------------------------
// Device scratch (allocation-free rule). All 16B aligned.
// ---------------------------------------------------------------------------
__device__ __align__(16) __half g_x_hi[ROWS * CDIM];
__device__ __align__(16) __half g_x_lo[ROWS * CDIM];
__device__ __align__(16) __half2 g_wqkv_hi[(CDIM/2) * QKV_N];  // [K/2][N] k-pair packed
__device__ __align__(16) __half2 g_wqkv_lo[(CDIM/2) * QKV_N];
__device__ __align__(16) __half2 g_wproj_hi[(DIM/2) * CDIM];
__device__ __align__(16) __half2 g_wproj_lo[(DIM/2) * CDIM];
__device__ __align__(16) __half g_qkv_hi[ROWS * QKV_N];
__device__ __align__(16) __half g_qkv_lo[ROWS * QKV_N];
__device__ __align__(16) __half2 g_vT_hi[BATCH*NH * HD * (T_SEQ/2)]; // [bh][d][T/2]
__device__ __align__(16) __half2 g_vT_lo[BATCH*NH * HD * (T_SEQ/2)];
__device__ __align__(16) __half g_attn_hi[ROWS * DIM];
__device__ __align__(16) __half g_attn_lo[ROWS * DIM];

// ---------------------------------------------------------------------------
// helpers
// ---------------------------------------------------------------------------
__device__ __forceinline__ void split_h(float x, __half& hi, __half& lo) {
    hi = __float2half_rn(x);
    lo = __float2half_rn(x - __half2float(hi));
}
__device__ __forceinline__ void split2(float a, float b, __half2& h, __half2& l) {
    __half ha, la, hb, lb;
    split_h(a, ha, la);
    split_h(b, hb, lb);
    h = __halves2half2(ha, hb);
    l = __halves2half2(la, lb);
}

__device__ __forceinline__ void mma_h(float* d,
    uint32_t a0, uint32_t a1, uint32_t a2, uint32_t a3,
    uint32_t b0, uint32_t b1)
{
    asm volatile(
        "mma.sync.aligned.m16n8k16.row.col.f32.f16.f16.f32 "
        "{%0,%1,%2,%3}, {%4,%5,%6,%7}, {%8,%9}, {%0,%1,%2,%3};\n"
        : "+f"(d[0]), "+f"(d[1]), "+f"(d[2]), "+f"(d[3])
        : "r"(a0), "r"(a1), "r"(a2), "r"(a3), "r"(b0), "r"(b1));
}
// hi*hi + hi*lo + lo*hi
__device__ __forceinline__ void mma3(float* d,
    const uint32_t ah[4], const uint32_t al[4],
    const uint32_t bh[2], const uint32_t bl[2])
{
    mma_h(d, ah[0], ah[1], ah[2], ah[3], bh[0], bh[1]);
    mma_h(d, ah[0], ah[1], ah[2], ah[3], bl[0], bl[1]);
    mma_h(d, al[0], al[1], al[2], al[3], bh[0], bh[1]);
}

__device__ __forceinline__ void ldsm_x4(uint32_t* r, uint32_t addr) {
    asm volatile("ldmatrix.sync.aligned.m8n8.x4.shared.b16 {%0,%1,%2,%3}, [%4];"
        : "=r"(r[0]), "=r"(r[1]), "=r"(r[2]), "=r"(r[3]) : "r"(addr));
}

__device__ __forceinline__ void cp16(void* dst, const void* src) {
    uint32_t d = (uint32_t)__cvta_generic_to_shared(dst);
    asm volatile("cp.async.cg.shared.global [%0], [%1], 16;\n" :: "r"(d), "l"(src));
}
__device__ __forceinline__ void cp_commit() { asm volatile("cp.async.commit_group;\n"); }
template<int N> __device__ __forceinline__ void cp_wait() {
    asm volatile("cp.async.wait_group %0;\n" :: "n"(N));
}

// sum of squares of 8 split halves
__device__ __forceinline__ float sumsq8(int4 hbits, int4 lbits) {
    const __half2* h = (const __half2*)&hbits;
    const __half2* l = (const __half2*)&lbits;
    float s = 0.f;
    #pragma unroll
    for (int i = 0; i < 4; i++) {
        float2 a = __half22float2(h[i]);
        float2 b = __half22float2(l[i]);
        float x = a.x + b.x, y = a.y + b.y;
        s += x * x + y * y;
    }
    return s;
}

// ---------------------------------------------------------------------------
// Prep kernels
// ---------------------------------------------------------------------------
__global__ void split_kernel(const float* __restrict__ src,
                             __half2* __restrict__ hi, __half2* __restrict__ lo,
                             int n4)
{
    int i = blockIdx.x * blockDim.x + threadIdx.x;
    if (i >= n4) return;
    float4 v = *(const float4*)(src + (size_t)i * 4);
    __half2 h0, l0, h1, l1;
    split2(v.x, v.y, h0, l0);
    split2(v.z, v.w, h1, l1);
    hi[(size_t)i * 2]     = h0;
    hi[(size_t)i * 2 + 1] = h1;
    lo[(size_t)i * 2]     = l0;
    lo[(size_t)i * 2 + 1] = l1;
}

// Pack weights: W[K][N] fp32 -> [K/2][N] half2 (k-pair in one half2)
__global__ void pack_w_kernel(const float* __restrict__ W,
                              __half2* __restrict__ hi, __half2* __restrict__ lo,
                              int K, int N)
{
    int idx = blockIdx.x * blockDim.x + threadIdx.x;
    int total = (K / 2) * (N / 4);
    if (idx >= total) return;
    int kp = idx / (N / 4);
    int n4 = (idx % (N / 4)) * 4;
    float4 r0 = *(const float4*)(W + (size_t)(2 * kp) * N + n4);
    float4 r1 = *(const float4*)(W + (size_t)(2 * kp + 1) * N + n4);
    const float a[4] = {r0.x, r0.y, r0.z, r0.w};
    const float b[4] = {r1.x, r1.y, r1.z, r1.w};
    #pragma unroll
    for (int t = 0; t < 4; t++) {
        __half h0, l0, h1, l1;
        split_h(a[t], h0, l0);
        split_h(b[t], h1, l1);
        hi[(size_t)kp * N + n4 + t] = __halves2half2(h0, h1);
        lo[(size_t)kp * N + n4 + t] = __halves2half2(l0, l1);
    }
}

// ---------------------------------------------------------------------------
// GEMM: C[M,N] = (Ahi+Alo)[M,K] @ W[K,N] + bias, fp16 split mma.
// BM=128 BN=128 BK=32, 8 warps (2x4), warp tile 64x32.
// 3-stage cp.async ring (1 sync per 32-k chunk); A frags via ldmatrix.x4.
// ---------------------------------------------------------------------------
#define AS_S 20     // half2 stride per m-row (16 used + 4 pad) = 80B
#define BS_S 132    // half2 stride per kp-row (128 used + 4 pad) = 528B
#define A_H2 (128 * AS_S)
#define B_H2 (16 * BS_S)
#define STG_H2 (2 * A_H2 + 2 * B_H2)
#define G_SMEM_BYTES (3 * STG_H2 * 4)

template<bool SPLIT_OUT>
__global__ __launch_bounds__(256, 2) void gemm_h2_kernel(
    const __half* __restrict__ Ahi, const __half* __restrict__ Alo,
    const __half2* __restrict__ Bhi, const __half2* __restrict__ Blo,
    const float* __restrict__ bias,
    float* __restrict__ Cf, __half2* __restrict__ Chi, __half2* __restrict__ Clo,
    int M, int N, int K)
{
    extern __shared__ __half2 smg[];

    const int tid   = threadIdx.x;
    const int lane  = tid & 31;
    const int wid   = tid >> 5;
    const int g     = lane >> 2;
    const int tg    = lane & 3;
    const int warpM = wid >> 2;
    const int warpN = wid & 3;
    const int rowBase = blockIdx.y * 128;
    const int colBase = blockIdx.x * 128;
    const uint32_t sbase = (uint32_t)__cvta_generic_to_shared(smg);

    const uint32_t lds_off = ((lane & 7) + (lane & 8)) * (AS_S * 4) + (lane & 16);

    float acc[4][4][4];
    #pragma unroll
    for (int mt = 0; mt < 4; mt++)
        #pragma unroll
        for (int nt = 0; nt < 4; nt++)
            #pragma unroll
            for (int i = 0; i < 4; i++) acc[mt][nt][i] = 0.f;

    const int NT = K / 32;

    auto issue = [&](int st, int kt) {
        __half2* S = smg + st * STG_H2;
        #pragma unroll
        for (int l = 0; l < 2; l++) {
            int id = tid + l * 256;
            int ar = id >> 2, ac = id & 3;
            const size_t src = (size_t)(rowBase + ar) * K + kt + ac * 8;
            cp16(&S[ar * AS_S + ac * 4], Ahi + src);
            cp16(&S[A_H2 + ar * AS_S + ac * 4], Alo + src);
        }
        #pragma unroll
        for (int l = 0; l < 2; l++) {
            int id = tid + l * 256;
            int br = id >> 5, bc = id & 31;
            const size_t src = (size_t)((kt >> 1) + br) * N + colBase + bc * 4;
            cp16(&S[2 * A_H2 + br * BS_S + bc * 4], Bhi + src);
            cp16(&S[2 * A_H2 + B_H2 + br * BS_S + bc * 4], Blo + src);
        }
        cp_commit();
    };

    issue(0, 0);
    issue(1, 32);

    for (int t = 0; t < NT; t++) {
        if (t + 1 < NT) cp_wait<1>(); else cp_wait<0>();
        __syncthreads();
        if (t + 2 < NT) issue((t + 2) % 3, (t + 2) * 32);

        const uint32_t stg = sbase + (uint32_t)((t % 3) * STG_H2) * 4u;
        const uint32_t aHb = stg + lds_off + (uint32_t)(warpM * 64) * (AS_S * 4);
        const uint32_t aLb = aHb + (uint32_t)A_H2 * 4u;
        const __half2* S = smg + (t % 3) * STG_H2;
        const __half2* Bh = S + 2 * A_H2;
        const __half2* Bl = S + 2 * A_H2 + B_H2;

        #pragma unroll
        for (int kk = 0; kk < 32; kk += 16) {
            const int kpr = kk >> 1;
            uint32_t bh[4][2], bl[4][2];
            #pragma unroll
            for (int nt = 0; nt < 4; nt++) {
                int n0 = warpN * 32 + nt * 8 + g;
                bh[nt][0] = *(const uint32_t*)&Bh[(kpr + tg) * BS_S + n0];
                bh[nt][1] = *(const uint32_t*)&Bh[(kpr + tg + 4) * BS_S + n0];
                bl[nt][0] = *(const uint32_t*)&Bl[(kpr + tg) * BS_S + n0];
                bl[nt][1] = *(const uint32_t*)&Bl[(kpr + tg + 4) * BS_S + n0];
            }
            #pragma unroll
            for (int mt = 0; mt < 4; mt++) {
                uint32_t off = (uint32_t)(mt * 16) * (AS_S * 4) + kk * 2;
                uint32_t ah[4], al[4];
                ldsm_x4(ah, aHb + off);
                ldsm_x4(al, aLb + off);
                #pragma unroll
                for (int nt = 0; nt < 4; nt++)
                    mma3(acc[mt][nt], ah, al, bh[nt], bl[nt]);
            }
        }
    }

    // epilogue
    #pragma unroll
    for (int mt = 0; mt < 4; mt++) {
        #pragma unroll
        for (int nt = 0; nt < 4; nt++) {
            int r0 = rowBase + warpM * 64 + mt * 16 + g;
            int c0 = colBase + warpN * 32 + nt * 8 + tg * 2;
            float bz0 = bias[c0], bz1 = bias[c0 + 1];
            float v0 = acc[mt][nt][0] + bz0, v1 = acc[mt][nt][1] + bz1;
            float v2 = acc[mt][nt][2] + bz0, v3 = acc[mt][nt][3] + bz1;
            if (SPLIT_OUT) {
                __half2 h, l;
                split2(v0, v1, h, l);
                Chi[(size_t)r0 * (N / 2) + c0 / 2] = h;
                Clo[(size_t)r0 * (N / 2) + c0 / 2] = l;
                split2(v2, v3, h, l);
                Chi[(size_t)(r0 + 8) * (N / 2) + c0 / 2] = h;
                Clo[(size_t)(r0 + 8) * (N / 2) + c0 / 2] = l;
            } else {
                *(float2*)&Cf[(size_t)r0 * N + c0] = make_float2(v0, v1);
                *(float2*)&Cf[(size_t)(r0 + 8) * N + c0] = make_float2(v2, v3);
            }
        }
    }
}

// ---------------------------------------------------------------------------
// Repack V: qkv v-region [row][d] halves -> vT [bh][d][T/2] half2 (j-pairs)
// ---------------------------------------------------------------------------
#define VT_S 36
__global__ __launch_bounds__(256) void repack_v_kernel(
    const __half* __restrict__ qkv_hi, const __half* __restrict__ qkv_lo,
    __half2* __restrict__ vT_hi, __half2* __restrict__ vT_lo)
{
    __shared__ __half2 sm_hi[64 * VT_S];
    __shared__ __half2 sm_lo[64 * VT_S];
    const int tid = threadIdx.x;
    const int bh  = blockIdx.y;
    const int b   = bh / NH;
    const int h   = bh % NH;
    const int j0  = blockIdx.x * 64;

    const size_t base = ((size_t)(b * T_SEQ + j0)) * QKV_N + 2 * DIM + h * HD;
    #pragma unroll
    for (int l = 0; l < 2; l++) {
        int id = tid + l * 256;
        int r  = id >> 3;
        int c  = id & 7;
        *(int4*)&sm_hi[r * VT_S + c * 4] = *(const int4*)(qkv_hi + base + (size_t)r * QKV_N + c * 8);
        *(int4*)&sm_lo[r * VT_S + c * 4] = *(const int4*)(qkv_lo + base + (size_t)r * QKV_N + c * 8);
    }
    __syncthreads();
    #pragma unroll
    for (int l = 0; l < 8; l++) {
        int id = tid + l * 256;
        int d  = id >> 5;
        int jp = id & 31;
        __half2 a = sm_hi[(2 * jp) * VT_S + (d >> 1)];
        __half2 c = sm_hi[(2 * jp + 1) * VT_S + (d >> 1)];
        __half va = (d & 1) ? __high2half(a) : __low2half(a);
        __half vc = (d & 1) ? __high2half(c) : __low2half(c);
        vT_hi[((size_t)bh * HD + d) * (T_SEQ / 2) + j0 / 2 + jp] = __halves2half2(va, vc);
        a = sm_lo[(2 * jp) * VT_S + (d >> 1)];
        c = sm_lo[(2 * jp + 1) * VT_S + (d >> 1)];
        va = (d & 1) ? __high2half(a) : __low2half(a);
        vc = (d & 1) ? __high2half(c) : __low2half(c);
        vT_lo[((size_t)bh * HD + d) * (T_SEQ / 2) + j0 / 2 + jp] = __halves2half2(va, vc);
    }
}

// ---------------------------------------------------------------------------
// Fused RBF attention, fp16-split mma, i-tile = 128, cp.async pipelined j-loop.
// vs double-buffered (V prefetched a full iteration ahead); qs single-buffered
// (Q prefetched after its reads complete, hidden by the S@V phase).
// ---------------------------------------------------------------------------
#define AT_S 36
#define AT_RB (AT_S * 4)       // row stride bytes (144 = 9*16, cp.async-legal)
#define ATT_SMEM_BYTES (768 * AT_S * 4 + 128 * 4 + 64 * 4)
#define LOG4096 8.317766166719343f
#define INV4096 2.44140625e-4f

__global__ __launch_bounds__(256, 2) void attn_h2_kernel(
    const __half* __restrict__ qkv_hi, const __half* __restrict__ qkv_lo,
    const __half2* __restrict__ vT_hi, const __half2* __restrict__ vT_lo,
    const float* __restrict__ rsig,
    __half2* __restrict__ attn_hi, __half2* __restrict__ attn_lo)
{
    extern __shared__ char smraw[];
    __half2* ks_hi = (__half2*)smraw;                 // [128][AT_S]
    __half2* ks_lo = ks_hi + 128 * AT_S;
    __half2* qs_hi = ks_lo + 128 * AT_S;              // [64][AT_S] single buffer
    __half2* qs_lo = qs_hi + 64 * AT_S;
    __half2* vs_hi = qs_lo + 64 * AT_S;               // [2][64][AT_S]
    __half2* vs_lo = vs_hi + 2 * 64 * AT_S;           // [2][64][AT_S]
    __half2* Ss    = vs_lo + 2 * 64 * AT_S;           // [128][AT_S]
    float*   knv   = (float*)(Ss + 128 * AT_S);
    float*   qnv   = knv + 128;

    const int tid   = threadIdx.x;
    const int lane  = tid & 31;
    const int wid   = tid >> 5;
    const int g     = lane >> 2;
    const int tg    = lane & 3;
    const int warpM = wid & 3;        // i: 32 rows each (0..3)
    const int warpN = wid >> 2;       // j/d: 32 cols each (0..1)
    const int bh    = blockIdx.y;
    const int b     = bh / NH;
    const int h     = bh % NH;
    const int i0    = blockIdx.x * 128;
    const float nsig = -rsig[0];

    const uint32_t ksHib = (uint32_t)__cvta_generic_to_shared(ks_hi);
    const uint32_t ksLob = (uint32_t)__cvta_generic_to_shared(ks_lo);
    const uint32_t Ssb   = (uint32_t)__cvta_generic_to_shared(Ss);
    const uint32_t lds_off = ((lane & 7) + (lane & 8)) * AT_RB + (lane & 16);

    const size_t qoff = (size_t)b * T_SEQ * QKV_N + 0 * DIM + h * HD;
    const size_t koff = (size_t)b * T_SEQ * QKV_N + 1 * DIM + h * HD;

    const int lr = tid >> 3;   // 0..31
    const int lc = tid & 7;    // 16B chunk

    auto issue_v = [&](int st, int j0) {
        #pragma unroll
        for (int p = 0; p < 2; p++) {
            int r = lr + p * 32;
            const size_t vbase = ((size_t)bh * HD + r) * (T_SEQ / 2) + j0 / 2;
            cp16(&vs_hi[st * 64 * AT_S + r * AT_S + lc * 4], vT_hi + vbase + lc * 4);
            cp16(&vs_lo[st * 64 * AT_S + r * AT_S + lc * 4], vT_lo + vbase + lc * 4);
        }
        cp_commit();
    };
    auto issue_q = [&](int j0) {
        #pragma unroll
        for (int p = 0; p < 2; p++) {
            int r = lr + p * 32;
            const size_t src = qoff + (size_t)(j0 + r) * QKV_N + lc * 8;
            cp16(&qs_hi[r * AT_S + lc * 4], qkv_hi + src);
            cp16(&qs_lo[r * AT_S + lc * 4], qkv_lo + src);
        }
        cp_commit();
    };

    // ---- load K tile (128 rows) + fused kn (plain loads, once) ----
    {
        float kp[4];
        #pragma unroll
        for (int p = 0; p < 4; p++) {
            int r = lr + p * 32;
            int4 vh = *(const int4*)(qkv_hi + koff + (size_t)(i0 + r) * QKV_N + lc * 8);
            int4 vl = *(const int4*)(qkv_lo + koff + (size_t)(i0 + r) * QKV_N + lc * 8);
            *(int4*)&ks_hi[r * AT_S + lc * 4] = vh;
            *(int4*)&ks_lo[r * AT_S + lc * 4] = vl;
            kp[p] = sumsq8(vh, vl);
        }
        #pragma unroll
        for (int d = 1; d < 8; d <<= 1) {
            #pragma unroll
            for (int p = 0; p < 4; p++)
                kp[p] += __shfl_xor_sync(0xffffffffu, kp[p], d);
        }
        if (lc == 0) {
            #pragma unroll
            for (int p = 0; p < 4; p++) knv[lr + p * 32] = kp[p];
        }
    }

    // ---- prologue prefetch: V(0) into stage 0, Q(0) ----
    issue_v(0, 0);
    issue_q(0);

    float out[2][4][4];
    #pragma unroll
    for (int mt = 0; mt < 2; mt++)
        #pragma unroll
        for (int nt = 0; nt < 4; nt++)
            #pragma unroll
            for (int i = 0; i < 4; i++) out[mt][nt][i] = 0.f;

    const int NT = T_SEQ / 64;
    for (int jt = 0; jt < NT; jt++) {
        cp_wait<0>();          // V(jt) + Q(jt) arrived
        __syncthreads();       // and prior iteration fully done

        // prefetch V(jt+1) into the other stage (reads of it ended last iter)
        if (jt + 1 < NT) issue_v((jt + 1) & 1, (jt + 1) * 64);

        // ---- qn from arrived q tile ----
        {
            float qp[2];
            #pragma unroll
            for (int p = 0; p < 2; p++) {
                int r = lr + p * 32;
                int4 vh = *(const int4*)&qs_hi[r * AT_S + lc * 4];
                int4 vl = *(const int4*)&qs_lo[r * AT_S + lc * 4];
                qp[p] = sumsq8(vh, vl);
            }
            #pragma unroll
            for (int d = 1; d < 8; d <<= 1) {
                qp[0] += __shfl_xor_sync(0xffffffffu, qp[0], d);
                qp[1] += __shfl_xor_sync(0xffffffffu, qp[1], d);
            }
            if (lc == 0) { qnv[lr] = qp[0]; qnv[32 + lr] = qp[1]; }
        }
        __syncthreads();

        // ---- S-mma: dot[i][j] over 64 dims (3-term split) ----
        float sacc[2][4][4];
        #pragma unroll
        for (int mt = 0; mt < 2; mt++)
            #pragma unroll
            for (int nt = 0; nt < 4; nt++)
                #pragma unroll
                for (int i = 0; i < 4; i++) sacc[mt][nt][i] = 0.f;

        #pragma unroll
        for (int kc = 0; kc < 4; kc++) {
            int kp = kc * 8;
            uint32_t bh2[4][2], bl2[4][2];
            #pragma unroll
            for (int nt = 0; nt < 4; nt++) {
                int n0 = warpN * 32 + nt * 8 + g;
                bh2[nt][0] = *(const uint32_t*)&qs_hi[n0 * AT_S + kp + tg];
                bh2[nt][1] = *(const uint32_t*)&qs_hi[n0 * AT_S + kp + tg + 4];
                bl2[nt][0] = *(const uint32_t*)&qs_lo[n0 * AT_S + kp + tg];
                bl2[nt][1] = *(const uint32_t*)&qs_lo[n0 * AT_S + kp + tg + 4];
            }
            #pragma unroll
            for (int mt = 0; mt < 2; mt++) {
                uint32_t rowb = (uint32_t)(warpM * 32 + mt * 16) * AT_RB + kc * 32 + lds_off;
                uint32_t ah[4], al[4];
                ldsm_x4(ah, ksHib + rowb);
                ldsm_x4(al, ksLob + rowb);
                #pragma unroll
                for (int nt = 0; nt < 4; nt++)
                    mma3(sacc[mt][nt], ah, al, bh2[nt], bl2[nt]);
            }
        }

        // ---- exp (scaled by 4096) ----
        float ev[2][4][4];
        #pragma unroll
        for (int mt = 0; mt < 2; mt++) {
            int si = warpM * 32 + mt * 16 + g;
            float kA = knv[si], kB = knv[si + 8];
            #pragma unroll
            for (int nt = 0; nt < 4; nt++) {
                int jj = warpN * 32 + nt * 8 + tg * 2;
                float qA = qnv[jj], qB = qnv[jj + 1];
                ev[mt][nt][0] = __expf(nsig * (kA + qA - 2.f * sacc[mt][nt][0]) + LOG4096);
                ev[mt][nt][1] = __expf(nsig * (kA + qB - 2.f * sacc[mt][nt][1]) + LOG4096);
                ev[mt][nt][2] = __expf(nsig * (kB + qA - 2.f * sacc[mt][nt][2]) + LOG4096);
                ev[mt][nt][3] = __expf(nsig * (kB + qB - 2.f * sacc[mt][nt][3]) + LOG4096);
            }
        }

        // ---- store scaled S (single fp16) into Ss ----
        #pragma unroll
        for (int mt = 0; mt < 2; mt++) {
            int si = warpM * 32 + mt * 16 + g;
            #pragma unroll
            for (int nt = 0; nt < 4; nt++) {
                int jp = warpN * 16 + nt * 4 + tg;
                Ss[si * AT_S + jp]       = __floats2half2_rn(ev[mt][nt][0], ev[mt][nt][1]);
                Ss[(si + 8) * AT_S + jp] = __floats2half2_rn(ev[mt][nt][2], ev[mt][nt][3]);
            }
        }
        __syncthreads();   // S visible; all S-mma reads of qs complete

        // prefetch Q(jt+1) into qs (safe: no more qs reads this iteration)
        if (jt + 1 < NT) issue_q((jt + 1) * 64);

        // ---- out += S @ V  (2-term; S frags via ldmatrix) ----
        const __half2* vsh = vs_hi + (jt & 1) * 64 * AT_S;
        const __half2* vsl = vs_lo + (jt & 1) * 64 * AT_S;
        #pragma unroll
        for (int kc = 0; kc < 4; kc++) {
            int kp = kc * 8;
            uint32_t bh2[4][2], bl2[4][2];
            #pragma unroll
            for (int nt = 0; nt < 4; nt++) {
                int n0 = warpN * 32 + nt * 8 + g;
                bh2[nt][0] = *(const uint32_t*)&vsh[n0 * AT_S + kp + tg];
                bh2[nt][1] = *(const uint32_t*)&vsh[n0 * AT_S + kp + tg + 4];
                bl2[nt][0] = *(const uint32_t*)&vsl[n0 * AT_S + kp + tg];
                bl2[nt][1] = *(const uint32_t*)&vsl[n0 * AT_S + kp + tg + 4];
            }
            #pragma unroll
            for (int mt = 0; mt < 2; mt++) {
                uint32_t rowb = (uint32_t)(warpM * 32 + mt * 16) * AT_RB + kc * 32 + lds_off;
                uint32_t ah[4];
                ldsm_x4(ah, Ssb + rowb);
                #pragma unroll
                for (int nt = 0; nt < 4; nt++) {
                    mma_h(out[mt][nt], ah[0], ah[1], ah[2], ah[3],
                          bh2[nt][0], bh2[nt][1]);
                    mma_h(out[mt][nt], ah[0], ah[1], ah[2], ah[3],
                          bl2[nt][0], bl2[nt][1]);
                }
            }
        }
    }

    // ---- epilogue: unscale, split halves in (b,t,h,d) layout ----
    #pragma unroll
    for (int mt = 0; mt < 2; mt++) {
        #pragma unroll
        for (int nt = 0; nt < 4; nt++) {
            int irow = i0 + warpM * 32 + mt * 16 + g;
            int dcol = warpN * 32 + nt * 8 + tg * 2;
            size_t base = ((size_t)(b * T_SEQ + irow)) * (DIM / 2) + (h * HD + dcol) / 2;
            __half2 hh, ll;
            split2(out[mt][nt][0] * INV4096, out[mt][nt][1] * INV4096, hh, ll);
            attn_hi[base] = hh;
            attn_lo[base] = ll;
            split2(out[mt][nt][2] * INV4096, out[mt][nt][3] * INV4096, hh, ll);
            attn_hi[base + (size_t)8 * (DIM / 2)] = hh;
            attn_lo[base + (size_t)8 * (DIM / 2)] = ll;
        }
    }
}

// ---------------------------------------------------------------------------
extern "C" void kernel_launch(void* const* d_in, const int* in_sizes, int n_in,
                              void* d_out, int out_size)
{
    const float* x     = (const float*)d_in[0];
    const float* Wqkv  = (const float*)d_in[1];
    const float* bqkv  = (const float*)d_in[2];
    const float* rsig  = (const float*)d_in[3];
    const float* Wproj = (const float*)d_in[4];
    const float* bproj = (const float*)d_in[5];
    float* out = (float*)d_out;

    __half *x_hi, *x_lo, *qkv_hi, *qkv_lo, *attn_hi, *attn_lo;
    __half2 *wqkv_hi, *wqkv_lo, *wproj_hi, *wproj_lo, *vT_hi, *vT_lo;
    cudaGetSymbolAddress((void**)&x_hi, g_x_hi);
    cudaGetSymbolAddress((void**)&x_lo, g_x_lo);
    cudaGetSymbolAddress((void**)&wqkv_hi, g_wqkv_hi);
    cudaGetSymbolAddress((void**)&wqkv_lo, g_wqkv_lo);
    cudaGetSymbolAddress((void**)&wproj_hi, g_wproj_hi);
    cudaGetSymbolAddress((void**)&wproj_lo, g_wproj_lo);
    cudaGetSymbolAddress((void**)&qkv_hi, g_qkv_hi);
    cudaGetSymbolAddress((void**)&qkv_lo, g_qkv_lo);
    cudaGetSymbolAddress((void**)&vT_hi, g_vT_hi);
    cudaGetSymbolAddress((void**)&vT_lo, g_vT_lo);
    cudaGetSymbolAddress((void**)&attn_hi, g_attn_hi);
    cudaGetSymbolAddress((void**)&attn_lo, g_attn_lo);

    cudaFuncSetAttribute(attn_h2_kernel,
                         cudaFuncAttributeMaxDynamicSharedMemorySize, ATT_SMEM_BYTES);
    cudaFuncSetAttribute(gemm_h2_kernel<true>,
                         cudaFuncAttributeMaxDynamicSharedMemorySize, G_SMEM_BYTES);
    cudaFuncSetAttribute(gemm_h2_kernel<false>,
                         cudaFuncAttributeMaxDynamicSharedMemorySize, G_SMEM_BYTES);

    // prep: split x, pack weights
    {
        int n4 = ROWS * CDIM / 4;
        split_kernel<<<(n4 + 255) / 256, 256>>>(x, (__half2*)x_hi, (__half2*)x_lo, n4);
        int tq = (CDIM / 2) * (QKV_N / 4);
        pack_w_kernel<<<(tq + 255) / 256, 256>>>(Wqkv, wqkv_hi, wqkv_lo, CDIM, QKV_N);
        int tp = (DIM / 2) * (CDIM / 4);
        pack_w_kernel<<<(tp + 255) / 256, 256>>>(Wproj, wproj_hi, wproj_lo, DIM, CDIM);
    }
    // stage 1: qkv (split output)
    {
        dim3 grid(QKV_N / 128, ROWS / 128);
        gemm_h2_kernel<true><<<grid, 256, G_SMEM_BYTES>>>(
            x_hi, x_lo, wqkv_hi, wqkv_lo, bqkv,
            nullptr, (__half2*)qkv_hi, (__half2*)qkv_lo, ROWS, QKV_N, CDIM);
    }
    // repack V
    {
        dim3 grid(T_SEQ / 64, BATCH * NH);
        repack_v_kernel<<<grid, 256>>>(qkv_hi, qkv_lo, vT_hi, vT_lo);
    }
    // stage 2: attention (i-tile 128, pipelined)
    {
        dim3 grid(T_SEQ / 128, BATCH * NH);
        attn_h2_kernel<<<grid, 256, ATT_SMEM_BYTES>>>(qkv_hi, qkv_lo, vT_hi, vT_lo,
                                                      rsig,
                                                      (__half2*)attn_hi, (__half2*)attn_lo);
    }
    // stage 3: out
    {
        dim3 grid(CDIM / 128, ROWS / 128);
        gemm_h2_kernel<false><<<grid, 256, G_SMEM_BYTES>>>(
            attn_hi, attn_lo, wproj_hi, wproj_lo, bproj,
            out, nullptr, nullptr, ROWS, CDIM, DIM);
    }
}

// round 11
// speedup vs baseline: 3.6056x; 1.1090x over previous
#include <cuda_runtime.h>
#include <cuda_fp16.h>
#include <cstdint>
#include <cstddef>

// Problem constants
#define BATCH   2
#define T_SEQ   2048
#define CDIM    1024
#define DIM     1024
#define NH      16
#define HD      64
#define QKV_N   3072
#define ROWS    (BATCH*T_SEQ)

// ---------------------------------------------------------------------------
// Device scratch (allocation-free rule). All 16B aligned.
// ---------------------------------------------------------------------------
__device__ __align__(16) __half g_x_hi[ROWS * CDIM];
__device__ __align__(16) __half g_x_lo[ROWS * CDIM];
__device__ __align__(16) __half2 g_wqkv_hi[(CDIM/2) * QKV_N];  // [K/2][N] k-pair packed
__device__ __align__(16) __half2 g_wqkv_lo[(CDIM/2) * QKV_N];
__device__ __align__(16) __half2 g_wproj_hi[(DIM/2) * CDIM];
__device__ __align__(16) __half2 g_wproj_lo[(DIM/2) * CDIM];
__device__ __align__(16) __half g_qkv_hi[ROWS * QKV_N];
__device__ __align__(16) __half g_qkv_lo[ROWS * QKV_N];
__device__ __align__(16) __half2 g_vT_hi[BATCH*NH * HD * (T_SEQ/2)]; // [bh][d][T/2]
__device__ __align__(16) __half2 g_vT_lo[BATCH*NH * HD * (T_SEQ/2)];
__device__ __align__(16) __half g_attn_hi[ROWS * DIM];

// ---------------------------------------------------------------------------
// helpers
// ---------------------------------------------------------------------------
__device__ __forceinline__ void split_h(float x, __half& hi, __half& lo) {
    hi = __float2half_rn(x);
    lo = __float2half_rn(x - __half2float(hi));
}
__device__ __forceinline__ void split2(float a, float b, __half2& h, __half2& l) {
    __half ha, la, hb, lb;
    split_h(a, ha, la);
    split_h(b, hb, lb);
    h = __halves2half2(ha, hb);
    l = __halves2half2(la, lb);
}

__device__ __forceinline__ void mma_h(float* d,
    uint32_t a0, uint32_t a1, uint32_t a2, uint32_t a3,
    uint32_t b0, uint32_t b1)
{
    asm volatile(
        "mma.sync.aligned.m16n8k16.row.col.f32.f16.f16.f32 "
        "{%0,%1,%2,%3}, {%4,%5,%6,%7}, {%8,%9}, {%0,%1,%2,%3};\n"
        : "+f"(d[0]), "+f"(d[1]), "+f"(d[2]), "+f"(d[3])
        : "r"(a0), "r"(a1), "r"(a2), "r"(a3), "r"(b0), "r"(b1));
}
// hi*hi + hi*lo + lo*hi
__device__ __forceinline__ void mma3(float* d,
    const uint32_t ah[4], const uint32_t al[4],
    const uint32_t bh[2], const uint32_t bl[2])
{
    mma_h(d, ah[0], ah[1], ah[2], ah[3], bh[0], bh[1]);
    mma_h(d, ah[0], ah[1], ah[2], ah[3], bl[0], bl[1]);
    mma_h(d, al[0], al[1], al[2], al[3], bh[0], bh[1]);
}

__device__ __forceinline__ void ldsm_x4(uint32_t* r, uint32_t addr) {
    asm volatile("ldmatrix.sync.aligned.m8n8.x4.shared.b16 {%0,%1,%2,%3}, [%4];"
        : "=r"(r[0]), "=r"(r[1]), "=r"(r[2]), "=r"(r[3]) : "r"(addr));
}

__device__ __forceinline__ void cp16(void* dst, const void* src) {
    uint32_t d = (uint32_t)__cvta_generic_to_shared(dst);
    asm volatile("cp.async.cg.shared.global [%0], [%1], 16;\n" :: "r"(d), "l"(src));
}
__device__ __forceinline__ void cp_commit() { asm volatile("cp.async.commit_group;\n"); }
template<int N> __device__ __forceinline__ void cp_wait() {
    asm volatile("cp.async.wait_group %0;\n" :: "n"(N));
}

// sum of squares of 8 split halves
__device__ __forceinline__ float sumsq8(int4 hbits, int4 lbits) {
    const __half2* h = (const __half2*)&hbits;
    const __half2* l = (const __half2*)&lbits;
    float s = 0.f;
    #pragma unroll
    for (int i = 0; i < 4; i++) {
        float2 a = __half22float2(h[i]);
        float2 b = __half22float2(l[i]);
        float x = a.x + b.x, y = a.y + b.y;
        s += x * x + y * y;
    }
    return s;
}

// ---------------------------------------------------------------------------
// Prep kernels
// ---------------------------------------------------------------------------
__global__ void split_kernel(const float* __restrict__ src,
                             __half2* __restrict__ hi, __half2* __restrict__ lo,
                             int n4)
{
    int i = blockIdx.x * blockDim.x + threadIdx.x;
    if (i >= n4) return;
    float4 v = *(const float4*)(src + (size_t)i * 4);
    __half2 h0, l0, h1, l1;
    split2(v.x, v.y, h0, l0);
    split2(v.z, v.w, h1, l1);
    hi[(size_t)i * 2]     = h0;
    hi[(size_t)i * 2 + 1] = h1;
    lo[(size_t)i * 2]     = l0;
    lo[(size_t)i * 2 + 1] = l1;
}

// Pack weights: W[K][N] fp32 -> [K/2][N] half2 (k-pair in one half2)
__global__ void pack_w_kernel(const float* __restrict__ W,
                              __half2* __restrict__ hi, __half2* __restrict__ lo,
                              int K, int N)
{
    int idx = blockIdx.x * blockDim.x + threadIdx.x;
    int total = (K / 2) * (N / 4);
    if (idx >= total) return;
    int kp = idx / (N / 4);
    int n4 = (idx % (N / 4)) * 4;
    float4 r0 = *(const float4*)(W + (size_t)(2 * kp) * N + n4);
    float4 r1 = *(const float4*)(W + (size_t)(2 * kp + 1) * N + n4);
    const float a[4] = {r0.x, r0.y, r0.z, r0.w};
    const float b[4] = {r1.x, r1.y, r1.z, r1.w};
    #pragma unroll
    for (int t = 0; t < 4; t++) {
        __half h0, l0, h1, l1;
        split_h(a[t], h0, l0);
        split_h(b[t], h1, l1);
        hi[(size_t)kp * N + n4 + t] = __halves2half2(h0, h1);
        lo[(size_t)kp * N + n4 + t] = __halves2half2(l0, l1);
    }
}

// ---------------------------------------------------------------------------
// GEMM: C[M,N] = A @ W[K,N] + bias, fp16 split mma.
// TERMS=3: (Ahi+Alo) full 3-term.  TERMS=2: Ahi only (Ah*Bh + Ah*Bl).
// BM=128 BN=128 BK=32, 8 warps (2x4), warp tile 64x32.
// 3-stage cp.async ring; A frags via ldmatrix.x4.
// ---------------------------------------------------------------------------
#define AS_S 20     // half2 stride per m-row (16 used + 4 pad) = 80B
#define BS_S 132    // half2 stride per kp-row (128 used + 4 pad) = 528B
#define A_H2 (128 * AS_S)
#define B_H2 (16 * BS_S)
#define STG_H2 (2 * A_H2 + 2 * B_H2)
#define G_SMEM_BYTES (3 * STG_H2 * 4)

template<bool SPLIT_OUT, int TERMS>
__global__ __launch_bounds__(256, 2) void gemm_h2_kernel(
    const __half* __restrict__ Ahi, const __half* __restrict__ Alo,
    const __half2* __restrict__ Bhi, const __half2* __restrict__ Blo,
    const float* __restrict__ bias,
    float* __restrict__ Cf, __half2* __restrict__ Chi, __half2* __restrict__ Clo,
    int M, int N, int K)
{
    extern __shared__ __half2 smg[];

    const int tid   = threadIdx.x;
    const int lane  = tid & 31;
    const int wid   = tid >> 5;
    const int g     = lane >> 2;
    const int tg    = lane & 3;
    const int warpM = wid >> 2;
    const int warpN = wid & 3;
    const int rowBase = blockIdx.y * 128;
    const int colBase = blockIdx.x * 128;
    const uint32_t sbase = (uint32_t)__cvta_generic_to_shared(smg);

    const uint32_t lds_off = ((lane & 7) + (lane & 8)) * (AS_S * 4) + (lane & 16);

    float acc[4][4][4];
    #pragma unroll
    for (int mt = 0; mt < 4; mt++)
        #pragma unroll
        for (int nt = 0; nt < 4; nt++)
            #pragma unroll
            for (int i = 0; i < 4; i++) acc[mt][nt][i] = 0.f;

    const int NT = K / 32;

    auto issue = [&](int st, int kt) {
        __half2* S = smg + st * STG_H2;
        #pragma unroll
        for (int l = 0; l < 2; l++) {
            int id = tid + l * 256;
            int ar = id >> 2, ac = id & 3;
            const size_t src = (size_t)(rowBase + ar) * K + kt + ac * 8;
            cp16(&S[ar * AS_S + ac * 4], Ahi + src);
            if (TERMS == 3)
                cp16(&S[A_H2 + ar * AS_S + ac * 4], Alo + src);
        }
        #pragma unroll
        for (int l = 0; l < 2; l++) {
            int id = tid + l * 256;
            int br = id >> 5, bc = id & 31;
            const size_t src = (size_t)((kt >> 1) + br) * N + colBase + bc * 4;
            cp16(&S[2 * A_H2 + br * BS_S + bc * 4], Bhi + src);
            cp16(&S[2 * A_H2 + B_H2 + br * BS_S + bc * 4], Blo + src);
        }
        cp_commit();
    };

    issue(0, 0);
    issue(1, 32);

    for (int t = 0; t < NT; t++) {
        if (t + 1 < NT) cp_wait<1>(); else cp_wait<0>();
        __syncthreads();
        if (t + 2 < NT) issue((t + 2) % 3, (t + 2) * 32);

        const uint32_t stg = sbase + (uint32_t)((t % 3) * STG_H2) * 4u;
        const uint32_t aHb = stg + lds_off + (uint32_t)(warpM * 64) * (AS_S * 4);
        const uint32_t aLb = aHb + (uint32_t)A_H2 * 4u;
        const __half2* S = smg + (t % 3) * STG_H2;
        const __half2* Bh = S + 2 * A_H2;
        const __half2* Bl = S + 2 * A_H2 + B_H2;

        #pragma unroll
        for (int kk = 0; kk < 32; kk += 16) {
            const int kpr = kk >> 1;
            uint32_t bh[4][2], bl[4][2];
            #pragma unroll
            for (int nt = 0; nt < 4; nt++) {
                int n0 = warpN * 32 + nt * 8 + g;
                bh[nt][0] = *(const uint32_t*)&Bh[(kpr + tg) * BS_S + n0];
                bh[nt][1] = *(const uint32_t*)&Bh[(kpr + tg + 4) * BS_S + n0];
                bl[nt][0] = *(const uint32_t*)&Bl[(kpr + tg) * BS_S + n0];
                bl[nt][1] = *(const uint32_t*)&Bl[(kpr + tg + 4) * BS_S + n0];
            }
            #pragma unroll
            for (int mt = 0; mt < 4; mt++) {
                uint32_t off = (uint32_t)(mt * 16) * (AS_S * 4) + kk * 2;
                uint32_t ah[4], al[4];
                ldsm_x4(ah, aHb + off);
                if (TERMS == 3) ldsm_x4(al, aLb + off);
                #pragma unroll
                for (int nt = 0; nt < 4; nt++) {
                    if (TERMS == 3) {
                        mma3(acc[mt][nt], ah, al, bh[nt], bl[nt]);
                    } else {
                        mma_h(acc[mt][nt], ah[0], ah[1], ah[2], ah[3],
                              bh[nt][0], bh[nt][1]);
                        mma_h(acc[mt][nt], ah[0], ah[1], ah[2], ah[3],
                              bl[nt][0], bl[nt][1]);
                    }
                }
            }
        }
    }

    // epilogue
    #pragma unroll
    for (int mt = 0; mt < 4; mt++) {
        #pragma unroll
        for (int nt = 0; nt < 4; nt++) {
            int r0 = rowBase + warpM * 64 + mt * 16 + g;
            int c0 = colBase + warpN * 32 + nt * 8 + tg * 2;
            float bz0 = bias[c0], bz1 = bias[c0 + 1];
            float v0 = acc[mt][nt][0] + bz0, v1 = acc[mt][nt][1] + bz1;
            float v2 = acc[mt][nt][2] + bz0, v3 = acc[mt][nt][3] + bz1;
            if (SPLIT_OUT) {
                __half2 h, l;
                split2(v0, v1, h, l);
                Chi[(size_t)r0 * (N / 2) + c0 / 2] = h;
                Clo[(size_t)r0 * (N / 2) + c0 / 2] = l;
                split2(v2, v3, h, l);
                Chi[(size_t)(r0 + 8) * (N / 2) + c0 / 2] = h;
                Clo[(size_t)(r0 + 8) * (N / 2) + c0 / 2] = l;
            } else {
                *(float2*)&Cf[(size_t)r0 * N + c0] = make_float2(v0, v1);
                *(float2*)&Cf[(size_t)(r0 + 8) * N + c0] = make_float2(v2, v3);
            }
        }
    }
}

// ---------------------------------------------------------------------------
// Repack V: qkv v-region [row][d] halves -> vT [bh][d][T/2] half2 (j-pairs)
// ---------------------------------------------------------------------------
#define VT_S 36
__global__ __launch_bounds__(256) void repack_v_kernel(
    const __half* __restrict__ qkv_hi, const __half* __restrict__ qkv_lo,
    __half2* __restrict__ vT_hi, __half2* __restrict__ vT_lo)
{
    __shared__ __half2 sm_hi[64 * VT_S];
    __shared__ __half2 sm_lo[64 * VT_S];
    const int tid = threadIdx.x;
    const int bh  = blockIdx.y;
    const int b   = bh / NH;
    const int h   = bh % NH;
    const int j0  = blockIdx.x * 64;

    const size_t base = ((size_t)(b * T_SEQ + j0)) * QKV_N + 2 * DIM + h * HD;
    #pragma unroll
    for (int l = 0; l < 2; l++) {
        int id = tid + l * 256;
        int r  = id >> 3;
        int c  = id & 7;
        *(int4*)&sm_hi[r * VT_S + c * 4] = *(const int4*)(qkv_hi + base + (size_t)r * QKV_N + c * 8);
        *(int4*)&sm_lo[r * VT_S + c * 4] = *(const int4*)(qkv_lo + base + (size_t)r * QKV_N + c * 8);
    }
    __syncthreads();
    #pragma unroll
    for (int l = 0; l < 8; l++) {
        int id = tid + l * 256;
        int d  = id >> 5;
        int jp = id & 31;
        __half2 a = sm_hi[(2 * jp) * VT_S + (d >> 1)];
        __half2 c = sm_hi[(2 * jp + 1) * VT_S + (d >> 1)];
        __half va = (d & 1) ? __high2half(a) : __low2half(a);
        __half vc = (d & 1) ? __high2half(c) : __low2half(c);
        vT_hi[((size_t)bh * HD + d) * (T_SEQ / 2) + j0 / 2 + jp] = __halves2half2(va, vc);
        a = sm_lo[(2 * jp) * VT_S + (d >> 1)];
        c = sm_lo[(2 * jp + 1) * VT_S + (d >> 1)];
        va = (d & 1) ? __high2half(a) : __low2half(a);
        vc = (d & 1) ? __high2half(c) : __low2half(c);
        vT_lo[((size_t)bh * HD + d) * (T_SEQ / 2) + j0 / 2 + jp] = __halves2half2(va, vc);
    }
}

// ---------------------------------------------------------------------------
// Fused RBF attention, fp16-split mma, i-tile = 128, pipelined j-loop.
// S-mma 2-term (k_hi*q_hi + k_hi*q_lo); S@V 2-term. fp16 output (no split).
// ---------------------------------------------------------------------------
#define AT_S 36
#define AT_RB (AT_S * 4)       // row stride bytes (144 = 9*16)
#define ATT_SMEM_BYTES (640 * AT_S * 4 + 128 * 4 + 64 * 4)
#define LOG4096 8.317766166719343f
#define INV4096 2.44140625e-4f

__global__ __launch_bounds__(256, 2) void attn_h2_kernel(
    const __half* __restrict__ qkv_hi, const __half* __restrict__ qkv_lo,
    const __half2* __restrict__ vT_hi, const __half2* __restrict__ vT_lo,
    const float* __restrict__ rsig,
    __half2* __restrict__ attn_hi)
{
    extern __shared__ char smraw[];
    __half2* ks_hi = (__half2*)smraw;                 // [128][AT_S]
    __half2* qs_hi = ks_hi + 128 * AT_S;              // [64][AT_S]
    __half2* qs_lo = qs_hi + 64 * AT_S;
    __half2* vs_hi = qs_lo + 64 * AT_S;               // [2][64][AT_S]
    __half2* vs_lo = vs_hi + 2 * 64 * AT_S;           // [2][64][AT_S]
    __half2* Ss    = vs_lo + 2 * 64 * AT_S;           // [128][AT_S]
    float*   knv   = (float*)(Ss + 128 * AT_S);
    float*   qnv   = knv + 128;

    const int tid   = threadIdx.x;
    const int lane  = tid & 31;
    const int wid   = tid >> 5;
    const int g     = lane >> 2;
    const int tg    = lane & 3;
    const int warpM = wid & 3;        // i: 32 rows each (0..3)
    const int warpN = wid >> 2;       // j/d: 32 cols each (0..1)
    const int bh    = blockIdx.y;
    const int b     = bh / NH;
    const int h     = bh % NH;
    const int i0    = blockIdx.x * 128;
    const float nsig = -rsig[0];

    const uint32_t ksHib = (uint32_t)__cvta_generic_to_shared(ks_hi);
    const uint32_t Ssb   = (uint32_t)__cvta_generic_to_shared(Ss);
    const uint32_t lds_off = ((lane & 7) + (lane & 8)) * AT_RB + (lane & 16);

    const size_t qoff = (size_t)b * T_SEQ * QKV_N + 0 * DIM + h * HD;
    const size_t koff = (size_t)b * T_SEQ * QKV_N + 1 * DIM + h * HD;

    const int lr = tid >> 3;   // 0..31
    const int lc = tid & 7;    // 16B chunk

    auto issue_v = [&](int st, int j0) {
        #pragma unroll
        for (int p = 0; p < 2; p++) {
            int r = lr + p * 32;
            const size_t vbase = ((size_t)bh * HD + r) * (T_SEQ / 2) + j0 / 2;
            cp16(&vs_hi[st * 64 * AT_S + r * AT_S + lc * 4], vT_hi + vbase + lc * 4);
            cp16(&vs_lo[st * 64 * AT_S + r * AT_S + lc * 4], vT_lo + vbase + lc * 4);
        }
        cp_commit();
    };
    auto issue_q = [&](int j0) {
        #pragma unroll
        for (int p = 0; p < 2; p++) {
            int r = lr + p * 32;
            const size_t src = qoff + (size_t)(j0 + r) * QKV_N + lc * 8;
            cp16(&qs_hi[r * AT_S + lc * 4], qkv_hi + src);
            cp16(&qs_lo[r * AT_S + lc * 4], qkv_lo + src);
        }
        cp_commit();
    };

    // ---- load K tile (128 rows, hi only in smem) + fused kn ----
    {
        float kp[4];
        #pragma unroll
        for (int p = 0; p < 4; p++) {
            int r = lr + p * 32;
            int4 vh = *(const int4*)(qkv_hi + koff + (size_t)(i0 + r) * QKV_N + lc * 8);
            int4 vl = *(const int4*)(qkv_lo + koff + (size_t)(i0 + r) * QKV_N + lc * 8);
            *(int4*)&ks_hi[r * AT_S + lc * 4] = vh;
            kp[p] = sumsq8(vh, vl);
        }
        #pragma unroll
        for (int d = 1; d < 8; d <<= 1) {
            #pragma unroll
            for (int p = 0; p < 4; p++)
                kp[p] += __shfl_xor_sync(0xffffffffu, kp[p], d);
        }
        if (lc == 0) {
            #pragma unroll
            for (int p = 0; p < 4; p++) knv[lr + p * 32] = kp[p];
        }
    }

    // ---- prologue prefetch: V(0) into stage 0, Q(0) ----
    issue_v(0, 0);
    issue_q(0);

    float out[2][4][4];
    #pragma unroll
    for (int mt = 0; mt < 2; mt++)
        #pragma unroll
        for (int nt = 0; nt < 4; nt++)
            #pragma unroll
            for (int i = 0; i < 4; i++) out[mt][nt][i] = 0.f;

    const int NT = T_SEQ / 64;
    for (int jt = 0; jt < NT; jt++) {
        cp_wait<0>();          // V(jt) + Q(jt) arrived
        __syncthreads();       // and prior iteration fully done

        if (jt + 1 < NT) issue_v((jt + 1) & 1, (jt + 1) * 64);

        // ---- qn from arrived q tile ----
        {
            float qp[2];
            #pragma unroll
            for (int p = 0; p < 2; p++) {
                int r = lr + p * 32;
                int4 vh = *(const int4*)&qs_hi[r * AT_S + lc * 4];
                int4 vl = *(const int4*)&qs_lo[r * AT_S + lc * 4];
                qp[p] = sumsq8(vh, vl);
            }
            #pragma unroll
            for (int d = 1; d < 8; d <<= 1) {
                qp[0] += __shfl_xor_sync(0xffffffffu, qp[0], d);
                qp[1] += __shfl_xor_sync(0xffffffffu, qp[1], d);
            }
            if (lc == 0) { qnv[lr] = qp[0]; qnv[32 + lr] = qp[1]; }
        }
        __syncthreads();

        // ---- S-mma: 2-term (k_hi*q_hi + k_hi*q_lo) ----
        float sacc[2][4][4];
        #pragma unroll
        for (int mt = 0; mt < 2; mt++)
            #pragma unroll
            for (int nt = 0; nt < 4; nt++)
                #pragma unroll
                for (int i = 0; i < 4; i++) sacc[mt][nt][i] = 0.f;

        #pragma unroll
        for (int kc = 0; kc < 4; kc++) {
            int kp = kc * 8;
            uint32_t bh2[4][2], bl2[4][2];
            #pragma unroll
            for (int nt = 0; nt < 4; nt++) {
                int n0 = warpN * 32 + nt * 8 + g;
                bh2[nt][0] = *(const uint32_t*)&qs_hi[n0 * AT_S + kp + tg];
                bh2[nt][1] = *(const uint32_t*)&qs_hi[n0 * AT_S + kp + tg + 4];
                bl2[nt][0] = *(const uint32_t*)&qs_lo[n0 * AT_S + kp + tg];
                bl2[nt][1] = *(const uint32_t*)&qs_lo[n0 * AT_S + kp + tg + 4];
            }
            #pragma unroll
            for (int mt = 0; mt < 2; mt++) {
                uint32_t rowb = (uint32_t)(warpM * 32 + mt * 16) * AT_RB + kc * 32 + lds_off;
                uint32_t ah[4];
                ldsm_x4(ah, ksHib + rowb);
                #pragma unroll
                for (int nt = 0; nt < 4; nt++) {
                    mma_h(sacc[mt][nt], ah[0], ah[1], ah[2], ah[3],
                          bh2[nt][0], bh2[nt][1]);
                    mma_h(sacc[mt][nt], ah[0], ah[1], ah[2], ah[3],
                          bl2[nt][0], bl2[nt][1]);
                }
            }
        }

        // ---- exp (scaled by 4096) ----
        float ev[2][4][4];
        #pragma unroll
        for (int mt = 0; mt < 2; mt++) {
            int si = warpM * 32 + mt * 16 + g;
            float kA = knv[si], kB = knv[si + 8];
            #pragma unroll
            for (int nt = 0; nt < 4; nt++) {
                int jj = warpN * 32 + nt * 8 + tg * 2;
                float qA = qnv[jj], qB = qnv[jj + 1];
                ev[mt][nt][0] = __expf(nsig * (kA + qA - 2.f * sacc[mt][nt][0]) + LOG4096);
                ev[mt][nt][1] = __expf(nsig * (kA + qB - 2.f * sacc[mt][nt][1]) + LOG4096);
                ev[mt][nt][2] = __expf(nsig * (kB + qA - 2.f * sacc[mt][nt][2]) + LOG4096);
                ev[mt][nt][3] = __expf(nsig * (kB + qB - 2.f * sacc[mt][nt][3]) + LOG4096);
            }
        }

        // ---- store scaled S (single fp16) into Ss ----
        #pragma unroll
        for (int mt = 0; mt < 2; mt++) {
            int si = warpM * 32 + mt * 16 + g;
            #pragma unroll
            for (int nt = 0; nt < 4; nt++) {
                int jp = warpN * 16 + nt * 4 + tg;
                Ss[si * AT_S + jp]       = __floats2half2_rn(ev[mt][nt][0], ev[mt][nt][1]);
                Ss[(si + 8) * AT_S + jp] = __floats2half2_rn(ev[mt][nt][2], ev[mt][nt][3]);
            }
        }
        __syncthreads();   // S visible; all S-mma reads of qs complete

        if (jt + 1 < NT) issue_q((jt + 1) * 64);

        // ---- out += S @ V  (2-term) ----
        const __half2* vsh = vs_hi + (jt & 1) * 64 * AT_S;
        const __half2* vsl = vs_lo + (jt & 1) * 64 * AT_S;
        #pragma unroll
        for (int kc = 0; kc < 4; kc++) {
            int kp = kc * 8;
            uint32_t bh2[4][2], bl2[4][2];
            #pragma unroll
            for (int nt = 0; nt < 4; nt++) {
                int n0 = warpN * 32 + nt * 8 + g;
                bh2[nt][0] = *(const uint32_t*)&vsh[n0 * AT_S + kp + tg];
                bh2[nt][1] = *(const uint32_t*)&vsh[n0 * AT_S + kp + tg + 4];
                bl2[nt][0] = *(const uint32_t*)&vsl[n0 * AT_S + kp + tg];
                bl2[nt][1] = *(const uint32_t*)&vsl[n0 * AT_S + kp + tg + 4];
            }
            #pragma unroll
            for (int mt = 0; mt < 2; mt++) {
                uint32_t rowb = (uint32_t)(warpM * 32 + mt * 16) * AT_RB + kc * 32 + lds_off;
                uint32_t ah[4];
                ldsm_x4(ah, Ssb + rowb);
                #pragma unroll
                for (int nt = 0; nt < 4; nt++) {
                    mma_h(out[mt][nt], ah[0], ah[1], ah[2], ah[3],
                          bh2[nt][0], bh2[nt][1]);
                    mma_h(out[mt][nt], ah[0], ah[1], ah[2], ah[3],
                          bl2[nt][0], bl2[nt][1]);
                }
            }
        }
    }

    // ---- epilogue: unscale, plain fp16 in (b,t,h,d) layout ----
    #pragma unroll
    for (int mt = 0; mt < 2; mt++) {
        #pragma unroll
        for (int nt = 0; nt < 4; nt++) {
            int irow = i0 + warpM * 32 + mt * 16 + g;
            int dcol = warpN * 32 + nt * 8 + tg * 2;
            size_t base = ((size_t)(b * T_SEQ + irow)) * (DIM / 2) + (h * HD + dcol) / 2;
            attn_hi[base] =
                __floats2half2_rn(out[mt][nt][0] * INV4096, out[mt][nt][1] * INV4096);
            attn_hi[base + (size_t)8 * (DIM / 2)] =
                __floats2half2_rn(out[mt][nt][2] * INV4096, out[mt][nt][3] * INV4096);
        }
    }
}

// ---------------------------------------------------------------------------
extern "C" void kernel_launch(void* const* d_in, const int* in_sizes, int n_in,
                              void* d_out, int out_size)
{
    const float* x     = (const float*)d_in[0];
    const float* Wqkv  = (const float*)d_in[1];
    const float* bqkv  = (const float*)d_in[2];
    const float* rsig  = (const float*)d_in[3];
    const float* Wproj = (const float*)d_in[4];
    const float* bproj = (const float*)d_in[5];
    float* out = (float*)d_out;

    __half *x_hi, *x_lo, *qkv_hi, *qkv_lo, *attn_hi;
    __half2 *wqkv_hi, *wqkv_lo, *wproj_hi, *wproj_lo, *vT_hi, *vT_lo;
    cudaGetSymbolAddress((void**)&x_hi, g_x_hi);
    cudaGetSymbolAddress((void**)&x_lo, g_x_lo);
    cudaGetSymbolAddress((void**)&wqkv_hi, g_wqkv_hi);
    cudaGetSymbolAddress((void**)&wqkv_lo, g_wqkv_lo);
    cudaGetSymbolAddress((void**)&wproj_hi, g_wproj_hi);
    cudaGetSymbolAddress((void**)&wproj_lo, g_wproj_lo);
    cudaGetSymbolAddress((void**)&qkv_hi, g_qkv_hi);
    cudaGetSymbolAddress((void**)&qkv_lo, g_qkv_lo);
    cudaGetSymbolAddress((void**)&vT_hi, g_vT_hi);
    cudaGetSymbolAddress((void**)&vT_lo, g_vT_lo);
    cudaGetSymbolAddress((void**)&attn_hi, g_attn_hi);

    cudaFuncSetAttribute(attn_h2_kernel,
                         cudaFuncAttributeMaxDynamicSharedMemorySize, ATT_SMEM_BYTES);
    cudaFuncSetAttribute(gemm_h2_kernel<true, 3>,
                         cudaFuncAttributeMaxDynamicSharedMemorySize, G_SMEM_BYTES);
    cudaFuncSetAttribute(gemm_h2_kernel<false, 2>,
                         cudaFuncAttributeMaxDynamicSharedMemorySize, G_SMEM_BYTES);

    // prep: split x, pack weights
    {
        int n4 = ROWS * CDIM / 4;
        split_kernel<<<(n4 + 255) / 256, 256>>>(x, (__half2*)x_hi, (__half2*)x_lo, n4);
        int tq = (CDIM / 2) * (QKV_N / 4);
        pack_w_kernel<<<(tq + 255) / 256, 256>>>(Wqkv, wqkv_hi, wqkv_lo, CDIM, QKV_N);
        int tp = (DIM / 2) * (CDIM / 4);
        pack_w_kernel<<<(tp + 255) / 256, 256>>>(Wproj, wproj_hi, wproj_lo, DIM, CDIM);
    }
    // stage 1: qkv (split output, 3-term)
    {
        dim3 grid(QKV_N / 128, ROWS / 128);
        gemm_h2_kernel<true, 3><<<grid, 256, G_SMEM_BYTES>>>(
            x_hi, x_lo, wqkv_hi, wqkv_lo, bqkv,
            nullptr, (__half2*)qkv_hi, (__half2*)qkv_lo, ROWS, QKV_N, CDIM);
    }
    // repack V
    {
        dim3 grid(T_SEQ / 64, BATCH * NH);
        repack_v_kernel<<<grid, 256>>>(qkv_hi, qkv_lo, vT_hi, vT_lo);
    }
    // stage 2: attention (i-tile 128, pipelined, fp16 out)
    {
        dim3 grid(T_SEQ / 128, BATCH * NH);
        attn_h2_kernel<<<grid, 256, ATT_SMEM_BYTES>>>(qkv_hi, qkv_lo, vT_hi, vT_lo,
                                                      rsig, (__half2*)attn_hi);
    }
    // stage 3: out (2-term, A = attn_hi only)
    {
        dim3 grid(CDIM / 128, ROWS / 128);
        gemm_h2_kernel<false, 2><<<grid, 256, G_SMEM_BYTES>>>(
            attn_hi, nullptr, wproj_hi, wproj_lo, bproj,
            out, nullptr, nullptr, ROWS, CDIM, DIM);
    }
}

// round 12
// speedup vs baseline: 3.9297x; 1.0899x over previous
#include <cuda_runtime.h>
#include <cuda_fp16.h>
#include <cstdint>
#include <cstddef>

// Problem constants
#define BATCH   2
#define T_SEQ   2048
#define CDIM    1024
#define DIM     1024
#define NH      16
#define HD      64
#define QKV_N   3072
#define ROWS    (BATCH*T_SEQ)

// ---------------------------------------------------------------------------
// Device scratch (allocation-free rule). All 16B aligned.
// ---------------------------------------------------------------------------
__device__ __align__(16) __half g_x_hi[ROWS * CDIM];
__device__ __align__(16) __half g_x_lo[ROWS * CDIM];
__device__ __align__(16) __half2 g_wqkv_hi[(CDIM/2) * QKV_N];  // [K/2][N] k-pair packed
__device__ __align__(16) __half2 g_wqkv_lo[(CDIM/2) * QKV_N];
__device__ __align__(16) __half2 g_wproj_hi[(DIM/2) * CDIM];
__device__ __align__(16) __half2 g_wproj_lo[(DIM/2) * CDIM];
__device__ __align__(16) __half g_qkv_hi[ROWS * QKV_N];
__device__ __align__(16) __half g_qkv_lo[ROWS * QKV_N];
__device__ __align__(16) __half2 g_vT_hi[BATCH*NH * HD * (T_SEQ/2)]; // [bh][d][T/2]
__device__ __align__(16) __half g_attn_hi[ROWS * DIM];

// ---------------------------------------------------------------------------
// helpers
// ---------------------------------------------------------------------------
__device__ __forceinline__ void split_h(float x, __half& hi, __half& lo) {
    hi = __float2half_rn(x);
    lo = __float2half_rn(x - __half2float(hi));
}
__device__ __forceinline__ void split2(float a, float b, __half2& h, __half2& l) {
    __half ha, la, hb, lb;
    split_h(a, ha, la);
    split_h(b, hb, lb);
    h = __halves2half2(ha, hb);
    l = __halves2half2(la, lb);
}

__device__ __forceinline__ void mma_h(float* d,
    uint32_t a0, uint32_t a1, uint32_t a2, uint32_t a3,
    uint32_t b0, uint32_t b1)
{
    asm volatile(
        "mma.sync.aligned.m16n8k16.row.col.f32.f16.f16.f32 "
        "{%0,%1,%2,%3}, {%4,%5,%6,%7}, {%8,%9}, {%0,%1,%2,%3};\n"
        : "+f"(d[0]), "+f"(d[1]), "+f"(d[2]), "+f"(d[3])
        : "r"(a0), "r"(a1), "r"(a2), "r"(a3), "r"(b0), "r"(b1));
}
// hi*hi + hi*lo + lo*hi
__device__ __forceinline__ void mma3(float* d,
    const uint32_t ah[4], const uint32_t al[4],
    const uint32_t bh[2], const uint32_t bl[2])
{
    mma_h(d, ah[0], ah[1], ah[2], ah[3], bh[0], bh[1]);
    mma_h(d, ah[0], ah[1], ah[2], ah[3], bl[0], bl[1]);
    mma_h(d, al[0], al[1], al[2], al[3], bh[0], bh[1]);
}

__device__ __forceinline__ void ldsm_x4(uint32_t* r, uint32_t addr) {
    asm volatile("ldmatrix.sync.aligned.m8n8.x4.shared.b16 {%0,%1,%2,%3}, [%4];"
        : "=r"(r[0]), "=r"(r[1]), "=r"(r[2]), "=r"(r[3]) : "r"(addr));
}

__device__ __forceinline__ void cp16(void* dst, const void* src) {
    uint32_t d = (uint32_t)__cvta_generic_to_shared(dst);
    asm volatile("cp.async.cg.shared.global [%0], [%1], 16;\n" :: "r"(d), "l"(src));
}
__device__ __forceinline__ void cp_commit() { asm volatile("cp.async.commit_group;\n"); }
template<int N> __device__ __forceinline__ void cp_wait() {
    asm volatile("cp.async.wait_group %0;\n" :: "n"(N));
}

// sum of squares of 8 split halves
__device__ __forceinline__ float sumsq8(int4 hbits, int4 lbits) {
    const __half2* h = (const __half2*)&hbits;
    const __half2* l = (const __half2*)&lbits;
    float s = 0.f;
    #pragma unroll
    for (int i = 0; i < 4; i++) {
        float2 a = __half22float2(h[i]);
        float2 b = __half22float2(l[i]);
        float x = a.x + b.x, y = a.y + b.y;
        s += x * x + y * y;
    }
    return s;
}

// ---------------------------------------------------------------------------
// Prep kernels
// ---------------------------------------------------------------------------
__global__ void split_kernel(const float* __restrict__ src,
                             __half2* __restrict__ hi, __half2* __restrict__ lo,
                             int n4)
{
    int i = blockIdx.x * blockDim.x + threadIdx.x;
    if (i >= n4) return;
    float4 v = *(const float4*)(src + (size_t)i * 4);
    __half2 h0, l0, h1, l1;
    split2(v.x, v.y, h0, l0);
    split2(v.z, v.w, h1, l1);
    hi[(size_t)i * 2]     = h0;
    hi[(size_t)i * 2 + 1] = h1;
    lo[(size_t)i * 2]     = l0;
    lo[(size_t)i * 2 + 1] = l1;
}

// Pack weights: W[K][N] fp32 -> [K/2][N] half2 (k-pair in one half2)
__global__ void pack_w_kernel(const float* __restrict__ W,
                              __half2* __restrict__ hi, __half2* __restrict__ lo,
                              int K, int N)
{
    int idx = blockIdx.x * blockDim.x + threadIdx.x;
    int total = (K / 2) * (N / 4);
    if (idx >= total) return;
    int kp = idx / (N / 4);
    int n4 = (idx % (N / 4)) * 4;
    float4 r0 = *(const float4*)(W + (size_t)(2 * kp) * N + n4);
    float4 r1 = *(const float4*)(W + (size_t)(2 * kp + 1) * N + n4);
    const float a[4] = {r0.x, r0.y, r0.z, r0.w};
    const float b[4] = {r1.x, r1.y, r1.z, r1.w};
    #pragma unroll
    for (int t = 0; t < 4; t++) {
        __half h0, l0, h1, l1;
        split_h(a[t], h0, l0);
        split_h(b[t], h1, l1);
        hi[(size_t)kp * N + n4 + t] = __halves2half2(h0, h1);
        lo[(size_t)kp * N + n4 + t] = __halves2half2(l0, l1);
    }
}

// ---------------------------------------------------------------------------
// GEMM: C[M,N] = A @ W[K,N] + bias, fp16 split mma.
// TERMS=3: (Ahi+Alo) full 3-term.  TERMS=2: Ahi only (Ah*Bh + Ah*Bl).
// BM=128 BN=128 BK=32, 8 warps (2x4), warp tile 64x32.
// 3-stage cp.async ring; A frags via ldmatrix.x4.
// ---------------------------------------------------------------------------
#define AS_S 20     // half2 stride per m-row (16 used + 4 pad) = 80B
#define BS_S 132    // half2 stride per kp-row (128 used + 4 pad) = 528B
#define A_H2 (128 * AS_S)
#define B_H2 (16 * BS_S)
#define STG_H2 (2 * A_H2 + 2 * B_H2)
#define G_SMEM_BYTES (3 * STG_H2 * 4)

template<bool SPLIT_OUT, int TERMS>
__global__ __launch_bounds__(256, 2) void gemm_h2_kernel(
    const __half* __restrict__ Ahi, const __half* __restrict__ Alo,
    const __half2* __restrict__ Bhi, const __half2* __restrict__ Blo,
    const float* __restrict__ bias,
    float* __restrict__ Cf, __half2* __restrict__ Chi, __half2* __restrict__ Clo,
    int M, int N, int K)
{
    extern __shared__ __half2 smg[];

    const int tid   = threadIdx.x;
    const int lane  = tid & 31;
    const int wid   = tid >> 5;
    const int g     = lane >> 2;
    const int tg    = lane & 3;
    const int warpM = wid >> 2;
    const int warpN = wid & 3;
    const int rowBase = blockIdx.y * 128;
    const int colBase = blockIdx.x * 128;
    const uint32_t sbase = (uint32_t)__cvta_generic_to_shared(smg);

    const uint32_t lds_off = ((lane & 7) + (lane & 8)) * (AS_S * 4) + (lane & 16);

    float acc[4][4][4];
    #pragma unroll
    for (int mt = 0; mt < 4; mt++)
        #pragma unroll
        for (int nt = 0; nt < 4; nt++)
            #pragma unroll
            for (int i = 0; i < 4; i++) acc[mt][nt][i] = 0.f;

    const int NT = K / 32;

    auto issue = [&](int st, int kt) {
        __half2* S = smg + st * STG_H2;
        #pragma unroll
        for (int l = 0; l < 2; l++) {
            int id = tid + l * 256;
            int ar = id >> 2, ac = id & 3;
            const size_t src = (size_t)(rowBase + ar) * K + kt + ac * 8;
            cp16(&S[ar * AS_S + ac * 4], Ahi + src);
            if (TERMS == 3)
                cp16(&S[A_H2 + ar * AS_S + ac * 4], Alo + src);
        }
        #pragma unroll
        for (int l = 0; l < 2; l++) {
            int id = tid + l * 256;
            int br = id >> 5, bc = id & 31;
            const size_t src = (size_t)((kt >> 1) + br) * N + colBase + bc * 4;
            cp16(&S[2 * A_H2 + br * BS_S + bc * 4], Bhi + src);
            cp16(&S[2 * A_H2 + B_H2 + br * BS_S + bc * 4], Blo + src);
        }
        cp_commit();
    };

    issue(0, 0);
    issue(1, 32);

    for (int t = 0; t < NT; t++) {
        if (t + 1 < NT) cp_wait<1>(); else cp_wait<0>();
        __syncthreads();
        if (t + 2 < NT) issue((t + 2) % 3, (t + 2) * 32);

        const uint32_t stg = sbase + (uint32_t)((t % 3) * STG_H2) * 4u;
        const uint32_t aHb = stg + lds_off + (uint32_t)(warpM * 64) * (AS_S * 4);
        const uint32_t aLb = aHb + (uint32_t)A_H2 * 4u;
        const __half2* S = smg + (t % 3) * STG_H2;
        const __half2* Bh = S + 2 * A_H2;
        const __half2* Bl = S + 2 * A_H2 + B_H2;

        #pragma unroll
        for (int kk = 0; kk < 32; kk += 16) {
            const int kpr = kk >> 1;
            uint32_t bh[4][2], bl[4][2];
            #pragma unroll
            for (int nt = 0; nt < 4; nt++) {
                int n0 = warpN * 32 + nt * 8 + g;
                bh[nt][0] = *(const uint32_t*)&Bh[(kpr + tg) * BS_S + n0];
                bh[nt][1] = *(const uint32_t*)&Bh[(kpr + tg + 4) * BS_S + n0];
                bl[nt][0] = *(const uint32_t*)&Bl[(kpr + tg) * BS_S + n0];
                bl[nt][1] = *(const uint32_t*)&Bl[(kpr + tg + 4) * BS_S + n0];
            }
            #pragma unroll
            for (int mt = 0; mt < 4; mt++) {
                uint32_t off = (uint32_t)(mt * 16) * (AS_S * 4) + kk * 2;
                uint32_t ah[4], al[4];
                ldsm_x4(ah, aHb + off);
                if (TERMS == 3) ldsm_x4(al, aLb + off);
                #pragma unroll
                for (int nt = 0; nt < 4; nt++) {
                    if (TERMS == 3) {
                        mma3(acc[mt][nt], ah, al, bh[nt], bl[nt]);
                    } else {
                        mma_h(acc[mt][nt], ah[0], ah[1], ah[2], ah[3],
                              bh[nt][0], bh[nt][1]);
                        mma_h(acc[mt][nt], ah[0], ah[1], ah[2], ah[3],
                              bl[nt][0], bl[nt][1]);
                    }
                }
            }
        }
    }

    // epilogue
    #pragma unroll
    for (int mt = 0; mt < 4; mt++) {
        #pragma unroll
        for (int nt = 0; nt < 4; nt++) {
            int r0 = rowBase + warpM * 64 + mt * 16 + g;
            int c0 = colBase + warpN * 32 + nt * 8 + tg * 2;
            float bz0 = bias[c0], bz1 = bias[c0 + 1];
            float v0 = acc[mt][nt][0] + bz0, v1 = acc[mt][nt][1] + bz1;
            float v2 = acc[mt][nt][2] + bz0, v3 = acc[mt][nt][3] + bz1;
            if (SPLIT_OUT) {
                __half2 h, l;
                split2(v0, v1, h, l);
                Chi[(size_t)r0 * (N / 2) + c0 / 2] = h;
                Clo[(size_t)r0 * (N / 2) + c0 / 2] = l;
                split2(v2, v3, h, l);
                Chi[(size_t)(r0 + 8) * (N / 2) + c0 / 2] = h;
                Clo[(size_t)(r0 + 8) * (N / 2) + c0 / 2] = l;
            } else {
                *(float2*)&Cf[(size_t)r0 * N + c0] = make_float2(v0, v1);
                *(float2*)&Cf[(size_t)(r0 + 8) * N + c0] = make_float2(v2, v3);
            }
        }
    }
}

// ---------------------------------------------------------------------------
// Repack V: qkv_hi v-region [row][d] -> vT [bh][d][T/2] half2 (j-pairs)
// Single fp16 (v_lo dropped: error ~3e-4 relative, within budget).
// ---------------------------------------------------------------------------
#define VT_S 36
__global__ __launch_bounds__(256) void repack_v_kernel(
    const __half* __restrict__ qkv_hi, __half2* __restrict__ vT_hi)
{
    __shared__ __half2 sm_hi[64 * VT_S];
    const int tid = threadIdx.x;
    const int bh  = blockIdx.y;
    const int b   = bh / NH;
    const int h   = bh % NH;
    const int j0  = blockIdx.x * 64;

    const size_t base = ((size_t)(b * T_SEQ + j0)) * QKV_N + 2 * DIM + h * HD;
    #pragma unroll
    for (int l = 0; l < 2; l++) {
        int id = tid + l * 256;
        int r  = id >> 3;
        int c  = id & 7;
        *(int4*)&sm_hi[r * VT_S + c * 4] = *(const int4*)(qkv_hi + base + (size_t)r * QKV_N + c * 8);
    }
    __syncthreads();
    #pragma unroll
    for (int l = 0; l < 8; l++) {
        int id = tid + l * 256;
        int d  = id >> 5;
        int jp = id & 31;
        __half2 a = sm_hi[(2 * jp) * VT_S + (d >> 1)];
        __half2 c = sm_hi[(2 * jp + 1) * VT_S + (d >> 1)];
        __half va = (d & 1) ? __high2half(a) : __low2half(a);
        __half vc = (d & 1) ? __high2half(c) : __low2half(c);
        vT_hi[((size_t)bh * HD + d) * (T_SEQ / 2) + j0 / 2 + jp] = __halves2half2(va, vc);
    }
}

// ---------------------------------------------------------------------------
// Fused RBF attention, fp16-split mma, i-tile = 128, pipelined j-loop.
// S-mma 2-term (k_hi*q_hi + k_hi*q_lo); S@V 1-term (V single fp16).
// fp16 output (no split).
// ---------------------------------------------------------------------------
#define AT_S 36
#define AT_RB (AT_S * 4)       // row stride bytes (144 = 9*16)
#define ATT_SMEM_BYTES (512 * AT_S * 4 + 128 * 4 + 64 * 4)
#define LOG4096 8.317766166719343f
#define INV4096 2.44140625e-4f

__global__ __launch_bounds__(256, 2) void attn_h2_kernel(
    const __half* __restrict__ qkv_hi, const __half* __restrict__ qkv_lo,
    const __half2* __restrict__ vT_hi,
    const float* __restrict__ rsig,
    __half2* __restrict__ attn_hi)
{
    extern __shared__ char smraw[];
    __half2* ks_hi = (__half2*)smraw;                 // [128][AT_S]
    __half2* qs_hi = ks_hi + 128 * AT_S;              // [64][AT_S]
    __half2* qs_lo = qs_hi + 64 * AT_S;
    __half2* vs_hi = qs_lo + 64 * AT_S;               // [2][64][AT_S]
    __half2* Ss    = vs_hi + 2 * 64 * AT_S;           // [128][AT_S]
    float*   knv   = (float*)(Ss + 128 * AT_S);
    float*   qnv   = knv + 128;

    const int tid   = threadIdx.x;
    const int lane  = tid & 31;
    const int wid   = tid >> 5;
    const int g     = lane >> 2;
    const int tg    = lane & 3;
    const int warpM = wid & 3;        // i: 32 rows each (0..3)
    const int warpN = wid >> 2;       // j/d: 32 cols each (0..1)
    const int bh    = blockIdx.y;
    const int b     = bh / NH;
    const int h     = bh % NH;
    const int i0    = blockIdx.x * 128;
    const float nsig = -rsig[0];

    const uint32_t ksHib = (uint32_t)__cvta_generic_to_shared(ks_hi);
    const uint32_t Ssb   = (uint32_t)__cvta_generic_to_shared(Ss);
    const uint32_t lds_off = ((lane & 7) + (lane & 8)) * AT_RB + (lane & 16);

    const size_t qoff = (size_t)b * T_SEQ * QKV_N + 0 * DIM + h * HD;
    const size_t koff = (size_t)b * T_SEQ * QKV_N + 1 * DIM + h * HD;

    const int lr = tid >> 3;   // 0..31
    const int lc = tid & 7;    // 16B chunk

    auto issue_v = [&](int st, int j0) {
        #pragma unroll
        for (int p = 0; p < 2; p++) {
            int r = lr + p * 32;
            const size_t vbase = ((size_t)bh * HD + r) * (T_SEQ / 2) + j0 / 2;
            cp16(&vs_hi[st * 64 * AT_S + r * AT_S + lc * 4], vT_hi + vbase + lc * 4);
        }
        cp_commit();
    };
    auto issue_q = [&](int j0) {
        #pragma unroll
        for (int p = 0; p < 2; p++) {
            int r = lr + p * 32;
            const size_t src = qoff + (size_t)(j0 + r) * QKV_N + lc * 8;
            cp16(&qs_hi[r * AT_S + lc * 4], qkv_hi + src);
            cp16(&qs_lo[r * AT_S + lc * 4], qkv_lo + src);
        }
        cp_commit();
    };

    // ---- load K tile (128 rows, hi only in smem) + fused kn ----
    {
        float kp[4];
        #pragma unroll
        for (int p = 0; p < 4; p++) {
            int r = lr + p * 32;
            int4 vh = *(const int4*)(qkv_hi + koff + (size_t)(i0 + r) * QKV_N + lc * 8);
            int4 vl = *(const int4*)(qkv_lo + koff + (size_t)(i0 + r) * QKV_N + lc * 8);
            *(int4*)&ks_hi[r * AT_S + lc * 4] = vh;
            kp[p] = sumsq8(vh, vl);
        }
        #pragma unroll
        for (int d = 1; d < 8; d <<= 1) {
            #pragma unroll
            for (int p = 0; p < 4; p++)
                kp[p] += __shfl_xor_sync(0xffffffffu, kp[p], d);
        }
        if (lc == 0) {
            #pragma unroll
            for (int p = 0; p < 4; p++) knv[lr + p * 32] = kp[p];
        }
    }

    // ---- prologue prefetch: V(0) into stage 0, Q(0) ----
    issue_v(0, 0);
    issue_q(0);

    float out[2][4][4];
    #pragma unroll
    for (int mt = 0; mt < 2; mt++)
        #pragma unroll
        for (int nt = 0; nt < 4; nt++)
            #pragma unroll
            for (int i = 0; i < 4; i++) out[mt][nt][i] = 0.f;

    const int NT = T_SEQ / 64;
    for (int jt = 0; jt < NT; jt++) {
        cp_wait<0>();          // V(jt) + Q(jt) arrived
        __syncthreads();       // and prior iteration fully done

        if (jt + 1 < NT) issue_v((jt + 1) & 1, (jt + 1) * 64);

        // ---- qn from arrived q tile ----
        {
            float qp[2];
            #pragma unroll
            for (int p = 0; p < 2; p++) {
                int r = lr + p * 32;
                int4 vh = *(const int4*)&qs_hi[r * AT_S + lc * 4];
                int4 vl = *(const int4*)&qs_lo[r * AT_S + lc * 4];
                qp[p] = sumsq8(vh, vl);
            }
            #pragma unroll
            for (int d = 1; d < 8; d <<= 1) {
                qp[0] += __shfl_xor_sync(0xffffffffu, qp[0], d);
                qp[1] += __shfl_xor_sync(0xffffffffu, qp[1], d);
            }
            if (lc == 0) { qnv[lr] = qp[0]; qnv[32 + lr] = qp[1]; }
        }
        __syncthreads();

        // ---- S-mma: 2-term (k_hi*q_hi + k_hi*q_lo) ----
        float sacc[2][4][4];
        #pragma unroll
        for (int mt = 0; mt < 2; mt++)
            #pragma unroll
            for (int nt = 0; nt < 4; nt++)
                #pragma unroll
                for (int i = 0; i < 4; i++) sacc[mt][nt][i] = 0.f;

        #pragma unroll
        for (int kc = 0; kc < 4; kc++) {
            int kp = kc * 8;
            uint32_t bh2[4][2], bl2[4][2];
            #pragma unroll
            for (int nt = 0; nt < 4; nt++) {
                int n0 = warpN * 32 + nt * 8 + g;
                bh2[nt][0] = *(const uint32_t*)&qs_hi[n0 * AT_S + kp + tg];
                bh2[nt][1] = *(const uint32_t*)&qs_hi[n0 * AT_S + kp + tg + 4];
                bl2[nt][0] = *(const uint32_t*)&qs_lo[n0 * AT_S + kp + tg];
                bl2[nt][1] = *(const uint32_t*)&qs_lo[n0 * AT_S + kp + tg + 4];
            }
            #pragma unroll
            for (int mt = 0; mt < 2; mt++) {
                uint32_t rowb = (uint32_t)(warpM * 32 + mt * 16) * AT_RB + kc * 32 + lds_off;
                uint32_t ah[4];
                ldsm_x4(ah, ksHib + rowb);
                #pragma unroll
                for (int nt = 0; nt < 4; nt++) {
                    mma_h(sacc[mt][nt], ah[0], ah[1], ah[2], ah[3],
                          bh2[nt][0], bh2[nt][1]);
                    mma_h(sacc[mt][nt], ah[0], ah[1], ah[2], ah[3],
                          bl2[nt][0], bl2[nt][1]);
                }
            }
        }

        // ---- exp (scaled by 4096) ----
        float ev[2][4][4];
        #pragma unroll
        for (int mt = 0; mt < 2; mt++) {
            int si = warpM * 32 + mt * 16 + g;
            float kA = knv[si], kB = knv[si + 8];
            #pragma unroll
            for (int nt = 0; nt < 4; nt++) {
                int jj = warpN * 32 + nt * 8 + tg * 2;
                float qA = qnv[jj], qB = qnv[jj + 1];
                ev[mt][nt][0] = __expf(nsig * (kA + qA - 2.f * sacc[mt][nt][0]) + LOG4096);
                ev[mt][nt][1] = __expf(nsig * (kA + qB - 2.f * sacc[mt][nt][1]) + LOG4096);
                ev[mt][nt][2] = __expf(nsig * (kB + qA - 2.f * sacc[mt][nt][2]) + LOG4096);
                ev[mt][nt][3] = __expf(nsig * (kB + qB - 2.f * sacc[mt][nt][3]) + LOG4096);
            }
        }

        // ---- store scaled S (single fp16) into Ss ----
        #pragma unroll
        for (int mt = 0; mt < 2; mt++) {
            int si = warpM * 32 + mt * 16 + g;
            #pragma unroll
            for (int nt = 0; nt < 4; nt++) {
                int jp = warpN * 16 + nt * 4 + tg;
                Ss[si * AT_S + jp]       = __floats2half2_rn(ev[mt][nt][0], ev[mt][nt][1]);
                Ss[(si + 8) * AT_S + jp] = __floats2half2_rn(ev[mt][nt][2], ev[mt][nt][3]);
            }
        }
        __syncthreads();   // S visible; all S-mma reads of qs complete

        if (jt + 1 < NT) issue_q((jt + 1) * 64);

        // ---- out += S @ V  (1-term, V single fp16) ----
        const __half2* vsh = vs_hi + (jt & 1) * 64 * AT_S;
        #pragma unroll
        for (int kc = 0; kc < 4; kc++) {
            int kp = kc * 8;
            uint32_t bh2[4][2];
            #pragma unroll
            for (int nt = 0; nt < 4; nt++) {
                int n0 = warpN * 32 + nt * 8 + g;
                bh2[nt][0] = *(const uint32_t*)&vsh[n0 * AT_S + kp + tg];
                bh2[nt][1] = *(const uint32_t*)&vsh[n0 * AT_S + kp + tg + 4];
            }
            #pragma unroll
            for (int mt = 0; mt < 2; mt++) {
                uint32_t rowb = (uint32_t)(warpM * 32 + mt * 16) * AT_RB + kc * 32 + lds_off;
                uint32_t ah[4];
                ldsm_x4(ah, Ssb + rowb);
                #pragma unroll
                for (int nt = 0; nt < 4; nt++)
                    mma_h(out[mt][nt], ah[0], ah[1], ah[2], ah[3],
                          bh2[nt][0], bh2[nt][1]);
            }
        }
    }

    // ---- epilogue: unscale, plain fp16 in (b,t,h,d) layout ----
    #pragma unroll
    for (int mt = 0; mt < 2; mt++) {
        #pragma unroll
        for (int nt = 0; nt < 4; nt++) {
            int irow = i0 + warpM * 32 + mt * 16 + g;
            int dcol = warpN * 32 + nt * 8 + tg * 2;
            size_t base = ((size_t)(b * T_SEQ + irow)) * (DIM / 2) + (h * HD + dcol) / 2;
            attn_hi[base] =
                __floats2half2_rn(out[mt][nt][0] * INV4096, out[mt][nt][1] * INV4096);
            attn_hi[base + (size_t)8 * (DIM / 2)] =
                __floats2half2_rn(out[mt][nt][2] * INV4096, out[mt][nt][3] * INV4096);
        }
    }
}

// ---------------------------------------------------------------------------
extern "C" void kernel_launch(void* const* d_in, const int* in_sizes, int n_in,
                              void* d_out, int out_size)
{
    const float* x     = (const float*)d_in[0];
    const float* Wqkv  = (const float*)d_in[1];
    const float* bqkv  = (const float*)d_in[2];
    const float* rsig  = (const float*)d_in[3];
    const float* Wproj = (const float*)d_in[4];
    const float* bproj = (const float*)d_in[5];
    float* out = (float*)d_out;

    __half *x_hi, *x_lo, *qkv_hi, *qkv_lo, *attn_hi;
    __half2 *wqkv_hi, *wqkv_lo, *wproj_hi, *wproj_lo, *vT_hi;
    cudaGetSymbolAddress((void**)&x_hi, g_x_hi);
    cudaGetSymbolAddress((void**)&x_lo, g_x_lo);
    cudaGetSymbolAddress((void**)&wqkv_hi, g_wqkv_hi);
    cudaGetSymbolAddress((void**)&wqkv_lo, g_wqkv_lo);
    cudaGetSymbolAddress((void**)&wproj_hi, g_wproj_hi);
    cudaGetSymbolAddress((void**)&wproj_lo, g_wproj_lo);
    cudaGetSymbolAddress((void**)&qkv_hi, g_qkv_hi);
    cudaGetSymbolAddress((void**)&qkv_lo, g_qkv_lo);
    cudaGetSymbolAddress((void**)&vT_hi, g_vT_hi);
    cudaGetSymbolAddress((void**)&attn_hi, g_attn_hi);

    cudaFuncSetAttribute(attn_h2_kernel,
                         cudaFuncAttributeMaxDynamicSharedMemorySize, ATT_SMEM_BYTES);
    cudaFuncSetAttribute(gemm_h2_kernel<true, 3>,
                         cudaFuncAttributeMaxDynamicSharedMemorySize, G_SMEM_BYTES);
    cudaFuncSetAttribute(gemm_h2_kernel<false, 2>,
                         cudaFuncAttributeMaxDynamicSharedMemorySize, G_SMEM_BYTES);

    // prep: split x, pack weights
    {
        int n4 = ROWS * CDIM / 4;
        split_kernel<<<(n4 + 255) / 256, 256>>>(x, (__half2*)x_hi, (__half2*)x_lo, n4);
        int tq = (CDIM / 2) * (QKV_N / 4);
        pack_w_kernel<<<(tq + 255) / 256, 256>>>(Wqkv, wqkv_hi, wqkv_lo, CDIM, QKV_N);
        int tp = (DIM / 2) * (CDIM / 4);
        pack_w_kernel<<<(tp + 255) / 256, 256>>>(Wproj, wproj_hi, wproj_lo, DIM, CDIM);
    }
    // stage 1: qkv (split output, 3-term)
    {
        dim3 grid(QKV_N / 128, ROWS / 128);
        gemm_h2_kernel<true, 3><<<grid, 256, G_SMEM_BYTES>>>(
            x_hi, x_lo, wqkv_hi, wqkv_lo, bqkv,
            nullptr, (__half2*)qkv_hi, (__half2*)qkv_lo, ROWS, QKV_N, CDIM);
    }
    // repack V (single fp16)
    {
        dim3 grid(T_SEQ / 64, BATCH * NH);
        repack_v_kernel<<<grid, 256>>>(qkv_hi, vT_hi);
    }
    // stage 2: attention (i-tile 128, pipelined, fp16 out)
    {
        dim3 grid(T_SEQ / 128, BATCH * NH);
        attn_h2_kernel<<<grid, 256, ATT_SMEM_BYTES>>>(qkv_hi, qkv_lo, vT_hi,
                                                      rsig, (__half2*)attn_hi);
    }
    // stage 3: out (2-term, A = attn_hi only)
    {
        dim3 grid(CDIM / 128, ROWS / 128);
        gemm_h2_kernel<false, 2><<<grid, 256, G_SMEM_BYTES>>>(
            attn_hi, nullptr, wproj_hi, wproj_lo, bproj,
            out, nullptr, nullptr, ROWS, CDIM, DIM);
    }
}

// round 13
// speedup vs baseline: 4.5137x; 1.1486x over previous
#include <cuda_runtime.h>
#include <cuda_fp16.h>
#include <cstdint>
#include <cstddef>

// Problem constants
#define BATCH   2
#define T_SEQ   2048
#define CDIM    1024
#define DIM     1024
#define NH      16
#define HD      64
#define QKV_N   3072
#define ROWS    (BATCH*T_SEQ)

// ---------------------------------------------------------------------------
// Device scratch (allocation-free rule). All 16B aligned.
// ---------------------------------------------------------------------------
__device__ __align__(16) __half g_x_hi[ROWS * CDIM];
__device__ __align__(16) __half g_x_lo[ROWS * CDIM];
__device__ __align__(16) __half2 g_wqkv_hi[(CDIM/2) * QKV_N];  // [K/2][N] k-pair packed
__device__ __align__(16) __half2 g_wqkv_lo[(CDIM/2) * QKV_N];
__device__ __align__(16) __half2 g_wproj_hi[(DIM/2) * CDIM];
__device__ __align__(16) __half2 g_wproj_lo[(DIM/2) * CDIM];
__device__ __align__(16) __half g_qkv_hi[ROWS * QKV_N];
__device__ __align__(16) __half g_qkv_lo[ROWS * QKV_N];
__device__ __align__(16) __half2 g_vT_hi[BATCH*NH * HD * (T_SEQ/2)]; // [bh][d][T/2]
__device__ __align__(16) __half g_attn_hi[ROWS * DIM];

// ---------------------------------------------------------------------------
// helpers
// ---------------------------------------------------------------------------
__device__ __forceinline__ void split_h(float x, __half& hi, __half& lo) {
    hi = __float2half_rn(x);
    lo = __float2half_rn(x - __half2float(hi));
}
__device__ __forceinline__ void split2(float a, float b, __half2& h, __half2& l) {
    __half ha, la, hb, lb;
    split_h(a, ha, la);
    split_h(b, hb, lb);
    h = __halves2half2(ha, hb);
    l = __halves2half2(la, lb);
}

__device__ __forceinline__ void mma_h(float* d,
    uint32_t a0, uint32_t a1, uint32_t a2, uint32_t a3,
    uint32_t b0, uint32_t b1)
{
    asm volatile(
        "mma.sync.aligned.m16n8k16.row.col.f32.f16.f16.f32 "
        "{%0,%1,%2,%3}, {%4,%5,%6,%7}, {%8,%9}, {%0,%1,%2,%3};\n"
        : "+f"(d[0]), "+f"(d[1]), "+f"(d[2]), "+f"(d[3])
        : "r"(a0), "r"(a1), "r"(a2), "r"(a3), "r"(b0), "r"(b1));
}
// hi*hi + hi*lo + lo*hi
__device__ __forceinline__ void mma3(float* d,
    const uint32_t ah[4], const uint32_t al[4],
    const uint32_t bh[2], const uint32_t bl[2])
{
    mma_h(d, ah[0], ah[1], ah[2], ah[3], bh[0], bh[1]);
    mma_h(d, ah[0], ah[1], ah[2], ah[3], bl[0], bl[1]);
    mma_h(d, al[0], al[1], al[2], al[3], bh[0], bh[1]);
}

__device__ __forceinline__ void ldsm_x4(uint32_t* r, uint32_t addr) {
    asm volatile("ldmatrix.sync.aligned.m8n8.x4.shared.b16 {%0,%1,%2,%3}, [%4];"
        : "=r"(r[0]), "=r"(r[1]), "=r"(r[2]), "=r"(r[3]) : "r"(addr));
}

__device__ __forceinline__ void cp16(void* dst, const void* src) {
    uint32_t d = (uint32_t)__cvta_generic_to_shared(dst);
    asm volatile("cp.async.cg.shared.global [%0], [%1], 16;\n" :: "r"(d), "l"(src));
}
__device__ __forceinline__ void cp_commit() { asm volatile("cp.async.commit_group;\n"); }
template<int N> __device__ __forceinline__ void cp_wait() {
    asm volatile("cp.async.wait_group %0;\n" :: "n"(N));
}

// sum of squares of 8 split halves
__device__ __forceinline__ float sumsq8(int4 hbits, int4 lbits) {
    const __half2* h = (const __half2*)&hbits;
    const __half2* l = (const __half2*)&lbits;
    float s = 0.f;
    #pragma unroll
    for (int i = 0; i < 4; i++) {
        float2 a = __half22float2(h[i]);
        float2 b = __half22float2(l[i]);
        float x = a.x + b.x, y = a.y + b.y;
        s += x * x + y * y;
    }
    return s;
}

// ---------------------------------------------------------------------------
// Prep kernels
// ---------------------------------------------------------------------------
__global__ void split_kernel(const float* __restrict__ src,
                             __half2* __restrict__ hi, __half2* __restrict__ lo,
                             int n4)
{
    int i = blockIdx.x * blockDim.x + threadIdx.x;
    if (i >= n4) return;
    float4 v = *(const float4*)(src + (size_t)i * 4);
    __half2 h0, l0, h1, l1;
    split2(v.x, v.y, h0, l0);
    split2(v.z, v.w, h1, l1);
    hi[(size_t)i * 2]     = h0;
    hi[(size_t)i * 2 + 1] = h1;
    lo[(size_t)i * 2]     = l0;
    lo[(size_t)i * 2 + 1] = l1;
}

// Pack weights: W[K][N] fp32 -> [K/2][N] half2 (k-pair in one half2)
__global__ void pack_w_kernel(const float* __restrict__ W,
                              __half2* __restrict__ hi, __half2* __restrict__ lo,
                              int K, int N)
{
    int idx = blockIdx.x * blockDim.x + threadIdx.x;
    int total = (K / 2) * (N / 4);
    if (idx >= total) return;
    int kp = idx / (N / 4);
    int n4 = (idx % (N / 4)) * 4;
    float4 r0 = *(const float4*)(W + (size_t)(2 * kp) * N + n4);
    float4 r1 = *(const float4*)(W + (size_t)(2 * kp + 1) * N + n4);
    const float a[4] = {r0.x, r0.y, r0.z, r0.w};
    const float b[4] = {r1.x, r1.y, r1.z, r1.w};
    #pragma unroll
    for (int t = 0; t < 4; t++) {
        __half h0, l0, h1, l1;
        split_h(a[t], h0, l0);
        split_h(b[t], h1, l1);
        hi[(size_t)kp * N + n4 + t] = __halves2half2(h0, h1);
        lo[(size_t)kp * N + n4 + t] = __halves2half2(l0, l1);
    }
}

// ---------------------------------------------------------------------------
// GEMM: C[M,N] = A @ W[K,N] + bias, fp16 split mma.
// TERMS=3: 3-term for columns < cols3, 2-term (A quantized) for the rest.
// TERMS=2: Ahi only everywhere.
// BM=128 BN=128 BK=32, 8 warps (2x4), warp tile 64x32.
// 3-stage cp.async ring; A frags via ldmatrix.x4.
// ---------------------------------------------------------------------------
#define AS_S 20     // half2 stride per m-row (16 used + 4 pad) = 80B
#define BS_S 132    // half2 stride per kp-row (128 used + 4 pad) = 528B
#define A_H2 (128 * AS_S)
#define B_H2 (16 * BS_S)
#define STG_H2 (2 * A_H2 + 2 * B_H2)
#define G_SMEM_BYTES (3 * STG_H2 * 4)

template<bool SPLIT_OUT, int TERMS>
__global__ __launch_bounds__(256, 2) void gemm_h2_kernel(
    const __half* __restrict__ Ahi, const __half* __restrict__ Alo,
    const __half2* __restrict__ Bhi, const __half2* __restrict__ Blo,
    const float* __restrict__ bias,
    float* __restrict__ Cf, __half2* __restrict__ Chi, __half2* __restrict__ Clo,
    int M, int N, int K, int cols3)
{
    extern __shared__ __half2 smg[];

    const int tid   = threadIdx.x;
    const int lane  = tid & 31;
    const int wid   = tid >> 5;
    const int g     = lane >> 2;
    const int tg    = lane & 3;
    const int warpM = wid >> 2;
    const int warpN = wid & 3;
    const int rowBase = blockIdx.y * 128;
    const int colBase = blockIdx.x * 128;
    const uint32_t sbase = (uint32_t)__cvta_generic_to_shared(smg);
    const bool t3 = (TERMS == 3) && (colBase < cols3);

    const uint32_t lds_off = ((lane & 7) + (lane & 8)) * (AS_S * 4) + (lane & 16);

    float acc[4][4][4];
    #pragma unroll
    for (int mt = 0; mt < 4; mt++)
        #pragma unroll
        for (int nt = 0; nt < 4; nt++)
            #pragma unroll
            for (int i = 0; i < 4; i++) acc[mt][nt][i] = 0.f;

    const int NT = K / 32;

    auto issue = [&](int st, int kt) {
        __half2* S = smg + st * STG_H2;
        #pragma unroll
        for (int l = 0; l < 2; l++) {
            int id = tid + l * 256;
            int ar = id >> 2, ac = id & 3;
            const size_t src = (size_t)(rowBase + ar) * K + kt + ac * 8;
            cp16(&S[ar * AS_S + ac * 4], Ahi + src);
            if (t3)
                cp16(&S[A_H2 + ar * AS_S + ac * 4], Alo + src);
        }
        #pragma unroll
        for (int l = 0; l < 2; l++) {
            int id = tid + l * 256;
            int br = id >> 5, bc = id & 31;
            const size_t src = (size_t)((kt >> 1) + br) * N + colBase + bc * 4;
            cp16(&S[2 * A_H2 + br * BS_S + bc * 4], Bhi + src);
            cp16(&S[2 * A_H2 + B_H2 + br * BS_S + bc * 4], Blo + src);
        }
        cp_commit();
    };

    issue(0, 0);
    issue(1, 32);

    for (int t = 0; t < NT; t++) {
        if (t + 1 < NT) cp_wait<1>(); else cp_wait<0>();
        __syncthreads();
        if (t + 2 < NT) issue((t + 2) % 3, (t + 2) * 32);

        const uint32_t stg = sbase + (uint32_t)((t % 3) * STG_H2) * 4u;
        const uint32_t aHb = stg + lds_off + (uint32_t)(warpM * 64) * (AS_S * 4);
        const uint32_t aLb = aHb + (uint32_t)A_H2 * 4u;
        const __half2* S = smg + (t % 3) * STG_H2;
        const __half2* Bh = S + 2 * A_H2;
        const __half2* Bl = S + 2 * A_H2 + B_H2;

        #pragma unroll
        for (int kk = 0; kk < 32; kk += 16) {
            const int kpr = kk >> 1;
            uint32_t bh[4][2], bl[4][2];
            #pragma unroll
            for (int nt = 0; nt < 4; nt++) {
                int n0 = warpN * 32 + nt * 8 + g;
                bh[nt][0] = *(const uint32_t*)&Bh[(kpr + tg) * BS_S + n0];
                bh[nt][1] = *(const uint32_t*)&Bh[(kpr + tg + 4) * BS_S + n0];
                bl[nt][0] = *(const uint32_t*)&Bl[(kpr + tg) * BS_S + n0];
                bl[nt][1] = *(const uint32_t*)&Bl[(kpr + tg + 4) * BS_S + n0];
            }
            if (t3) {
                #pragma unroll
                for (int mt = 0; mt < 4; mt++) {
                    uint32_t off = (uint32_t)(mt * 16) * (AS_S * 4) + kk * 2;
                    uint32_t ah[4], al[4];
                    ldsm_x4(ah, aHb + off);
                    ldsm_x4(al, aLb + off);
                    #pragma unroll
                    for (int nt = 0; nt < 4; nt++)
                        mma3(acc[mt][nt], ah, al, bh[nt], bl[nt]);
                }
            } else {
                #pragma unroll
                for (int mt = 0; mt < 4; mt++) {
                    uint32_t off = (uint32_t)(mt * 16) * (AS_S * 4) + kk * 2;
                    uint32_t ah[4];
                    ldsm_x4(ah, aHb + off);
                    #pragma unroll
                    for (int nt = 0; nt < 4; nt++) {
                        mma_h(acc[mt][nt], ah[0], ah[1], ah[2], ah[3],
                              bh[nt][0], bh[nt][1]);
                        mma_h(acc[mt][nt], ah[0], ah[1], ah[2], ah[3],
                              bl[nt][0], bl[nt][1]);
                    }
                }
            }
        }
    }

    // epilogue
    #pragma unroll
    for (int mt = 0; mt < 4; mt++) {
        #pragma unroll
        for (int nt = 0; nt < 4; nt++) {
            int r0 = rowBase + warpM * 64 + mt * 16 + g;
            int c0 = colBase + warpN * 32 + nt * 8 + tg * 2;
            float bz0 = bias[c0], bz1 = bias[c0 + 1];
            float v0 = acc[mt][nt][0] + bz0, v1 = acc[mt][nt][1] + bz1;
            float v2 = acc[mt][nt][2] + bz0, v3 = acc[mt][nt][3] + bz1;
            if (SPLIT_OUT) {
                __half2 h, l;
                split2(v0, v1, h, l);
                Chi[(size_t)r0 * (N / 2) + c0 / 2] = h;
                if (t3) Clo[(size_t)r0 * (N / 2) + c0 / 2] = l;
                split2(v2, v3, h, l);
                Chi[(size_t)(r0 + 8) * (N / 2) + c0 / 2] = h;
                if (t3) Clo[(size_t)(r0 + 8) * (N / 2) + c0 / 2] = l;
            } else {
                *(float2*)&Cf[(size_t)r0 * N + c0] = make_float2(v0, v1);
                *(float2*)&Cf[(size_t)(r0 + 8) * N + c0] = make_float2(v2, v3);
            }
        }
    }
}

// ---------------------------------------------------------------------------
// Repack V: qkv_hi v-region [row][d] -> vT [bh][d][T/2] half2 (j-pairs)
// ---------------------------------------------------------------------------
#define VT_S 36
__global__ __launch_bounds__(256) void repack_v_kernel(
    const __half* __restrict__ qkv_hi, __half2* __restrict__ vT_hi)
{
    __shared__ __half2 sm_hi[64 * VT_S];
    const int tid = threadIdx.x;
    const int bh  = blockIdx.y;
    const int b   = bh / NH;
    const int h   = bh % NH;
    const int j0  = blockIdx.x * 64;

    const size_t base = ((size_t)(b * T_SEQ + j0)) * QKV_N + 2 * DIM + h * HD;
    #pragma unroll
    for (int l = 0; l < 2; l++) {
        int id = tid + l * 256;
        int r  = id >> 3;
        int c  = id & 7;
        *(int4*)&sm_hi[r * VT_S + c * 4] = *(const int4*)(qkv_hi + base + (size_t)r * QKV_N + c * 8);
    }
    __syncthreads();
    #pragma unroll
    for (int l = 0; l < 8; l++) {
        int id = tid + l * 256;
        int d  = id >> 5;
        int jp = id & 31;
        __half2 a = sm_hi[(2 * jp) * VT_S + (d >> 1)];
        __half2 c = sm_hi[(2 * jp + 1) * VT_S + (d >> 1)];
        __half va = (d & 1) ? __high2half(a) : __low2half(a);
        __half vc = (d & 1) ? __high2half(c) : __low2half(c);
        vT_hi[((size_t)bh * HD + d) * (T_SEQ / 2) + j0 / 2 + jp] = __halves2half2(va, vc);
    }
}

// ---------------------------------------------------------------------------
// Fused RBF attention, i-tile = 128, pipelined j-loop.
// S-mma 1-term (k_hi*q_hi) with EXACT kn/qn (hi+lo); S@V 1-term.
// fp16 output (no split).
// ---------------------------------------------------------------------------
#define AT_S 36
#define AT_RB (AT_S * 4)       // row stride bytes (144 = 9*16)
#define ATT_SMEM_BYTES (512 * AT_S * 4 + 128 * 4 + 64 * 4)
#define LOG4096 8.317766166719343f
#define INV4096 2.44140625e-4f

__global__ __launch_bounds__(256, 2) void attn_h2_kernel(
    const __half* __restrict__ qkv_hi, const __half* __restrict__ qkv_lo,
    const __half2* __restrict__ vT_hi,
    const float* __restrict__ rsig,
    __half2* __restrict__ attn_hi)
{
    extern __shared__ char smraw[];
    __half2* ks_hi = (__half2*)smraw;                 // [128][AT_S]
    __half2* qs_hi = ks_hi + 128 * AT_S;              // [64][AT_S]
    __half2* qs_lo = qs_hi + 64 * AT_S;               // for exact qn only
    __half2* vs_hi = qs_lo + 64 * AT_S;               // [2][64][AT_S]
    __half2* Ss    = vs_hi + 2 * 64 * AT_S;           // [128][AT_S]
    float*   knv   = (float*)(Ss + 128 * AT_S);
    float*   qnv   = knv + 128;

    const int tid   = threadIdx.x;
    const int lane  = tid & 31;
    const int wid   = tid >> 5;
    const int g     = lane >> 2;
    const int tg    = lane & 3;
    const int warpM = wid & 3;        // i: 32 rows each (0..3)
    const int warpN = wid >> 2;       // j/d: 32 cols each (0..1)
    const int bh    = blockIdx.y;
    const int b     = bh / NH;
    const int h     = bh % NH;
    const int i0    = blockIdx.x * 128;
    const float nsig = -rsig[0];

    const uint32_t ksHib = (uint32_t)__cvta_generic_to_shared(ks_hi);
    const uint32_t Ssb   = (uint32_t)__cvta_generic_to_shared(Ss);
    const uint32_t lds_off = ((lane & 7) + (lane & 8)) * AT_RB + (lane & 16);

    const size_t qoff = (size_t)b * T_SEQ * QKV_N + 0 * DIM + h * HD;
    const size_t koff = (size_t)b * T_SEQ * QKV_N + 1 * DIM + h * HD;

    const int lr = tid >> 3;   // 0..31
    const int lc = tid & 7;    // 16B chunk

    auto issue_v = [&](int st, int j0) {
        #pragma unroll
        for (int p = 0; p < 2; p++) {
            int r = lr + p * 32;
            const size_t vbase = ((size_t)bh * HD + r) * (T_SEQ / 2) + j0 / 2;
            cp16(&vs_hi[st * 64 * AT_S + r * AT_S + lc * 4], vT_hi + vbase + lc * 4);
        }
        cp_commit();
    };
    auto issue_q = [&](int j0) {
        #pragma unroll
        for (int p = 0; p < 2; p++) {
            int r = lr + p * 32;
            const size_t src = qoff + (size_t)(j0 + r) * QKV_N + lc * 8;
            cp16(&qs_hi[r * AT_S + lc * 4], qkv_hi + src);
            cp16(&qs_lo[r * AT_S + lc * 4], qkv_lo + src);
        }
        cp_commit();
    };

    // ---- load K tile (128 rows, hi only in smem) + exact kn ----
    {
        float kp[4];
        #pragma unroll
        for (int p = 0; p < 4; p++) {
            int r = lr + p * 32;
            int4 vh = *(const int4*)(qkv_hi + koff + (size_t)(i0 + r) * QKV_N + lc * 8);
            int4 vl = *(const int4*)(qkv_lo + koff + (size_t)(i0 + r) * QKV_N + lc * 8);
            *(int4*)&ks_hi[r * AT_S + lc * 4] = vh;
            kp[p] = sumsq8(vh, vl);
        }
        #pragma unroll
        for (int d = 1; d < 8; d <<= 1) {
            #pragma unroll
            for (int p = 0; p < 4; p++)
                kp[p] += __shfl_xor_sync(0xffffffffu, kp[p], d);
        }
        if (lc == 0) {
            #pragma unroll
            for (int p = 0; p < 4; p++) knv[lr + p * 32] = kp[p];
        }
    }

    // ---- prologue prefetch: V(0) into stage 0, Q(0) ----
    issue_v(0, 0);
    issue_q(0);

    float out[2][4][4];
    #pragma unroll
    for (int mt = 0; mt < 2; mt++)
        #pragma unroll
        for (int nt = 0; nt < 4; nt++)
            #pragma unroll
            for (int i = 0; i < 4; i++) out[mt][nt][i] = 0.f;

    const int NT = T_SEQ / 64;
    for (int jt = 0; jt < NT; jt++) {
        cp_wait<0>();          // V(jt) + Q(jt) arrived
        __syncthreads();       // and prior iteration fully done

        if (jt + 1 < NT) issue_v((jt + 1) & 1, (jt + 1) * 64);

        // ---- exact qn from arrived q tile (hi+lo) ----
        {
            float qp[2];
            #pragma unroll
            for (int p = 0; p < 2; p++) {
                int r = lr + p * 32;
                int4 vh = *(const int4*)&qs_hi[r * AT_S + lc * 4];
                int4 vl = *(const int4*)&qs_lo[r * AT_S + lc * 4];
                qp[p] = sumsq8(vh, vl);
            }
            #pragma unroll
            for (int d = 1; d < 8; d <<= 1) {
                qp[0] += __shfl_xor_sync(0xffffffffu, qp[0], d);
                qp[1] += __shfl_xor_sync(0xffffffffu, qp[1], d);
            }
            if (lc == 0) { qnv[lr] = qp[0]; qnv[32 + lr] = qp[1]; }
        }
        __syncthreads();

        // ---- S-mma: 1-term (k_hi * q_hi) ----
        float sacc[2][4][4];
        #pragma unroll
        for (int mt = 0; mt < 2; mt++)
            #pragma unroll
            for (int nt = 0; nt < 4; nt++)
                #pragma unroll
                for (int i = 0; i < 4; i++) sacc[mt][nt][i] = 0.f;

        #pragma unroll
        for (int kc = 0; kc < 4; kc++) {
            int kp = kc * 8;
            uint32_t bh2[4][2];
            #pragma unroll
            for (int nt = 0; nt < 4; nt++) {
                int n0 = warpN * 32 + nt * 8 + g;
                bh2[nt][0] = *(const uint32_t*)&qs_hi[n0 * AT_S + kp + tg];
                bh2[nt][1] = *(const uint32_t*)&qs_hi[n0 * AT_S + kp + tg + 4];
            }
            #pragma unroll
            for (int mt = 0; mt < 2; mt++) {
                uint32_t rowb = (uint32_t)(warpM * 32 + mt * 16) * AT_RB + kc * 32 + lds_off;
                uint32_t ah[4];
                ldsm_x4(ah, ksHib + rowb);
                #pragma unroll
                for (int nt = 0; nt < 4; nt++)
                    mma_h(sacc[mt][nt], ah[0], ah[1], ah[2], ah[3],
                          bh2[nt][0], bh2[nt][1]);
            }
        }

        // ---- exp (scaled by 4096) ----
        float ev[2][4][4];
        #pragma unroll
        for (int mt = 0; mt < 2; mt++) {
            int si = warpM * 32 + mt * 16 + g;
            float kA = knv[si], kB = knv[si + 8];
            #pragma unroll
            for (int nt = 0; nt < 4; nt++) {
                int jj = warpN * 32 + nt * 8 + tg * 2;
                float qA = qnv[jj], qB = qnv[jj + 1];
                ev[mt][nt][0] = __expf(nsig * (kA + qA - 2.f * sacc[mt][nt][0]) + LOG4096);
                ev[mt][nt][1] = __expf(nsig * (kA + qB - 2.f * sacc[mt][nt][1]) + LOG4096);
                ev[mt][nt][2] = __expf(nsig * (kB + qA - 2.f * sacc[mt][nt][2]) + LOG4096);
                ev[mt][nt][3] = __expf(nsig * (kB + qB - 2.f * sacc[mt][nt][3]) + LOG4096);
            }
        }

        // ---- store scaled S (single fp16) into Ss ----
        #pragma unroll
        for (int mt = 0; mt < 2; mt++) {
            int si = warpM * 32 + mt * 16 + g;
            #pragma unroll
            for (int nt = 0; nt < 4; nt++) {
                int jp = warpN * 16 + nt * 4 + tg;
                Ss[si * AT_S + jp]       = __floats2half2_rn(ev[mt][nt][0], ev[mt][nt][1]);
                Ss[(si + 8) * AT_S + jp] = __floats2half2_rn(ev[mt][nt][2], ev[mt][nt][3]);
            }
        }
        __syncthreads();   // S visible; all S-mma reads of qs complete

        if (jt + 1 < NT) issue_q((jt + 1) * 64);

        // ---- out += S @ V  (1-term, V single fp16) ----
        const __half2* vsh = vs_hi + (jt & 1) * 64 * AT_S;
        #pragma unroll
        for (int kc = 0; kc < 4; kc++) {
            int kp = kc * 8;
            uint32_t bh2[4][2];
            #pragma unroll
            for (int nt = 0; nt < 4; nt++) {
                int n0 = warpN * 32 + nt * 8 + g;
                bh2[nt][0] = *(const uint32_t*)&vsh[n0 * AT_S + kp + tg];
                bh2[nt][1] = *(const uint32_t*)&vsh[n0 * AT_S + kp + tg + 4];
            }
            #pragma unroll
            for (int mt = 0; mt < 2; mt++) {
                uint32_t rowb = (uint32_t)(warpM * 32 + mt * 16) * AT_RB + kc * 32 + lds_off;
                uint32_t ah[4];
                ldsm_x4(ah, Ssb + rowb);
                #pragma unroll
                for (int nt = 0; nt < 4; nt++)
                    mma_h(out[mt][nt], ah[0], ah[1], ah[2], ah[3],
                          bh2[nt][0], bh2[nt][1]);
            }
        }
    }

    // ---- epilogue: unscale, plain fp16 in (b,t,h,d) layout ----
    #pragma unroll
    for (int mt = 0; mt < 2; mt++) {
        #pragma unroll
        for (int nt = 0; nt < 4; nt++) {
            int irow = i0 + warpM * 32 + mt * 16 + g;
            int dcol = warpN * 32 + nt * 8 + tg * 2;
            size_t base = ((size_t)(b * T_SEQ + irow)) * (DIM / 2) + (h * HD + dcol) / 2;
            attn_hi[base] =
                __floats2half2_rn(out[mt][nt][0] * INV4096, out[mt][nt][1] * INV4096);
            attn_hi[base + (size_t)8 * (DIM / 2)] =
                __floats2half2_rn(out[mt][nt][2] * INV4096, out[mt][nt][3] * INV4096);
        }
    }
}

// ---------------------------------------------------------------------------
extern "C" void kernel_launch(void* const* d_in, const int* in_sizes, int n_in,
                              void* d_out, int out_size)
{
    const float* x     = (const float*)d_in[0];
    const float* Wqkv  = (const float*)d_in[1];
    const float* bqkv  = (const float*)d_in[2];
    const float* rsig  = (const float*)d_in[3];
    const float* Wproj = (const float*)d_in[4];
    const float* bproj = (const float*)d_in[5];
    float* out = (float*)d_out;

    __half *x_hi, *x_lo, *qkv_hi, *qkv_lo, *attn_hi;
    __half2 *wqkv_hi, *wqkv_lo, *wproj_hi, *wproj_lo, *vT_hi;
    cudaGetSymbolAddress((void**)&x_hi, g_x_hi);
    cudaGetSymbolAddress((void**)&x_lo, g_x_lo);
    cudaGetSymbolAddress((void**)&wqkv_hi, g_wqkv_hi);
    cudaGetSymbolAddress((void**)&wqkv_lo, g_wqkv_lo);
    cudaGetSymbolAddress((void**)&wproj_hi, g_wproj_hi);
    cudaGetSymbolAddress((void**)&wproj_lo, g_wproj_lo);
    cudaGetSymbolAddress((void**)&qkv_hi, g_qkv_hi);
    cudaGetSymbolAddress((void**)&qkv_lo, g_qkv_lo);
    cudaGetSymbolAddress((void**)&vT_hi, g_vT_hi);
    cudaGetSymbolAddress((void**)&attn_hi, g_attn_hi);

    cudaFuncSetAttribute(attn_h2_kernel,
                         cudaFuncAttributeMaxDynamicSharedMemorySize, ATT_SMEM_BYTES);
    cudaFuncSetAttribute(gemm_h2_kernel<true, 3>,
                         cudaFuncAttributeMaxDynamicSharedMemorySize, G_SMEM_BYTES);
    cudaFuncSetAttribute(gemm_h2_kernel<false, 2>,
                         cudaFuncAttributeMaxDynamicSharedMemorySize, G_SMEM_BYTES);

    // prep: split x, pack weights
    {
        int n4 = ROWS * CDIM / 4;
        split_kernel<<<(n4 + 255) / 256, 256>>>(x, (__half2*)x_hi, (__half2*)x_lo, n4);
        int tq = (CDIM / 2) * (QKV_N / 4);
        pack_w_kernel<<<(tq + 255) / 256, 256>>>(Wqkv, wqkv_hi, wqkv_lo, CDIM, QKV_N);
        int tp = (DIM / 2) * (CDIM / 4);
        pack_w_kernel<<<(tp + 255) / 256, 256>>>(Wproj, wproj_hi, wproj_lo, DIM, CDIM);
    }
    // stage 1: qkv — 3-term for q/k cols [0,2048), 2-term for v cols [2048,3072)
    {
        dim3 grid(QKV_N / 128, ROWS / 128);
        gemm_h2_kernel<true, 3><<<grid, 256, G_SMEM_BYTES>>>(
            x_hi, x_lo, wqkv_hi, wqkv_lo, bqkv,
            nullptr, (__half2*)qkv_hi, (__half2*)qkv_lo, ROWS, QKV_N, CDIM, 2048);
    }
    // repack V (single fp16)
    {
        dim3 grid(T_SEQ / 64, BATCH * NH);
        repack_v_kernel<<<grid, 256>>>(qkv_hi, vT_hi);
    }
    // stage 2: attention (i-tile 128, pipelined, fp16 out)
    {
        dim3 grid(T_SEQ / 128, BATCH * NH);
        attn_h2_kernel<<<grid, 256, ATT_SMEM_BYTES>>>(qkv_hi, qkv_lo, vT_hi,
                                                      rsig, (__half2*)attn_hi);
    }
    // stage 3: out (2-term, A = attn_hi only)
    {
        dim3 grid(CDIM / 128, ROWS / 128);
        gemm_h2_kernel<false, 2><<<grid, 256, G_SMEM_BYTES>>>(
            attn_hi, nullptr, wproj_hi, wproj_lo, bproj,
            out, nullptr, nullptr, ROWS, CDIM, DIM, 0);
    }
}